// round 11
// baseline (speedup 1.0000x reference)
#include <cuda_runtime.h>
#include <cuda_fp16.h>
#include <math.h>

#define NB 128
#define NT 256
#define B_   64
#define T_   64
#define D_   512
#define LEPS 1e-3f
#define STAGEB 3456            // per-warp per-stage bytes: A 16*144 + W 8*144
#define DEPTH  5
#define WRING  (DEPTH*STAGEB)  // 17280 B per warp
#define SMEMB  (8*WRING)       // 138240 B per block

// ---------------- static device scratch ----------------
static __device__ __align__(16) __half g_comW1t[3ull*2048*2048];
static __device__ __align__(16) __half g_comW2t[3ull*2048*2048];
static __device__ __align__(16) __half g_decW1t[2ull*2048*1536];  // [slot][n=2048][k=1536]
static __device__ __align__(16) __half g_decW2t[2ull*1536*2048];  // [slot][n=1536][k=2048]
static __device__ __align__(16) __half g_Wd1t[512*2048];          // [n=512][k=2048]
static __device__ __align__(16) __half g_Wobst[512*128];          // [n=512][k=128]
static __device__ __align__(16) __half g_obsh[B_*T_*128];
static __device__ __align__(16) __half g_Xcomb[4096*1024];        // [(t*64+b)][1024]
static __device__ __align__(16) __half g_Xvh[B_*1024];            // [vi, hi]
static __device__ __align__(16) __half g_Xpc[B_*3*1024];          // [pm, cand]
static __device__ __align__(16) __half g_Xp[B_*512];              // parent
static __device__ __align__(16) __half g_A1h[B_*2048];
static __device__ __align__(16) float  g_obsinp[B_*T_*D_];
static __device__ __align__(16) float  g_PCcom[3ull*4096*2048];
static __device__ __align__(16) float  g_PCdec[2ull*4096*2048];
static __device__ __align__(16) float  g_PCdist[4096*512];
static __device__ __align__(16) float  g_PChead[4096*16];
static __device__ __align__(16) float  g_Af[B_*2048];
static __device__ __align__(16) float  g_H1[B_*3*D_];
static __device__ __align__(16) float  g_H[B_*D_];
static __device__ __align__(16) float  g_M[B_*3*D_];
static __device__ __align__(16) float  g_cand[B_*3*D_];
static __device__ __align__(16) float  g_chl[B_*3*D_];
static __device__ __align__(16) float  g_TE[B_*D_];
static __device__              float  g_P[B_*3];
static __device__              float  g_PE[B_];

// ---------------- grid barrier (acquire/release) ----------------
static __device__ unsigned g_cnt = 0;
static __device__ unsigned g_gen = 0;

__device__ __forceinline__ unsigned ld_acq(unsigned* p){
    unsigned v;
    asm volatile("ld.acquire.gpu.global.u32 %0, [%1];" : "=r"(v) : "l"(p));
    return v;
}

__device__ __forceinline__ void gridbar(){
    __syncthreads();
    if (threadIdx.x == 0){
        unsigned g = g_gen;
        unsigned old;
        asm volatile("atom.release.gpu.global.add.u32 %0, [%1], 1;"
                     : "=r"(old) : "l"(&g_cnt));
        if (old == (unsigned)(NB - 1)){
            g_cnt = 0;
            asm volatile("st.release.gpu.global.u32 [%0], %1;" :: "l"(&g_gen), "r"(g + 1));
        } else {
            while (ld_acq(&g_gen) == g) __nanosleep(20);
        }
    }
    __syncthreads();
}

// ---------------- helpers (8 warps) ----------------
__device__ __forceinline__ float sigmf(float x){ return 1.f/(1.f+expf(-x)); }

__device__ __forceinline__ float2 red2(float s, float q, float* shs, float* shq){
    int lane = threadIdx.x & 31, w = threadIdx.x >> 5;
    #pragma unroll
    for (int off=16; off; off>>=1){
        s += __shfl_down_sync(0xffffffffu, s, off);
        q += __shfl_down_sync(0xffffffffu, q, off);
    }
    if (lane==0){ shs[w]=s; shq[w]=q; }
    __syncthreads();
    if (w==0){
        s = (lane<8)? shs[lane] : 0.f;
        q = (lane<8)? shq[lane] : 0.f;
        #pragma unroll
        for (int off=4; off; off>>=1){
            s += __shfl_down_sync(0xffffffffu, s, off);
            q += __shfl_down_sync(0xffffffffu, q, off);
        }
        if (lane==0){ shs[0]=s; shq[0]=q; }
    }
    __syncthreads();
    float2 r = make_float2(shs[0], shq[0]);
    __syncthreads();
    return r;
}

__device__ __forceinline__ float red1(float s, float* shs){
    int lane = threadIdx.x & 31, w = threadIdx.x >> 5;
    #pragma unroll
    for (int off=16; off; off>>=1) s += __shfl_down_sync(0xffffffffu, s, off);
    if (lane==0) shs[w]=s;
    __syncthreads();
    if (w==0){
        s = (lane<8)? shs[lane] : 0.f;
        #pragma unroll
        for (int off=4; off; off>>=1) s += __shfl_down_sync(0xffffffffu, s, off);
        if (lane==0) shs[0]=s;
    }
    __syncthreads();
    float r = shs[0];
    __syncthreads();
    return r;
}

// ---------------- cp.async ----------------
__device__ __forceinline__ void cpa16(unsigned saddr, const void* g){
    asm volatile("cp.async.ca.shared.global [%0], [%1], 16;" :: "r"(saddr), "l"(g));
}
#define CP_COMMIT() asm volatile("cp.async.commit_group;")
#define CP_WAIT3()  asm volatile("cp.async.wait_group 3;")
#define CP_WAIT0()  asm volatile("cp.async.wait_group 0;")

// ---------------- transpose-convert: W(KxN fp32) -> Wt(NxK fp16) ----------------
__device__ void dev_tcvt(const float* __restrict__ W, __half* __restrict__ Wt,
                         int K, int N, __half (*S)[72])
{
    const int tid = threadIdx.x;
    const int r = tid >> 3, c4 = (tid & 7) * 4;
    const int Ntl = N >> 5;
    const int jobs = (K >> 5) * Ntl;
    for (int job = blockIdx.x; job < jobs; job += NB){
        const int k0 = (job / Ntl) << 5, n0 = (job % Ntl) << 5;
        __syncthreads();
        float4 v = *(const float4*)(W + (size_t)(k0 + r)*N + n0 + c4);
        S[r][c4]   = __float2half(v.x);
        S[r][c4+1] = __float2half(v.y);
        S[r][c4+2] = __float2half(v.z);
        S[r][c4+3] = __float2half(v.w);
        __syncthreads();
        __half2 h0 = __halves2half2(S[c4][r],   S[c4+1][r]);
        __half2 h1 = __halves2half2(S[c4+2][r], S[c4+3][r]);
        *(__half2*)(Wt + (size_t)(n0 + r)*K + k0 + c4)     = h0;
        *(__half2*)(Wt + (size_t)(n0 + r)*K + k0 + c4 + 2) = h1;
    }
    __syncthreads();
}

// ---------------- convert fp32 -> fp16 ----------------
__device__ void dev_cvt4(const float* __restrict__ s, __half* __restrict__ d, int n4){
    const float4* s4 = (const float4*)s;
    __half2* d2 = (__half2*)d;
    for (int i = blockIdx.x*NT + threadIdx.x; i < n4; i += NB*NT){
        float4 v = s4[i];
        d2[2*i]   = __floats2half2_rn(v.x, v.y);
        d2[2*i+1] = __floats2half2_rn(v.z, v.w);
    }
}

__device__ void dev_prep(const float* __restrict__ emb, const int* __restrict__ ids,
                         const float* __restrict__ prevm){
    int i0 = blockIdx.x*NT + threadIdx.x, stride = NB*NT;
    for (int i = i0; i < B_*D_; i += stride){
        int b = i >> 9;
        g_TE[i] = emb[ids[b]*D_ + (i & 511)];
    }
    for (int i = i0; i < B_*3*D_; i += stride) g_M[i] = prevm[i];
}

__device__ void dev_xcomb(){
    for (int i = blockIdx.x*NT + threadIdx.x; i < 4096*1024; i += NB*NT){
        int row = i >> 10, d = i & 1023;
        int t = row >> 6, b = row & 63;
        float v = (d < 512) ? g_obsinp[(b*T_ + t)*512 + d]
                            : g_TE[b*512 + (d - 512)];
        g_Xcomb[i] = __float2half(v);
    }
}

__device__ void dev_pchead(const float* __restrict__ Wa, const float* __restrict__ ba){
    int gw = (blockIdx.x*NT + threadIdx.x) >> 5;
    int lane = threadIdx.x & 31;
    for (int row = gw; row < 4096; row += (NB*NT)>>5){
        int t = row >> 6, b = row & 63;
        float acc[15];
        #pragma unroll
        for (int a=0;a<15;a++) acc[a]=0.f;
        for (int d = lane; d < 512; d += 32){
            float te = g_TE[b*512 + d];
            float iv = g_obsinp[(b*T_ + t)*512 + d];
            #pragma unroll
            for (int a=0;a<15;a++)
                acc[a] += te*Wa[(512+d)*15 + a] + iv*Wa[(1024+d)*15 + a];
        }
        #pragma unroll
        for (int a=0;a<15;a++){
            float v = acc[a];
            #pragma unroll
            for (int off=16; off; off>>=1) v += __shfl_down_sync(0xffffffffu, v, off);
            if (lane == 0) g_PChead[row*16 + a] = v + ba[a];
        }
    }
}

// ---------------- warp-autonomous GEMM ----------------
// C(MxN) = A(MxK) @ Wt(NxK)^T + aux. 32x32 block tile; 8 warps each own a 16x8
// output fragment and a private 5-slot cp.async ring. No __syncthreads in loop.
// EPI 0: +bias[col] -> Cf ; EPI 3: +PC[row][col], relu -> Ch ; EPI 4: +PC[row/3][col], leaky -> Cf
template<int EPI>
__device__ __noinline__ void dev_gemm(const __half* __restrict__ A, int lda,
                                      const __half* __restrict__ Wt, int ldw,
                                      const float* __restrict__ aux, int ldaux,
                                      float* __restrict__ Cf, __half* __restrict__ Ch,
                                      int M, int N, int K,
                                      char* sm, unsigned smu)
{
    const int warp = threadIdx.x >> 5, lane = threadIdx.x & 31;
    const int wm = (warp & 1) * 16, wn8 = (warp >> 1) * 8;
    const int g  = lane >> 2,  tq = lane & 3;
    const int lr = lane >> 3;        // base row 0..3
    const int sg = lane & 7;         // 16B segment 0..7 within 128B row
    const int Ntiles = N >> 5;
    const int njobs = (M >> 5) * Ntiles;
    const int KT = K >> 6;

    const unsigned wu = smu + warp * WRING;
    const __half* wh = (const __half*)(sm + warp * WRING);

    for (int job = blockIdx.x; job < njobs; job += NB){
        const int bM = (job / Ntiles) << 5, bN = (job % Ntiles) << 5;
        // per-lane global srcs
        const __half* Ab = A  + (size_t)(bM + wm  + lr) * lda + sg*8;
        const __half* Wb = Wt + (size_t)(bN + wn8 + lr) * ldw + sg*8;

        CP_WAIT0();            // ring free from previous job
        __syncwarp();

        #pragma unroll
        for (int p = 0; p < 4; p++){
            if (p < KT){
                const unsigned du = wu + p*STAGEB + lr*144 + sg*16;
                const int ko = p*64;
                cpa16(du,          Ab + ko);
                cpa16(du + 4*144,  Ab + ko + (size_t)4*lda);
                cpa16(du + 8*144,  Ab + ko + (size_t)8*lda);
                cpa16(du + 12*144, Ab + ko + (size_t)12*lda);
                cpa16(du + 2304,         Wb + ko);
                cpa16(du + 2304 + 4*144, Wb + ko + (size_t)4*ldw);
            }
            CP_COMMIT();
        }

        float c0=0.f, c1=0.f, c2=0.f, c3=0.f;
        for (int kt = 0; kt < KT; kt++){
            CP_WAIT3();
            __syncwarp();
            const int slot = kt % DEPTH;
            const __half* Aw = wh + slot*(STAGEB/2);
            const __half* Ww = Aw + 1152;
            #pragma unroll
            for (int ks = 0; ks < 4; ks++){
                const int ko = ks * 16;
                unsigned a0 = *(const unsigned*)(Aw + g*72     + ko + tq*2);
                unsigned a1 = *(const unsigned*)(Aw + (g+8)*72 + ko + tq*2);
                unsigned a2 = *(const unsigned*)(Aw + g*72     + ko + 8 + tq*2);
                unsigned a3 = *(const unsigned*)(Aw + (g+8)*72 + ko + 8 + tq*2);
                unsigned b0 = *(const unsigned*)(Ww + g*72     + ko + tq*2);
                unsigned b1 = *(const unsigned*)(Ww + g*72     + ko + 8 + tq*2);
                asm volatile(
                    "mma.sync.aligned.m16n8k16.row.col.f32.f16.f16.f32 "
                    "{%0,%1,%2,%3},{%4,%5,%6,%7},{%8,%9},{%0,%1,%2,%3};\n"
                    : "+f"(c0), "+f"(c1), "+f"(c2), "+f"(c3)
                    : "r"(a0), "r"(a1), "r"(a2), "r"(a3), "r"(b0), "r"(b1));
            }
            if (kt + 4 < KT){
                const int ps = (kt+4) % DEPTH;
                const unsigned du = wu + ps*STAGEB + lr*144 + sg*16;
                const int ko = (kt+4)*64;
                cpa16(du,          Ab + ko);
                cpa16(du + 4*144,  Ab + ko + (size_t)4*lda);
                cpa16(du + 8*144,  Ab + ko + (size_t)8*lda);
                cpa16(du + 12*144, Ab + ko + (size_t)12*lda);
                cpa16(du + 2304,         Wb + ko);
                cpa16(du + 2304 + 4*144, Wb + ko + (size_t)4*ldw);
            }
            CP_COMMIT();
        }

        const int row = bM + wm + g;
        const int col = bN + wn8 + tq*2;
        float a00,a01,a10,a11;
        if (EPI == 0){
            a00 = aux[col]; a01 = aux[col+1]; a10 = a00; a11 = a01;
        } else if (EPI == 3){
            const float* p0 = aux + (size_t)row*ldaux;
            const float* p1 = aux + (size_t)(row+8)*ldaux;
            a00 = p0[col]; a01 = p0[col+1]; a10 = p1[col]; a11 = p1[col+1];
        } else {
            const float* p0 = aux + (size_t)(row/3)*ldaux;
            const float* p1 = aux + (size_t)((row+8)/3)*ldaux;
            a00 = p0[col]; a01 = p0[col+1]; a10 = p1[col]; a11 = p1[col+1];
        }
        float v00 = c0 + a00, v01 = c1 + a01, v10 = c2 + a10, v11 = c3 + a11;
        if (EPI == 3){
            v00 = fmaxf(v00,0.f); v01 = fmaxf(v01,0.f);
            v10 = fmaxf(v10,0.f); v11 = fmaxf(v11,0.f);
            *(__half2*)(Ch + (size_t)row*N + col)     = __floats2half2_rn(v00, v01);
            *(__half2*)(Ch + (size_t)(row+8)*N + col) = __floats2half2_rn(v10, v11);
        } else {
            if (EPI == 4){
                v00 = v00>0.f? v00 : 0.3f*v00;  v01 = v01>0.f? v01 : 0.3f*v01;
                v10 = v10>0.f? v10 : 0.3f*v10;  v11 = v11>0.f? v11 : 0.3f*v11;
            }
            *(float2*)(Cf + (size_t)row*N + col)     = make_float2(v00, v01);
            *(float2*)(Cf + (size_t)(row+8)*N + col) = make_float2(v10, v11);
        }
    }
}

// ---------------- elementwise stages (block b = batch row b) ----------------
__device__ void dev_pack_step(const float* __restrict__ inp){
    int b = blockIdx.x;
    if (b >= B_) return;
    for (int d = threadIdx.x; d < 512; d += NT){
        g_Xvh[b*1024 + d]       = __float2half(inp[b*(T_*D_) + d]);
        g_Xvh[b*1024 + 512 + d] = __float2half(g_M[b*1536 + 1024 + d]);
    }
}

__device__ __noinline__ void dev_com_post(const float* __restrict__ gamma, const float* __restrict__ beta,
                                          const float* __restrict__ inp, int slot,
                                          float* shs, float* shq)
{
    int b = blockIdx.x;
    if (b >= B_) return;
    const float* a = g_Af + b*2048;
    float gv[2], gh[2], gc[2];
    float s=0.f, q=0.f;
    #pragma unroll
    for (int j=0;j<2;j++){
        int d = threadIdx.x + j*256;
        gv[j]=a[d]; gh[j]=a[512+d]; gc[j]=a[1024+d];
        s += gv[j]+gh[j]+gc[j];
        q += gv[j]*gv[j]+gh[j]*gh[j]+gc[j]*gc[j];
    }
    float2 r = red2(s,q,shs,shq);
    float mu = r.x*(1.f/1536.f);
    float var = r.y*(1.f/1536.f) - mu*mu;
    float rs = rsqrtf(var + LEPS);

    float s2[2]; float ss=0.f, qq=0.f;
    #pragma unroll
    for (int j=0;j<2;j++){
        int d = threadIdx.x + j*256;
        float vg = sigmf((gv[j]-mu)*rs*gamma[d]      + beta[d]);
        float hg = sigmf((gh[j]-mu)*rs*gamma[512+d]  + beta[512+d]);
        float cg = sigmf((gc[j]-mu)*rs*gamma[1024+d] + beta[1024+d]);
        float viv = (slot==2) ? inp[b*(T_*D_) + d] : g_H[b*512 + d];
        float hiv = g_M[b*1536 + slot*512 + d];
        float cell = a[1536 + d];
        s2[j] = vg*viv + hg*hiv + cg*cell;
        ss += s2[j]; qq += s2[j]*s2[j];
    }
    float2 r2 = red2(ss,qq,shs,shq);
    float mu2 = r2.x*(1.f/512.f);
    float var2 = r2.y*(1.f/512.f) - mu2*mu2;
    float rs2 = rsqrtf(var2 + LEPS);

    #pragma unroll
    for (int j=0;j<2;j++){
        int d = threadIdx.x + j*256;
        float hnew = (s2[j]-mu2)*rs2;
        g_H[b*512 + d] = hnew;
        g_cand[b*1536 + slot*512 + d] = hnew;
        if (slot > 0){
            g_Xvh[b*1024 + d]       = __float2half(hnew);
            g_Xvh[b*1024 + 512 + d] = __float2half(g_M[b*1536 + (slot-1)*512 + d]);
        } else {
            #pragma unroll
            for (int n=0;n<3;n++){
                int rr = b*3 + n;
                g_Xpc[rr*1024 + d]       = __float2half(g_M[b*1536 + n*512 + d]);
                float cv = (n==0) ? hnew : g_cand[b*1536 + n*512 + d];
                g_Xpc[rr*1024 + 512 + d] = __float2half(cv);
            }
        }
    }
}

__device__ __noinline__ void dev_stick(const float* __restrict__ Wd2, const float* __restrict__ bd2,
                                       float* __restrict__ out_ph, int t,
                                       float* shs, float* shq)
{
    int b = blockIdx.x;
    if (b >= B_) return;
    float a0=0.f, a1=0.f, a2=0.f;
    #pragma unroll
    for (int j=0;j<2;j++){
        int d = threadIdx.x + j*256;
        float w = Wd2[d];
        a0 += g_H1[(b*3+0)*512 + d]*w;
        a1 += g_H1[(b*3+1)*512 + d]*w;
        a2 += g_H1[(b*3+2)*512 + d]*w;
    }
    float dot0 = red1(a0, shs);
    float dot1 = red1(a1, shs);
    float dot2 = red1(a2, shs);
    if (threadIdx.x == 0){
        float bb = bd2[0];
        float b0 = sigmf(dot0+bb), b1 = sigmf(dot1+bb), b2 = sigmf(dot2+bb);
        float y0 = 1.f-b2, y1 = y0*(1.f-b1), y2 = y1*(1.f-b0);
        float ph0 = y2, ph1 = b0*y1, ph2 = b1*y0, ph3 = b2;
        float* op = out_ph + (size_t)(b*T_ + t)*4;
        op[0]=ph0; op[1]=ph1; op[2]=ph2; op[3]=ph3;
        float inv = 1.f/(ph1+ph2+ph3);
        float p0 = ph1*inv, p1 = ph2*inv, p2 = ph3*inv;
        g_P[b*3]=p0; g_P[b*3+1]=p1; g_P[b*3+2]=p2;
        g_PE[b] = ph0;
        shq[0] = p0+p1+p2;
        shq[1] = p1+p2;
        shq[2] = p2;
    }
    __syncthreads();
    float rc0 = shq[0], rc1 = shq[1], rc2 = shq[2];
    #pragma unroll
    for (int j=0;j<2;j++){
        int d = threadIdx.x + j*256;
        float m0;
        {
            float mm = g_M[b*1536 + d]*(1.f-rc0) + g_cand[b*1536 + d]*rc0;
            g_M[b*1536 + d] = mm; m0 = mm;
        }
        {
            float mm = g_M[b*1536 + 512 + d]*(1.f-rc1) + g_cand[b*1536 + 512 + d]*rc1;
            g_M[b*1536 + 512 + d] = mm;
        }
        {
            float mm = g_M[b*1536 + 1024 + d]*(1.f-rc2) + g_cand[b*1536 + 1024 + d]*rc2;
            g_M[b*1536 + 1024 + d] = mm;
        }
        g_chl[b*1536 + d] = m0;
        g_Xp[b*512 + d] = __float2half(m0);
    }
    __syncthreads();
}

__device__ __noinline__ void dev_dec_post(const float* __restrict__ gamma, const float* __restrict__ beta,
                                          int slot, float* shs, float* shq)
{
    int b = blockIdx.x;
    if (b >= B_) return;
    const float* a = g_Af + b*1536;
    float g0[2], g1[2];
    float s=0.f, q=0.f;
    #pragma unroll
    for (int j=0;j<2;j++){
        int d = threadIdx.x + j*256;
        g0[j]=a[d]; g1[j]=a[512+d];
        s += g0[j]+g1[j];
        q += g0[j]*g0[j]+g1[j]*g1[j];
    }
    float2 r = red2(s,q,shs,shq);
    float mu = r.x*(1.f/1024.f);
    float var = r.y*(1.f/1024.f) - mu*mu;
    float rs = rsqrtf(var + LEPS);

    float s2[2]; float ss=0.f, qq=0.f;
    #pragma unroll
    for (int j=0;j<2;j++){
        int d = threadIdx.x + j*256;
        float gate  = sigmf((g0[j]-mu)*rs*gamma[d]     + beta[d]);
        float cgate = sigmf((g1[j]-mu)*rs*gamma[512+d] + beta[512+d]);
        float parent = g_chl[b*1536 + slot*512 + d];
        float cell = a[1024 + d];
        s2[j] = gate*parent + cgate*cell;
        ss += s2[j]; qq += s2[j]*s2[j];
    }
    float2 r2 = red2(ss,qq,shs,shq);
    float mu2 = r2.x*(1.f/512.f);
    float var2 = r2.y*(1.f/512.f) - mu2*mu2;
    float rs2 = rsqrtf(var2 + LEPS);

    #pragma unroll
    for (int j=0;j<2;j++){
        int d = threadIdx.x + j*256;
        float hnew = (s2[j]-mu2)*rs2;
        g_chl[b*1536 + (slot+1)*512 + d] = hnew;
        if (slot == 0) g_Xp[b*512 + d] = __float2half(hnew);
    }
}

__device__ __noinline__ void dev_head(const float* __restrict__ Wa,
                                      float* __restrict__ out_lg, int t, float* shs)
{
    int b = blockIdx.x;
    if (b >= B_) return;
    if (threadIdx.x < 15) shs[threadIdx.x] = 0.f;
    __syncthreads();

    float p0 = g_P[b*3], p1 = g_P[b*3+1], p2 = g_P[b*3+2];
    float acc[15];
    #pragma unroll
    for (int a=0;a<15;a++) acc[a]=0.f;
    for (int d = threadIdx.x; d < 512; d += NT){
        float x = p0*g_chl[b*1536 + d] + p1*g_chl[b*1536 + 512 + d] + p2*g_chl[b*1536 + 1024 + d];
        #pragma unroll
        for (int a=0;a<15;a++) acc[a] += x * Wa[d*15 + a];
    }
    #pragma unroll
    for (int a=0;a<15;a++){
        float v = acc[a];
        #pragma unroll
        for (int off=16; off; off>>=1) v += __shfl_down_sync(0xffffffffu, v, off);
        if ((threadIdx.x & 31) == 0) atomicAdd(&shs[a], v);
    }
    __syncthreads();

    if (threadIdx.x == 0){
        const float* pc = g_PChead + (size_t)(t*64 + b)*16;
        float lg[15], mx = -1e30f;
        #pragma unroll
        for (int a=0;a<15;a++){ lg[a] = shs[a] + pc[a]; mx = fmaxf(mx, lg[a]); }
        float sum = 0.f;
        #pragma unroll
        for (int a=0;a<15;a++){ lg[a] = expf(lg[a]-mx); sum += lg[a]; }
        float pe = g_PE[b];
        pe = fminf(fmaxf(pe, 1e-6f), 1.f - 1e-6f);
        float scale = (1.f - pe)/sum;
        float* op = out_lg + (size_t)(b*T_ + t)*16;
        #pragma unroll
        for (int a=0;a<15;a++){
            int j = (a < 5) ? a : a + 1;
            op[j] = logf(lg[a]*scale);
        }
        op[5] = logf(pe);
    }
    __syncthreads();
}

// ---------------- megakernel ----------------
__global__ void __launch_bounds__(NT, 1)
mega_kernel(const float* obs, const int* env_ids, const float* prev_m,
            const float* emb, const float* W_obs, const float* b_obs,
            const float* com_W1, const float* com_b1, const float* com_W2, const float* com_b2,
            const float* com_g, const float* com_beta,
            const float* dec_W1, const float* dec_b1, const float* dec_W2, const float* dec_b2,
            const float* dec_g, const float* dec_beta,
            const float* Wd1, const float* bd1, const float* Wd2, const float* bd2,
            const float* Wa, const float* ba,
            float* out_logits, float* out_ph)
{
    extern __shared__ char dynsm[];
    __shared__ float shs[16], shq[16];
    unsigned smu = (unsigned)__cvta_generic_to_shared(dynsm);
    __half (*S)[72] = (__half(*)[72])dynsm;

    // stage 0: transpose-convert weights, convert obs, gather/prep state
    for (int i = 0; i < 3; i++){
        dev_tcvt(com_W1 + (size_t)i*2048*2048, g_comW1t + (size_t)i*2048*2048, 2048, 2048, S);
        dev_tcvt(com_W2 + (size_t)i*2048*2048, g_comW2t + (size_t)i*2048*2048, 2048, 2048, S);
    }
    for (int i = 0; i < 2; i++){
        dev_tcvt(dec_W1 + (size_t)i*1536*2048, g_decW1t + (size_t)i*2048*1536, 1536, 2048, S);
        dev_tcvt(dec_W2 + (size_t)i*2048*1536, g_decW2t + (size_t)i*1536*2048, 2048, 1536, S);
    }
    dev_tcvt(Wd1,   g_Wd1t,  2048, 512, S);
    dev_tcvt(W_obs, g_Wobst, 128,  512, S);
    dev_cvt4(obs, g_obsh, B_*T_*128/4);
    dev_prep(emb, env_ids, prev_m);
    gridbar();

    // obs encoder
    dev_gemm<0>(g_obsh, 128, g_Wobst, 128, b_obs, 0, g_obsinp, nullptr,
                B_*T_, 512, 128, dynsm, smu);
    gridbar();

    dev_xcomb();
    dev_pchead(Wa, ba);
    dev_pack_step(g_obsinp);
    gridbar();

    // precompute comb-dependent GEMM halves
    for (int i = 0; i < 3; i++)
        dev_gemm<0>(g_Xcomb, 1024, g_comW1t + (size_t)i*2048*2048 + 1024, 2048,
                    com_b1 + i*2048, 0, g_PCcom + (size_t)i*4096*2048, nullptr,
                    4096, 2048, 1024, dynsm, smu);
    for (int i = 0; i < 2; i++)
        dev_gemm<0>(g_Xcomb, 1024, g_decW1t + (size_t)i*2048*1536 + 512, 1536,
                    dec_b1 + i*2048, 0, g_PCdec + (size_t)i*4096*2048, nullptr,
                    4096, 2048, 1024, dynsm, smu);
    dev_gemm<0>(g_Xcomb, 1024, g_Wd1t, 2048, bd1, 0, g_PCdist, nullptr,
                4096, 512, 1024, dynsm, smu);
    gridbar();

    for (int t = 0; t < T_; t++){
        const float* inp = g_obsinp + t*512;

        for (int i = 2; i >= 0; i--){
            dev_gemm<3>(g_Xvh, 1024, g_comW1t + (size_t)i*2048*2048, 2048,
                        g_PCcom + ((size_t)i*4096 + t*64)*2048, 2048,
                        nullptr, g_A1h, 64, 2048, 1024, dynsm, smu);
            gridbar();
            dev_gemm<0>(g_A1h, 2048, g_comW2t + (size_t)i*2048*2048, 2048,
                        com_b2 + i*2048, 0, g_Af, nullptr, 64, 2048, 2048, dynsm, smu);
            gridbar();
            dev_com_post(com_g + i*1536, com_beta + i*1536, inp, i, shs, shq);
            gridbar();
        }

        dev_gemm<4>(g_Xpc, 1024, g_Wd1t + 1024, 2048,
                    g_PCdist + (size_t)t*64*512, 512,
                    g_H1, nullptr, 192, 512, 1024, dynsm, smu);
        gridbar();
        dev_stick(Wd2, bd2, out_ph, t, shs, shq);
        gridbar();

        for (int i = 0; i < 2; i++){
            dev_gemm<3>(g_Xp, 512, g_decW1t + (size_t)i*2048*1536, 1536,
                        g_PCdec + ((size_t)i*4096 + t*64)*2048, 2048,
                        nullptr, g_A1h, 64, 2048, 512, dynsm, smu);
            gridbar();
            dev_gemm<0>(g_A1h, 2048, g_decW2t + (size_t)i*1536*2048, 2048,
                        dec_b2 + i*1536, 0, g_Af, nullptr, 64, 1536, 2048, dynsm, smu);
            gridbar();
            dev_dec_post(dec_g + i*1024, dec_beta + i*1024, i, shs, shq);
            gridbar();
        }

        dev_head(Wa, out_logits, t, shs);
        if (t + 1 < T_) dev_pack_step(g_obsinp + (t+1)*512);
        gridbar();
    }
}

// ---------------- launch ----------------
extern "C" void kernel_launch(void* const* d_in, const int* in_sizes, int n_in,
                              void* d_out, int out_size)
{
    const float* obs      = (const float*)d_in[0];
    const int*   env_ids  = (const int*)  d_in[1];
    const float* prev_m   = (const float*)d_in[2];
    const float* emb      = (const float*)d_in[4];
    const float* W_obs    = (const float*)d_in[5];
    const float* b_obs    = (const float*)d_in[6];
    const float* com_W1   = (const float*)d_in[7];
    const float* com_b1   = (const float*)d_in[8];
    const float* com_W2   = (const float*)d_in[9];
    const float* com_b2   = (const float*)d_in[10];
    const float* com_g    = (const float*)d_in[11];
    const float* com_beta = (const float*)d_in[12];
    const float* dec_W1   = (const float*)d_in[13];
    const float* dec_b1   = (const float*)d_in[14];
    const float* dec_W2   = (const float*)d_in[15];
    const float* dec_b2   = (const float*)d_in[16];
    const float* dec_g    = (const float*)d_in[17];
    const float* dec_beta = (const float*)d_in[18];
    const float* Wd1      = (const float*)d_in[19];
    const float* bd1      = (const float*)d_in[20];
    const float* Wd2      = (const float*)d_in[21];
    const float* bd2      = (const float*)d_in[22];
    const float* Wa       = (const float*)d_in[23];
    const float* ba       = (const float*)d_in[24];

    float* out_logits = (float*)d_out;
    float* out_ph     = (float*)d_out + B_*T_*16;

    static bool attr_set = false;
    if (!attr_set){
        cudaFuncSetAttribute(mega_kernel, cudaFuncAttributeMaxDynamicSharedMemorySize, SMEMB);
        attr_set = true;
    }

    mega_kernel<<<NB, NT, SMEMB>>>(obs, env_ids, prev_m, emb, W_obs, b_obs,
                            com_W1, com_b1, com_W2, com_b2, com_g, com_beta,
                            dec_W1, dec_b1, dec_W2, dec_b2, dec_g, dec_beta,
                            Wd1, bd1, Wd2, bd2, Wa, ba,
                            out_logits, out_ph);
}

// round 12
// speedup vs baseline: 1.0417x; 1.0417x over previous
#include <cuda_runtime.h>
#include <cuda_fp16.h>
#include <math.h>

#define NB 128
#define NT 256
#define B_   64
#define T_   64
#define D_   512
#define LEPS 1e-3f
#define STAGEB 17408           // A 32*272 + W 32*272
#define DEPTH  4
#define SMEMB  (DEPTH*STAGEB)  // 69632 B

// ---------------- static device scratch ----------------
static __device__ __align__(16) __half g_comW1t[3ull*2048*2048];
static __device__ __align__(16) __half g_comW2t[3ull*2048*2048];
static __device__ __align__(16) __half g_decW1t[2ull*2048*1536];  // [slot][n=2048][k=1536]
static __device__ __align__(16) __half g_decW2t[2ull*1536*2048];  // [slot][n=1536][k=2048]
static __device__ __align__(16) __half g_Wd1t[512*2048];          // [n=512][k=2048]
static __device__ __align__(16) __half g_Wobst[512*128];          // [n=512][k=128]
static __device__ __align__(16) __half g_obsh[B_*T_*128];
static __device__ __align__(16) __half g_Xcomb[4096*1024];        // [(t*64+b)][1024]
static __device__ __align__(16) __half g_Xvh[B_*1024];            // [vi, hi]
static __device__ __align__(16) __half g_Xpc[B_*3*1024];          // [pm, cand]
static __device__ __align__(16) __half g_Xp[B_*512];              // parent
static __device__ __align__(16) __half g_A1h[B_*2048];
static __device__ __align__(16) float  g_obsinp[B_*T_*D_];
static __device__ __align__(16) float  g_PCcom[3ull*4096*2048];
static __device__ __align__(16) float  g_PCdec[2ull*4096*2048];
static __device__ __align__(16) float  g_PCdist[4096*512];
static __device__ __align__(16) float  g_PChead[4096*16];
static __device__ __align__(16) float  g_Af[B_*2048];
static __device__ __align__(16) float  g_H1[B_*3*D_];
static __device__ __align__(16) float  g_H[B_*D_];
static __device__ __align__(16) float  g_M[B_*3*D_];
static __device__ __align__(16) float  g_cand[B_*3*D_];
static __device__ __align__(16) float  g_chl[B_*3*D_];
static __device__ __align__(16) float  g_TE[B_*D_];
static __device__              float  g_P[B_*3];
static __device__              float  g_PE[B_];

// ---------------- hierarchical grid barrier ----------------
static __device__ __align__(128) unsigned g_sub[8*32];   // 8 counters on separate lines
static __device__ unsigned g_root = 0;
static __device__ unsigned g_gen = 0;

__device__ __forceinline__ unsigned ld_acq(unsigned* p){
    unsigned v;
    asm volatile("ld.acquire.gpu.global.u32 %0, [%1];" : "=r"(v) : "l"(p));
    return v;
}

__device__ __forceinline__ void gridbar(){
    __syncthreads();
    if (threadIdx.x == 0){
        unsigned g = g_gen;   // changes only at release
        unsigned* sub = &g_sub[(blockIdx.x & 7) * 32];
        unsigned old;
        asm volatile("atom.acq_rel.gpu.global.add.u32 %0, [%1], 1;"
                     : "=r"(old) : "l"(sub));
        bool release = false;
        if (old == 15){                   // last of 16 in subgroup
            *sub = 0;
            unsigned r;
            asm volatile("atom.acq_rel.gpu.global.add.u32 %0, [%1], 1;"
                         : "=r"(r) : "l"(&g_root));
            if (r == 7){
                g_root = 0;
                asm volatile("st.release.gpu.global.u32 [%0], %1;"
                             :: "l"(&g_gen), "r"(g + 1));
                release = true;
            }
        }
        if (!release){
            while (ld_acq(&g_gen) == g) __nanosleep(20);
        }
    }
    __syncthreads();
}

// ---------------- helpers (8 warps) ----------------
__device__ __forceinline__ float sigmf(float x){ return 1.f/(1.f+expf(-x)); }

__device__ __forceinline__ float2 red2(float s, float q, float* shs, float* shq){
    int lane = threadIdx.x & 31, w = threadIdx.x >> 5;
    #pragma unroll
    for (int off=16; off; off>>=1){
        s += __shfl_down_sync(0xffffffffu, s, off);
        q += __shfl_down_sync(0xffffffffu, q, off);
    }
    if (lane==0){ shs[w]=s; shq[w]=q; }
    __syncthreads();
    if (w==0){
        s = (lane<8)? shs[lane] : 0.f;
        q = (lane<8)? shq[lane] : 0.f;
        #pragma unroll
        for (int off=4; off; off>>=1){
            s += __shfl_down_sync(0xffffffffu, s, off);
            q += __shfl_down_sync(0xffffffffu, q, off);
        }
        if (lane==0){ shs[0]=s; shq[0]=q; }
    }
    __syncthreads();
    float2 r = make_float2(shs[0], shq[0]);
    __syncthreads();
    return r;
}

__device__ __forceinline__ float red1(float s, float* shs){
    int lane = threadIdx.x & 31, w = threadIdx.x >> 5;
    #pragma unroll
    for (int off=16; off; off>>=1) s += __shfl_down_sync(0xffffffffu, s, off);
    if (lane==0) shs[w]=s;
    __syncthreads();
    if (w==0){
        s = (lane<8)? shs[lane] : 0.f;
        #pragma unroll
        for (int off=4; off; off>>=1) s += __shfl_down_sync(0xffffffffu, s, off);
        if (lane==0) shs[0]=s;
    }
    __syncthreads();
    float r = shs[0];
    __syncthreads();
    return r;
}

// ---------------- cp.async ----------------
__device__ __forceinline__ void cpa16(unsigned saddr, const void* g){
    asm volatile("cp.async.ca.shared.global [%0], [%1], 16;" :: "r"(saddr), "l"(g));
}
#define CP_COMMIT() asm volatile("cp.async.commit_group;")
#define CP_WAIT2()  asm volatile("cp.async.wait_group 2;")

// ---------------- transpose-convert: W(KxN fp32) -> Wt(NxK fp16) ----------------
__device__ void dev_tcvt(const float* __restrict__ W, __half* __restrict__ Wt,
                         int K, int N, __half (*S)[72])
{
    const int tid = threadIdx.x;
    const int r = tid >> 3, c4 = (tid & 7) * 4;
    const int Ntl = N >> 5;
    const int jobs = (K >> 5) * Ntl;
    for (int job = blockIdx.x; job < jobs; job += NB){
        const int k0 = (job / Ntl) << 5, n0 = (job % Ntl) << 5;
        __syncthreads();
        float4 v = *(const float4*)(W + (size_t)(k0 + r)*N + n0 + c4);
        S[r][c4]   = __float2half(v.x);
        S[r][c4+1] = __float2half(v.y);
        S[r][c4+2] = __float2half(v.z);
        S[r][c4+3] = __float2half(v.w);
        __syncthreads();
        __half2 h0 = __halves2half2(S[c4][r],   S[c4+1][r]);
        __half2 h1 = __halves2half2(S[c4+2][r], S[c4+3][r]);
        *(__half2*)(Wt + (size_t)(n0 + r)*K + k0 + c4)     = h0;
        *(__half2*)(Wt + (size_t)(n0 + r)*K + k0 + c4 + 2) = h1;
    }
    __syncthreads();
}

// ---------------- convert fp32 -> fp16 ----------------
__device__ void dev_cvt4(const float* __restrict__ s, __half* __restrict__ d, int n4){
    const float4* s4 = (const float4*)s;
    __half2* d2 = (__half2*)d;
    for (int i = blockIdx.x*NT + threadIdx.x; i < n4; i += NB*NT){
        float4 v = s4[i];
        d2[2*i]   = __floats2half2_rn(v.x, v.y);
        d2[2*i+1] = __floats2half2_rn(v.z, v.w);
    }
}

__device__ void dev_prep(const float* __restrict__ emb, const int* __restrict__ ids,
                         const float* __restrict__ prevm){
    int i0 = blockIdx.x*NT + threadIdx.x, stride = NB*NT;
    for (int i = i0; i < B_*D_; i += stride){
        int b = i >> 9;
        g_TE[i] = emb[ids[b]*D_ + (i & 511)];
    }
    for (int i = i0; i < B_*3*D_; i += stride) g_M[i] = prevm[i];
}

__device__ void dev_xcomb(){
    for (int i = blockIdx.x*NT + threadIdx.x; i < 4096*1024; i += NB*NT){
        int row = i >> 10, d = i & 1023;
        int t = row >> 6, b = row & 63;
        float v = (d < 512) ? g_obsinp[(b*T_ + t)*512 + d]
                            : g_TE[b*512 + (d - 512)];
        g_Xcomb[i] = __float2half(v);
    }
}

__device__ void dev_pchead(const float* __restrict__ Wa, const float* __restrict__ ba){
    int gw = (blockIdx.x*NT + threadIdx.x) >> 5;
    int lane = threadIdx.x & 31;
    for (int row = gw; row < 4096; row += (NB*NT)>>5){
        int t = row >> 6, b = row & 63;
        float acc[15];
        #pragma unroll
        for (int a=0;a<15;a++) acc[a]=0.f;
        for (int d = lane; d < 512; d += 32){
            float te = g_TE[b*512 + d];
            float iv = g_obsinp[(b*T_ + t)*512 + d];
            #pragma unroll
            for (int a=0;a<15;a++)
                acc[a] += te*Wa[(512+d)*15 + a] + iv*Wa[(1024+d)*15 + a];
        }
        #pragma unroll
        for (int a=0;a<15;a++){
            float v = acc[a];
            #pragma unroll
            for (int off=16; off; off>>=1) v += __shfl_down_sync(0xffffffffu, v, off);
            if (lane == 0) g_PChead[row*16 + a] = v + ba[a];
        }
    }
}

// ---------------- GEMM: C = A(MxK)@Wt(NxK)^T + aux ; 32x32 tiles, BK=128 ----------------
// 4-deep cp.async ring; ONE __syncthreads per 128-wide k-chunk.
// EPI 0: +bias[col] -> Cf ; EPI 3: +PC[row][col], relu -> Ch ; EPI 4: +PC[row/3][col], leaky -> Cf
template<int EPI>
__device__ __noinline__ void dev_gemm(const __half* __restrict__ A, int lda,
                                      const __half* __restrict__ Wt, int ldw,
                                      const float* __restrict__ aux, int ldaux,
                                      float* __restrict__ Cf, __half* __restrict__ Ch,
                                      int M, int N, int K,
                                      unsigned smu, char* smp)
{
    const int tid  = threadIdx.x;
    const int warp = tid >> 5, lane = tid & 31;
    const int wm = (warp & 1) * 16, wn = (warp >> 1) * 8;
    const int g  = lane >> 2,  tq = lane & 3;
    const int lrow = tid >> 3, lseg = tid & 7;   // 32 rows x 8 thread-segs
    const int Ntiles = N >> 5;
    const int njobs = (M >> 5) * Ntiles;
    const int KT = K >> 7;

    for (int job = blockIdx.x; job < njobs; job += NB){
        const int bM = (job / Ntiles) << 5, bN = (job % Ntiles) << 5;
        const __half* Ab = A  + (size_t)(bM + lrow) * lda + lseg*8;
        const __half* Wb = Wt + (size_t)(bN + lrow) * ldw + lseg*8;
        const unsigned dA = smu + lrow*272 + lseg*16;
        const unsigned dW = dA + 8704;

        __syncthreads();   // previous consumers done with ring
        #pragma unroll
        for (int p = 0; p < 3; p++){
            if (p < KT){
                const int ko = p*128;
                const unsigned so = p*STAGEB;
                cpa16(dA + so,       Ab + ko);
                cpa16(dA + so + 128, Ab + ko + 64);
                cpa16(dW + so,       Wb + ko);
                cpa16(dW + so + 128, Wb + ko + 64);
            }
            CP_COMMIT();
        }

        float c0=0.f, c1=0.f, c2=0.f, c3=0.f;
        for (int kt = 0; kt < KT; kt++){
            CP_WAIT2();
            __syncthreads();
            if (kt + 3 < KT){
                const unsigned so = ((kt+3)&3)*STAGEB;
                const int ko = (kt+3)*128;
                cpa16(dA + so,       Ab + ko);
                cpa16(dA + so + 128, Ab + ko + 64);
                cpa16(dW + so,       Wb + ko);
                cpa16(dW + so + 128, Wb + ko + 64);
            }
            CP_COMMIT();
            const char* base = smp + (kt & 3)*STAGEB;
            const __half* As = (const __half*)base;
            const __half* Ws = (const __half*)(base + 8704);
            #pragma unroll
            for (int ks = 0; ks < 8; ks++){
                const int ko = ks * 16;
                unsigned a0 = *(const unsigned*)(As + (wm+g)*136   + ko + tq*2);
                unsigned a1 = *(const unsigned*)(As + (wm+g+8)*136 + ko + tq*2);
                unsigned a2 = *(const unsigned*)(As + (wm+g)*136   + ko + 8 + tq*2);
                unsigned a3 = *(const unsigned*)(As + (wm+g+8)*136 + ko + 8 + tq*2);
                unsigned b0 = *(const unsigned*)(Ws + (wn+g)*136   + ko + tq*2);
                unsigned b1 = *(const unsigned*)(Ws + (wn+g)*136   + ko + 8 + tq*2);
                asm volatile(
                    "mma.sync.aligned.m16n8k16.row.col.f32.f16.f16.f32 "
                    "{%0,%1,%2,%3},{%4,%5,%6,%7},{%8,%9},{%0,%1,%2,%3};\n"
                    : "+f"(c0), "+f"(c1), "+f"(c2), "+f"(c3)
                    : "r"(a0), "r"(a1), "r"(a2), "r"(a3), "r"(b0), "r"(b1));
            }
        }

        const int row = bM + wm + g;
        const int col = bN + wn + tq*2;
        float a00,a01,a10,a11;
        if (EPI == 0){
            a00 = aux[col]; a01 = aux[col+1]; a10 = a00; a11 = a01;
        } else if (EPI == 3){
            const float* p0 = aux + (size_t)row*ldaux;
            const float* p1 = aux + (size_t)(row+8)*ldaux;
            a00 = p0[col]; a01 = p0[col+1]; a10 = p1[col]; a11 = p1[col+1];
        } else {
            const float* p0 = aux + (size_t)(row/3)*ldaux;
            const float* p1 = aux + (size_t)((row+8)/3)*ldaux;
            a00 = p0[col]; a01 = p0[col+1]; a10 = p1[col]; a11 = p1[col+1];
        }
        float v00 = c0 + a00, v01 = c1 + a01, v10 = c2 + a10, v11 = c3 + a11;
        if (EPI == 3){
            v00 = fmaxf(v00,0.f); v01 = fmaxf(v01,0.f);
            v10 = fmaxf(v10,0.f); v11 = fmaxf(v11,0.f);
            *(__half2*)(Ch + (size_t)row*N + col)     = __floats2half2_rn(v00, v01);
            *(__half2*)(Ch + (size_t)(row+8)*N + col) = __floats2half2_rn(v10, v11);
        } else {
            if (EPI == 4){
                v00 = v00>0.f? v00 : 0.3f*v00;  v01 = v01>0.f? v01 : 0.3f*v01;
                v10 = v10>0.f? v10 : 0.3f*v10;  v11 = v11>0.f? v11 : 0.3f*v11;
            }
            *(float2*)(Cf + (size_t)row*N + col)     = make_float2(v00, v01);
            *(float2*)(Cf + (size_t)(row+8)*N + col) = make_float2(v10, v11);
        }
    }
}

// ---------------- elementwise stages (block b = batch row b) ----------------
__device__ void dev_pack_step(const float* __restrict__ inp){
    int b = blockIdx.x;
    if (b >= B_) return;
    for (int d = threadIdx.x; d < 512; d += NT){
        g_Xvh[b*1024 + d]       = __float2half(inp[b*(T_*D_) + d]);
        g_Xvh[b*1024 + 512 + d] = __float2half(g_M[b*1536 + 1024 + d]);
    }
}

__device__ __noinline__ void dev_com_post(const float* __restrict__ gamma, const float* __restrict__ beta,
                                          const float* __restrict__ inp, int slot,
                                          float* shs, float* shq)
{
    int b = blockIdx.x;
    if (b >= B_) return;
    const float* a = g_Af + b*2048;
    float gv[2], gh[2], gc[2];
    float s=0.f, q=0.f;
    #pragma unroll
    for (int j=0;j<2;j++){
        int d = threadIdx.x + j*256;
        gv[j]=a[d]; gh[j]=a[512+d]; gc[j]=a[1024+d];
        s += gv[j]+gh[j]+gc[j];
        q += gv[j]*gv[j]+gh[j]*gh[j]+gc[j]*gc[j];
    }
    float2 r = red2(s,q,shs,shq);
    float mu = r.x*(1.f/1536.f);
    float var = r.y*(1.f/1536.f) - mu*mu;
    float rs = rsqrtf(var + LEPS);

    float s2[2]; float ss=0.f, qq=0.f;
    #pragma unroll
    for (int j=0;j<2;j++){
        int d = threadIdx.x + j*256;
        float vg = sigmf((gv[j]-mu)*rs*gamma[d]      + beta[d]);
        float hg = sigmf((gh[j]-mu)*rs*gamma[512+d]  + beta[512+d]);
        float cg = sigmf((gc[j]-mu)*rs*gamma[1024+d] + beta[1024+d]);
        float viv = (slot==2) ? inp[b*(T_*D_) + d] : g_H[b*512 + d];
        float hiv = g_M[b*1536 + slot*512 + d];
        float cell = a[1536 + d];
        s2[j] = vg*viv + hg*hiv + cg*cell;
        ss += s2[j]; qq += s2[j]*s2[j];
    }
    float2 r2 = red2(ss,qq,shs,shq);
    float mu2 = r2.x*(1.f/512.f);
    float var2 = r2.y*(1.f/512.f) - mu2*mu2;
    float rs2 = rsqrtf(var2 + LEPS);

    #pragma unroll
    for (int j=0;j<2;j++){
        int d = threadIdx.x + j*256;
        float hnew = (s2[j]-mu2)*rs2;
        g_H[b*512 + d] = hnew;
        g_cand[b*1536 + slot*512 + d] = hnew;
        if (slot > 0){
            g_Xvh[b*1024 + d]       = __float2half(hnew);
            g_Xvh[b*1024 + 512 + d] = __float2half(g_M[b*1536 + (slot-1)*512 + d]);
        } else {
            #pragma unroll
            for (int n=0;n<3;n++){
                int rr = b*3 + n;
                g_Xpc[rr*1024 + d]       = __float2half(g_M[b*1536 + n*512 + d]);
                float cv = (n==0) ? hnew : g_cand[b*1536 + n*512 + d];
                g_Xpc[rr*1024 + 512 + d] = __float2half(cv);
            }
        }
    }
}

__device__ __noinline__ void dev_stick(const float* __restrict__ Wd2, const float* __restrict__ bd2,
                                       float* __restrict__ out_ph, int t,
                                       float* shs, float* shq)
{
    int b = blockIdx.x;
    if (b >= B_) return;
    float a0=0.f, a1=0.f, a2=0.f;
    #pragma unroll
    for (int j=0;j<2;j++){
        int d = threadIdx.x + j*256;
        float w = Wd2[d];
        a0 += g_H1[(b*3+0)*512 + d]*w;
        a1 += g_H1[(b*3+1)*512 + d]*w;
        a2 += g_H1[(b*3+2)*512 + d]*w;
    }
    float dot0 = red1(a0, shs);
    float dot1 = red1(a1, shs);
    float dot2 = red1(a2, shs);
    if (threadIdx.x == 0){
        float bb = bd2[0];
        float b0 = sigmf(dot0+bb), b1 = sigmf(dot1+bb), b2 = sigmf(dot2+bb);
        float y0 = 1.f-b2, y1 = y0*(1.f-b1), y2 = y1*(1.f-b0);
        float ph0 = y2, ph1 = b0*y1, ph2 = b1*y0, ph3 = b2;
        float* op = out_ph + (size_t)(b*T_ + t)*4;
        op[0]=ph0; op[1]=ph1; op[2]=ph2; op[3]=ph3;
        float inv = 1.f/(ph1+ph2+ph3);
        float p0 = ph1*inv, p1 = ph2*inv, p2 = ph3*inv;
        g_P[b*3]=p0; g_P[b*3+1]=p1; g_P[b*3+2]=p2;
        g_PE[b] = ph0;
        shq[0] = p0+p1+p2;
        shq[1] = p1+p2;
        shq[2] = p2;
    }
    __syncthreads();
    float rc0 = shq[0], rc1 = shq[1], rc2 = shq[2];
    #pragma unroll
    for (int j=0;j<2;j++){
        int d = threadIdx.x + j*256;
        float m0;
        {
            float mm = g_M[b*1536 + d]*(1.f-rc0) + g_cand[b*1536 + d]*rc0;
            g_M[b*1536 + d] = mm; m0 = mm;
        }
        {
            float mm = g_M[b*1536 + 512 + d]*(1.f-rc1) + g_cand[b*1536 + 512 + d]*rc1;
            g_M[b*1536 + 512 + d] = mm;
        }
        {
            float mm = g_M[b*1536 + 1024 + d]*(1.f-rc2) + g_cand[b*1536 + 1024 + d]*rc2;
            g_M[b*1536 + 1024 + d] = mm;
        }
        g_chl[b*1536 + d] = m0;
        g_Xp[b*512 + d] = __float2half(m0);
    }
    __syncthreads();
}

__device__ __noinline__ void dev_dec_post(const float* __restrict__ gamma, const float* __restrict__ beta,
                                          int slot, float* shs, float* shq)
{
    int b = blockIdx.x;
    if (b >= B_) return;
    const float* a = g_Af + b*1536;
    float g0[2], g1[2];
    float s=0.f, q=0.f;
    #pragma unroll
    for (int j=0;j<2;j++){
        int d = threadIdx.x + j*256;
        g0[j]=a[d]; g1[j]=a[512+d];
        s += g0[j]+g1[j];
        q += g0[j]*g0[j]+g1[j]*g1[j];
    }
    float2 r = red2(s,q,shs,shq);
    float mu = r.x*(1.f/1024.f);
    float var = r.y*(1.f/1024.f) - mu*mu;
    float rs = rsqrtf(var + LEPS);

    float s2[2]; float ss=0.f, qq=0.f;
    #pragma unroll
    for (int j=0;j<2;j++){
        int d = threadIdx.x + j*256;
        float gate  = sigmf((g0[j]-mu)*rs*gamma[d]     + beta[d]);
        float cgate = sigmf((g1[j]-mu)*rs*gamma[512+d] + beta[512+d]);
        float parent = g_chl[b*1536 + slot*512 + d];
        float cell = a[1024 + d];
        s2[j] = gate*parent + cgate*cell;
        ss += s2[j]; qq += s2[j]*s2[j];
    }
    float2 r2 = red2(ss,qq,shs,shq);
    float mu2 = r2.x*(1.f/512.f);
    float var2 = r2.y*(1.f/512.f) - mu2*mu2;
    float rs2 = rsqrtf(var2 + LEPS);

    #pragma unroll
    for (int j=0;j<2;j++){
        int d = threadIdx.x + j*256;
        float hnew = (s2[j]-mu2)*rs2;
        g_chl[b*1536 + (slot+1)*512 + d] = hnew;
        if (slot == 0) g_Xp[b*512 + d] = __float2half(hnew);
    }
}

__device__ __noinline__ void dev_head(const float* __restrict__ Wa,
                                      float* __restrict__ out_lg, int t, float* shs)
{
    int b = blockIdx.x;
    if (b >= B_) return;
    if (threadIdx.x < 15) shs[threadIdx.x] = 0.f;
    __syncthreads();

    float p0 = g_P[b*3], p1 = g_P[b*3+1], p2 = g_P[b*3+2];
    float acc[15];
    #pragma unroll
    for (int a=0;a<15;a++) acc[a]=0.f;
    for (int d = threadIdx.x; d < 512; d += NT){
        float x = p0*g_chl[b*1536 + d] + p1*g_chl[b*1536 + 512 + d] + p2*g_chl[b*1536 + 1024 + d];
        #pragma unroll
        for (int a=0;a<15;a++) acc[a] += x * Wa[d*15 + a];
    }
    #pragma unroll
    for (int a=0;a<15;a++){
        float v = acc[a];
        #pragma unroll
        for (int off=16; off; off>>=1) v += __shfl_down_sync(0xffffffffu, v, off);
        if ((threadIdx.x & 31) == 0) atomicAdd(&shs[a], v);
    }
    __syncthreads();

    if (threadIdx.x == 0){
        const float* pc = g_PChead + (size_t)(t*64 + b)*16;
        float lg[15], mx = -1e30f;
        #pragma unroll
        for (int a=0;a<15;a++){ lg[a] = shs[a] + pc[a]; mx = fmaxf(mx, lg[a]); }
        float sum = 0.f;
        #pragma unroll
        for (int a=0;a<15;a++){ lg[a] = expf(lg[a]-mx); sum += lg[a]; }
        float pe = g_PE[b];
        pe = fminf(fmaxf(pe, 1e-6f), 1.f - 1e-6f);
        float scale = (1.f - pe)/sum;
        float* op = out_lg + (size_t)(b*T_ + t)*16;
        #pragma unroll
        for (int a=0;a<15;a++){
            int j = (a < 5) ? a : a + 1;
            op[j] = logf(lg[a]*scale);
        }
        op[5] = logf(pe);
    }
    __syncthreads();
}

// ---------------- megakernel ----------------
__global__ void __launch_bounds__(NT, 1)
mega_kernel(const float* obs, const int* env_ids, const float* prev_m,
            const float* emb, const float* W_obs, const float* b_obs,
            const float* com_W1, const float* com_b1, const float* com_W2, const float* com_b2,
            const float* com_g, const float* com_beta,
            const float* dec_W1, const float* dec_b1, const float* dec_W2, const float* dec_b2,
            const float* dec_g, const float* dec_beta,
            const float* Wd1, const float* bd1, const float* Wd2, const float* bd2,
            const float* Wa, const float* ba,
            float* out_logits, float* out_ph)
{
    extern __shared__ char dynsm[];
    __shared__ float shs[16], shq[16];
    unsigned smu = (unsigned)__cvta_generic_to_shared(dynsm);
    __half (*S)[72] = (__half(*)[72])dynsm;

    // stage 0: transpose-convert weights, convert obs, gather/prep state
    for (int i = 0; i < 3; i++){
        dev_tcvt(com_W1 + (size_t)i*2048*2048, g_comW1t + (size_t)i*2048*2048, 2048, 2048, S);
        dev_tcvt(com_W2 + (size_t)i*2048*2048, g_comW2t + (size_t)i*2048*2048, 2048, 2048, S);
    }
    for (int i = 0; i < 2; i++){
        dev_tcvt(dec_W1 + (size_t)i*1536*2048, g_decW1t + (size_t)i*2048*1536, 1536, 2048, S);
        dev_tcvt(dec_W2 + (size_t)i*2048*1536, g_decW2t + (size_t)i*1536*2048, 2048, 1536, S);
    }
    dev_tcvt(Wd1,   g_Wd1t,  2048, 512, S);
    dev_tcvt(W_obs, g_Wobst, 128,  512, S);
    dev_cvt4(obs, g_obsh, B_*T_*128/4);
    dev_prep(emb, env_ids, prev_m);
    gridbar();

    // obs encoder
    dev_gemm<0>(g_obsh, 128, g_Wobst, 128, b_obs, 0, g_obsinp, nullptr,
                B_*T_, 512, 128, smu, dynsm);
    gridbar();

    dev_xcomb();
    dev_pchead(Wa, ba);
    dev_pack_step(g_obsinp);
    gridbar();

    // precompute comb-dependent GEMM halves
    for (int i = 0; i < 3; i++)
        dev_gemm<0>(g_Xcomb, 1024, g_comW1t + (size_t)i*2048*2048 + 1024, 2048,
                    com_b1 + i*2048, 0, g_PCcom + (size_t)i*4096*2048, nullptr,
                    4096, 2048, 1024, smu, dynsm);
    for (int i = 0; i < 2; i++)
        dev_gemm<0>(g_Xcomb, 1024, g_decW1t + (size_t)i*2048*1536 + 512, 1536,
                    dec_b1 + i*2048, 0, g_PCdec + (size_t)i*4096*2048, nullptr,
                    4096, 2048, 1024, smu, dynsm);
    dev_gemm<0>(g_Xcomb, 1024, g_Wd1t, 2048, bd1, 0, g_PCdist, nullptr,
                4096, 512, 1024, smu, dynsm);
    gridbar();

    for (int t = 0; t < T_; t++){
        const float* inp = g_obsinp + t*512;

        for (int i = 2; i >= 0; i--){
            dev_gemm<3>(g_Xvh, 1024, g_comW1t + (size_t)i*2048*2048, 2048,
                        g_PCcom + ((size_t)i*4096 + t*64)*2048, 2048,
                        nullptr, g_A1h, 64, 2048, 1024, smu, dynsm);
            gridbar();
            dev_gemm<0>(g_A1h, 2048, g_comW2t + (size_t)i*2048*2048, 2048,
                        com_b2 + i*2048, 0, g_Af, nullptr, 64, 2048, 2048, smu, dynsm);
            gridbar();
            dev_com_post(com_g + i*1536, com_beta + i*1536, inp, i, shs, shq);
            gridbar();
        }

        dev_gemm<4>(g_Xpc, 1024, g_Wd1t + 1024, 2048,
                    g_PCdist + (size_t)t*64*512, 512,
                    g_H1, nullptr, 192, 512, 1024, smu, dynsm);
        gridbar();
        dev_stick(Wd2, bd2, out_ph, t, shs, shq);
        gridbar();

        for (int i = 0; i < 2; i++){
            dev_gemm<3>(g_Xp, 512, g_decW1t + (size_t)i*2048*1536, 1536,
                        g_PCdec + ((size_t)i*4096 + t*64)*2048, 2048,
                        nullptr, g_A1h, 64, 2048, 512, smu, dynsm);
            gridbar();
            dev_gemm<0>(g_A1h, 2048, g_decW2t + (size_t)i*1536*2048, 2048,
                        dec_b2 + i*1536, 0, g_Af, nullptr, 64, 1536, 2048, smu, dynsm);
            gridbar();
            dev_dec_post(dec_g + i*1024, dec_beta + i*1024, i, shs, shq);
            gridbar();
        }

        dev_head(Wa, out_logits, t, shs);
        if (t + 1 < T_) dev_pack_step(g_obsinp + (t+1)*512);
        gridbar();
    }
}

// ---------------- launch ----------------
extern "C" void kernel_launch(void* const* d_in, const int* in_sizes, int n_in,
                              void* d_out, int out_size)
{
    const float* obs      = (const float*)d_in[0];
    const int*   env_ids  = (const int*)  d_in[1];
    const float* prev_m   = (const float*)d_in[2];
    const float* emb      = (const float*)d_in[4];
    const float* W_obs    = (const float*)d_in[5];
    const float* b_obs    = (const float*)d_in[6];
    const float* com_W1   = (const float*)d_in[7];
    const float* com_b1   = (const float*)d_in[8];
    const float* com_W2   = (const float*)d_in[9];
    const float* com_b2   = (const float*)d_in[10];
    const float* com_g    = (const float*)d_in[11];
    const float* com_beta = (const float*)d_in[12];
    const float* dec_W1   = (const float*)d_in[13];
    const float* dec_b1   = (const float*)d_in[14];
    const float* dec_W2   = (const float*)d_in[15];
    const float* dec_b2   = (const float*)d_in[16];
    const float* dec_g    = (const float*)d_in[17];
    const float* dec_beta = (const float*)d_in[18];
    const float* Wd1      = (const float*)d_in[19];
    const float* bd1      = (const float*)d_in[20];
    const float* Wd2      = (const float*)d_in[21];
    const float* bd2      = (const float*)d_in[22];
    const float* Wa       = (const float*)d_in[23];
    const float* ba       = (const float*)d_in[24];

    float* out_logits = (float*)d_out;
    float* out_ph     = (float*)d_out + B_*T_*16;

    static bool attr_set = false;
    if (!attr_set){
        cudaFuncSetAttribute(mega_kernel, cudaFuncAttributeMaxDynamicSharedMemorySize, SMEMB);
        attr_set = true;
    }

    mega_kernel<<<NB, NT, SMEMB>>>(obs, env_ids, prev_m, emb, W_obs, b_obs,
                            com_W1, com_b1, com_W2, com_b2, com_g, com_beta,
                            dec_W1, dec_b1, dec_W2, dec_b2, dec_g, dec_beta,
                            Wd1, bd1, Wd2, bd2, Wa, ba,
                            out_logits, out_ph);
}

// round 13
// speedup vs baseline: 1.2144x; 1.1657x over previous
#include <cuda_runtime.h>
#include <cuda_fp16.h>
#include <math.h>

#define NB 128
#define NH 64
#define NT 256
#define B_   64
#define T_   64
#define D_   512
#define LEPS 1e-3f

// ---------------- static device scratch ----------------
static __device__ __align__(16) __half g_comW1t[3ull*2048*2048];
static __device__ __align__(16) __half g_comW2t[3ull*2048*2048];
static __device__ __align__(16) __half g_decW1t[2ull*2048*1536];
static __device__ __align__(16) __half g_decW2t[2ull*1536*2048];
static __device__ __align__(16) __half g_Wd1t[512*2048];
static __device__ __align__(16) __half g_Wobst[512*128];
static __device__ __align__(16) __half g_obsh[B_*T_*128];
static __device__ __align__(16) __half g_Xcomb[4096*1024];
static __device__ __align__(16) __half g_Xvh[B_*1024];
static __device__ __align__(16) __half g_Xpc[B_*3*1024];
static __device__ __align__(16) __half g_Xp2[2][B_*512];
static __device__ __align__(16) __half g_A1c[B_*2048];
static __device__ __align__(16) __half g_A1d[B_*2048];
static __device__ __align__(16) float  g_obsinp[B_*T_*D_];
static __device__ __align__(16) float  g_PCcom[3ull*4096*2048];
static __device__ __align__(16) float  g_PCdec[2ull*4096*2048];
static __device__ __align__(16) float  g_PCdist[4096*512];
static __device__ __align__(16) float  g_PChead[4096*16];
static __device__ __align__(16) float  g_Afc[B_*2048];
static __device__ __align__(16) float  g_Afd[B_*2048];
static __device__ __align__(16) float  g_H1[B_*3*D_];
static __device__ __align__(16) float  g_H[B_*D_];
static __device__ __align__(16) float  g_M[B_*3*D_];
static __device__ __align__(16) float  g_cand[B_*3*D_];
static __device__ __align__(16) float  g_chl2[2][B_*3*D_];
static __device__ __align__(16) float  g_TE[B_*D_];
static __device__              float  g_P2[2][B_*3];
static __device__              float  g_PE2[2][B_];

// ---------------- barriers: id 0 = full(128), 1 = A-half(64), 2 = B-half(64) ----------------
static __device__ __align__(128) unsigned g_bcnt[3*32];
static __device__ __align__(128) unsigned g_bgen[3*32];

__device__ __forceinline__ unsigned ld_acq(unsigned* p){
    unsigned v;
    asm volatile("ld.acquire.gpu.global.u32 %0, [%1];" : "=r"(v) : "l"(p));
    return v;
}

__device__ __forceinline__ void barid(int id, unsigned n){
    __syncthreads();
    if (threadIdx.x == 0){
        unsigned* c  = &g_bcnt[id*32];
        unsigned* ge = &g_bgen[id*32];
        unsigned g = *ge;
        unsigned old;
        asm volatile("atom.acq_rel.gpu.global.add.u32 %0, [%1], 1;"
                     : "=r"(old) : "l"(c));
        if (old == n - 1){
            *c = 0;
            asm volatile("st.release.gpu.global.u32 [%0], %1;" :: "l"(ge), "r"(g + 1));
        } else {
            while (ld_acq(ge) == g) __nanosleep(20);
        }
    }
    __syncthreads();
}
#define gridbar() barid(0, NB)

// ---------------- helpers (8 warps) ----------------
__device__ __forceinline__ float sigmf(float x){ return 1.f/(1.f+expf(-x)); }

__device__ __forceinline__ float2 red2(float s, float q, float* shs, float* shq){
    int lane = threadIdx.x & 31, w = threadIdx.x >> 5;
    #pragma unroll
    for (int off=16; off; off>>=1){
        s += __shfl_down_sync(0xffffffffu, s, off);
        q += __shfl_down_sync(0xffffffffu, q, off);
    }
    if (lane==0){ shs[w]=s; shq[w]=q; }
    __syncthreads();
    if (w==0){
        s = (lane<8)? shs[lane] : 0.f;
        q = (lane<8)? shq[lane] : 0.f;
        #pragma unroll
        for (int off=4; off; off>>=1){
            s += __shfl_down_sync(0xffffffffu, s, off);
            q += __shfl_down_sync(0xffffffffu, q, off);
        }
        if (lane==0){ shs[0]=s; shq[0]=q; }
    }
    __syncthreads();
    float2 r = make_float2(shs[0], shq[0]);
    __syncthreads();
    return r;
}

__device__ __forceinline__ float red1(float s, float* shs){
    int lane = threadIdx.x & 31, w = threadIdx.x >> 5;
    #pragma unroll
    for (int off=16; off; off>>=1) s += __shfl_down_sync(0xffffffffu, s, off);
    if (lane==0) shs[w]=s;
    __syncthreads();
    if (w==0){
        s = (lane<8)? shs[lane] : 0.f;
        #pragma unroll
        for (int off=4; off; off>>=1) s += __shfl_down_sync(0xffffffffu, s, off);
        if (lane==0) shs[0]=s;
    }
    __syncthreads();
    float r = shs[0];
    __syncthreads();
    return r;
}

// ---------------- cp.async ----------------
__device__ __forceinline__ void cpa16(unsigned saddr, const void* g){
    asm volatile("cp.async.ca.shared.global [%0], [%1], 16;" :: "r"(saddr), "l"(g));
}
#define CP_COMMIT() asm volatile("cp.async.commit_group;")
#define CP_WAIT3()  asm volatile("cp.async.wait_group 3;")

// ---------------- transpose-convert ----------------
__device__ void dev_tcvt(const float* __restrict__ W, __half* __restrict__ Wt,
                         int K, int N, __half (*S)[72])
{
    const int tid = threadIdx.x;
    const int r = tid >> 3, c4 = (tid & 7) * 4;
    const int Ntl = N >> 5;
    const int jobs = (K >> 5) * Ntl;
    for (int job = blockIdx.x; job < jobs; job += NB){
        const int k0 = (job / Ntl) << 5, n0 = (job % Ntl) << 5;
        __syncthreads();
        float4 v = *(const float4*)(W + (size_t)(k0 + r)*N + n0 + c4);
        S[r][c4]   = __float2half(v.x);
        S[r][c4+1] = __float2half(v.y);
        S[r][c4+2] = __float2half(v.z);
        S[r][c4+3] = __float2half(v.w);
        __syncthreads();
        __half2 h0 = __halves2half2(S[c4][r],   S[c4+1][r]);
        __half2 h1 = __halves2half2(S[c4+2][r], S[c4+3][r]);
        *(__half2*)(Wt + (size_t)(n0 + r)*K + k0 + c4)     = h0;
        *(__half2*)(Wt + (size_t)(n0 + r)*K + k0 + c4 + 2) = h1;
    }
    __syncthreads();
}

__device__ void dev_cvt4(const float* __restrict__ s, __half* __restrict__ d, int n4){
    const float4* s4 = (const float4*)s;
    __half2* d2 = (__half2*)d;
    for (int i = blockIdx.x*NT + threadIdx.x; i < n4; i += NB*NT){
        float4 v = s4[i];
        d2[2*i]   = __floats2half2_rn(v.x, v.y);
        d2[2*i+1] = __floats2half2_rn(v.z, v.w);
    }
}

__device__ void dev_prep(const float* __restrict__ emb, const int* __restrict__ ids,
                         const float* __restrict__ prevm){
    int i0 = blockIdx.x*NT + threadIdx.x, stride = NB*NT;
    for (int i = i0; i < B_*D_; i += stride){
        int b = i >> 9;
        g_TE[i] = emb[ids[b]*D_ + (i & 511)];
    }
    for (int i = i0; i < B_*3*D_; i += stride) g_M[i] = prevm[i];
}

__device__ void dev_xcomb(){
    for (int i = blockIdx.x*NT + threadIdx.x; i < 4096*1024; i += NB*NT){
        int row = i >> 10, d = i & 1023;
        int t = row >> 6, b = row & 63;
        float v = (d < 512) ? g_obsinp[(b*T_ + t)*512 + d]
                            : g_TE[b*512 + (d - 512)];
        g_Xcomb[i] = __float2half(v);
    }
}

__device__ void dev_pchead(const float* __restrict__ Wa, const float* __restrict__ ba){
    int gw = (blockIdx.x*NT + threadIdx.x) >> 5;
    int lane = threadIdx.x & 31;
    for (int row = gw; row < 4096; row += (NB*NT)>>5){
        int t = row >> 6, b = row & 63;
        float acc[15];
        #pragma unroll
        for (int a=0;a<15;a++) acc[a]=0.f;
        for (int d = lane; d < 512; d += 32){
            float te = g_TE[b*512 + d];
            float iv = g_obsinp[(b*T_ + t)*512 + d];
            #pragma unroll
            for (int a=0;a<15;a++)
                acc[a] += te*Wa[(512+d)*15 + a] + iv*Wa[(1024+d)*15 + a];
        }
        #pragma unroll
        for (int a=0;a<15;a++){
            float v = acc[a];
            #pragma unroll
            for (int off=16; off; off>>=1) v += __shfl_down_sync(0xffffffffu, v, off);
            if (lane == 0) g_PChead[row*16 + a] = v + ba[a];
        }
    }
}

// ---------------- GEMM (R9 core): 32x32 tiles, BK=64, 5-deep ring ----------------
// base/cnt select the participating block subset. Only blocks in [base,base+cnt) may call.
template<int EPI>
__device__ __noinline__ void dev_gemm(const __half* __restrict__ A, int lda,
                                      const __half* __restrict__ Wt, int ldw,
                                      const float* __restrict__ aux, int ldaux,
                                      float* __restrict__ Cf, __half* __restrict__ Ch,
                                      int M, int N, int K, int base, int cnt,
                                      unsigned sA, unsigned sW,
                                      __half (*As)[72], __half (*Ws)[72])
{
    const int tid  = threadIdx.x;
    const int warp = tid >> 5, lane = tid & 31;
    const int wm = (warp & 1) * 16, wn = (warp >> 1) * 8;
    const int g  = lane >> 2,  tq = lane & 3;
    const int row8 = tid >> 3, seg = (tid & 7) * 8;
    const int Ntiles = N >> 5;
    const int njobs = (M >> 5) * Ntiles;
    const int KT = K >> 6;

    for (int job = blockIdx.x - base; job < njobs; job += cnt){
        const int bM = (job / Ntiles) << 5, bN = (job % Ntiles) << 5;
        const __half* Ab = A  + (size_t)(bM + row8) * lda + seg;
        const __half* Wb = Wt + (size_t)(bN + row8) * ldw + seg;
        const unsigned dA = sA + row8*144 + seg*2;
        const unsigned dW = sW + row8*144 + seg*2;

        __syncthreads();
        #pragma unroll
        for (int p = 0; p < 4; p++){
            if (p < KT){
                cpa16(dA + p*4608, Ab + p*64);
                cpa16(dW + p*4608, Wb + p*64);
            }
            CP_COMMIT();
        }

        float c0=0.f, c1=0.f, c2=0.f, c3=0.f;
        for (int kt = 0; kt < KT; kt++){
            CP_WAIT3();
            __syncthreads();
            if (kt + 4 < KT){
                const int s2 = ((kt+4)%5)*4608;
                cpa16(dA + s2, Ab + (kt+4)*64);
                cpa16(dW + s2, Wb + (kt+4)*64);
            }
            CP_COMMIT();
            const int s = (kt % 5) * 32;
            #pragma unroll
            for (int ks = 0; ks < 4; ks++){
                const int ko = ks * 16;
                unsigned a0 = *(const unsigned*)&As[s + wm + g    ][ko + tq*2];
                unsigned a1 = *(const unsigned*)&As[s + wm + g + 8][ko + tq*2];
                unsigned a2 = *(const unsigned*)&As[s + wm + g    ][ko + 8 + tq*2];
                unsigned a3 = *(const unsigned*)&As[s + wm + g + 8][ko + 8 + tq*2];
                unsigned b0 = *(const unsigned*)&Ws[s + wn + g][ko + tq*2];
                unsigned b1 = *(const unsigned*)&Ws[s + wn + g][ko + 8 + tq*2];
                asm volatile(
                    "mma.sync.aligned.m16n8k16.row.col.f32.f16.f16.f32 "
                    "{%0,%1,%2,%3},{%4,%5,%6,%7},{%8,%9},{%0,%1,%2,%3};\n"
                    : "+f"(c0), "+f"(c1), "+f"(c2), "+f"(c3)
                    : "r"(a0), "r"(a1), "r"(a2), "r"(a3), "r"(b0), "r"(b1));
            }
        }

        const int row = bM + wm + g;
        const int col = bN + wn + tq*2;
        float a00,a01,a10,a11;
        if (EPI == 0){
            a00 = aux[col]; a01 = aux[col+1]; a10 = a00; a11 = a01;
        } else if (EPI == 3){
            const float* p0 = aux + (size_t)row*ldaux;
            const float* p1 = aux + (size_t)(row+8)*ldaux;
            a00 = p0[col]; a01 = p0[col+1]; a10 = p1[col]; a11 = p1[col+1];
        } else {
            const float* p0 = aux + (size_t)(row/3)*ldaux;
            const float* p1 = aux + (size_t)((row+8)/3)*ldaux;
            a00 = p0[col]; a01 = p0[col+1]; a10 = p1[col]; a11 = p1[col+1];
        }
        float v00 = c0 + a00, v01 = c1 + a01, v10 = c2 + a10, v11 = c3 + a11;
        if (EPI == 3){
            v00 = fmaxf(v00,0.f); v01 = fmaxf(v01,0.f);
            v10 = fmaxf(v10,0.f); v11 = fmaxf(v11,0.f);
            *(__half2*)(Ch + (size_t)row*N + col)     = __floats2half2_rn(v00, v01);
            *(__half2*)(Ch + (size_t)(row+8)*N + col) = __floats2half2_rn(v10, v11);
        } else {
            if (EPI == 4){
                v00 = v00>0.f? v00 : 0.3f*v00;  v01 = v01>0.f? v01 : 0.3f*v01;
                v10 = v10>0.f? v10 : 0.3f*v10;  v11 = v11>0.f? v11 : 0.3f*v11;
            }
            *(float2*)(Cf + (size_t)row*N + col)     = make_float2(v00, v01);
            *(float2*)(Cf + (size_t)(row+8)*N + col) = make_float2(v10, v11);
        }
    }
}

// ---------------- elementwise stages ----------------
__device__ void dev_pack_step0(const float* __restrict__ inp){
    int b = blockIdx.x;
    if (b >= B_) return;
    for (int d = threadIdx.x; d < 512; d += NT){
        g_Xvh[b*1024 + d]       = __float2half(inp[b*(T_*D_) + d]);
        g_Xvh[b*1024 + 512 + d] = __float2half(g_M[b*1536 + 1024 + d]);
    }
}

__device__ __noinline__ void dev_com_post(const float* __restrict__ gamma, const float* __restrict__ beta,
                                          const float* __restrict__ inp, int slot, int b,
                                          float* shs, float* shq)
{
    if (b < 0 || b >= B_) return;
    const float* a = g_Afc + b*2048;
    float gv[2], gh[2], gc[2];
    float s=0.f, q=0.f;
    #pragma unroll
    for (int j=0;j<2;j++){
        int d = threadIdx.x + j*256;
        gv[j]=a[d]; gh[j]=a[512+d]; gc[j]=a[1024+d];
        s += gv[j]+gh[j]+gc[j];
        q += gv[j]*gv[j]+gh[j]*gh[j]+gc[j]*gc[j];
    }
    float2 r = red2(s,q,shs,shq);
    float mu = r.x*(1.f/1536.f);
    float var = r.y*(1.f/1536.f) - mu*mu;
    float rs = rsqrtf(var + LEPS);

    float s2[2]; float ss=0.f, qq=0.f;
    #pragma unroll
    for (int j=0;j<2;j++){
        int d = threadIdx.x + j*256;
        float vg = sigmf((gv[j]-mu)*rs*gamma[d]      + beta[d]);
        float hg = sigmf((gh[j]-mu)*rs*gamma[512+d]  + beta[512+d]);
        float cg = sigmf((gc[j]-mu)*rs*gamma[1024+d] + beta[1024+d]);
        float viv = (slot==2) ? inp[b*(T_*D_) + d] : g_H[b*512 + d];
        float hiv = g_M[b*1536 + slot*512 + d];
        float cell = a[1536 + d];
        s2[j] = vg*viv + hg*hiv + cg*cell;
        ss += s2[j]; qq += s2[j]*s2[j];
    }
    float2 r2 = red2(ss,qq,shs,shq);
    float mu2 = r2.x*(1.f/512.f);
    float var2 = r2.y*(1.f/512.f) - mu2*mu2;
    float rs2 = rsqrtf(var2 + LEPS);

    #pragma unroll
    for (int j=0;j<2;j++){
        int d = threadIdx.x + j*256;
        float hnew = (s2[j]-mu2)*rs2;
        g_H[b*512 + d] = hnew;
        g_cand[b*1536 + slot*512 + d] = hnew;
        if (slot > 0){
            g_Xvh[b*1024 + d]       = __float2half(hnew);
            g_Xvh[b*1024 + 512 + d] = __float2half(g_M[b*1536 + (slot-1)*512 + d]);
        } else {
            #pragma unroll
            for (int n=0;n<3;n++){
                int rr = b*3 + n;
                g_Xpc[rr*1024 + d]       = __float2half(g_M[b*1536 + n*512 + d]);
                float cv = (n==0) ? hnew : g_cand[b*1536 + n*512 + d];
                g_Xpc[rr*1024 + 512 + d] = __float2half(cv);
            }
        }
    }
}

// stick: outputs into parity buffers; also packs Xvh for the NEXT com step (inpn may be null)
__device__ __noinline__ void dev_stick(const float* __restrict__ Wd2, const float* __restrict__ bd2,
                                       float* __restrict__ out_ph, int tc, int par,
                                       const float* __restrict__ inpn, int b,
                                       float* shs, float* shq)
{
    if (b < 0 || b >= B_) return;
    float a0=0.f, a1=0.f, a2=0.f;
    #pragma unroll
    for (int j=0;j<2;j++){
        int d = threadIdx.x + j*256;
        float w = Wd2[d];
        a0 += g_H1[(b*3+0)*512 + d]*w;
        a1 += g_H1[(b*3+1)*512 + d]*w;
        a2 += g_H1[(b*3+2)*512 + d]*w;
    }
    float dot0 = red1(a0, shs);
    float dot1 = red1(a1, shs);
    float dot2 = red1(a2, shs);
    if (threadIdx.x == 0){
        float bb = bd2[0];
        float b0 = sigmf(dot0+bb), b1 = sigmf(dot1+bb), b2 = sigmf(dot2+bb);
        float y0 = 1.f-b2, y1 = y0*(1.f-b1), y2 = y1*(1.f-b0);
        float ph0 = y2, ph1 = b0*y1, ph2 = b1*y0, ph3 = b2;
        float* op = out_ph + (size_t)(b*T_ + tc)*4;
        op[0]=ph0; op[1]=ph1; op[2]=ph2; op[3]=ph3;
        float inv = 1.f/(ph1+ph2+ph3);
        float p0 = ph1*inv, p1 = ph2*inv, p2 = ph3*inv;
        g_P2[par][b*3]=p0; g_P2[par][b*3+1]=p1; g_P2[par][b*3+2]=p2;
        g_PE2[par][b] = ph0;
        shq[0] = p0+p1+p2;
        shq[1] = p1+p2;
        shq[2] = p2;
    }
    __syncthreads();
    float rc0 = shq[0], rc1 = shq[1], rc2 = shq[2];
    #pragma unroll
    for (int j=0;j<2;j++){
        int d = threadIdx.x + j*256;
        float m0, m2;
        {
            float mm = g_M[b*1536 + d]*(1.f-rc0) + g_cand[b*1536 + d]*rc0;
            g_M[b*1536 + d] = mm; m0 = mm;
        }
        {
            float mm = g_M[b*1536 + 512 + d]*(1.f-rc1) + g_cand[b*1536 + 512 + d]*rc1;
            g_M[b*1536 + 512 + d] = mm;
        }
        {
            float mm = g_M[b*1536 + 1024 + d]*(1.f-rc2) + g_cand[b*1536 + 1024 + d]*rc2;
            g_M[b*1536 + 1024 + d] = mm; m2 = mm;
        }
        g_chl2[par][b*1536 + d] = m0;
        g_Xp2[par][b*512 + d] = __float2half(m0);
        if (inpn){
            g_Xvh[b*1024 + d]       = __float2half(inpn[b*(T_*D_) + d]);
            g_Xvh[b*1024 + 512 + d] = __float2half(m2);
        }
    }
    __syncthreads();
}

__device__ __noinline__ void dev_dec_post(const float* __restrict__ gamma, const float* __restrict__ beta,
                                          int slot, int par, int b, float* shs, float* shq)
{
    if (b < 0 || b >= B_) return;
    const float* a = g_Afd + b*1536;
    float g0[2], g1[2];
    float s=0.f, q=0.f;
    #pragma unroll
    for (int j=0;j<2;j++){
        int d = threadIdx.x + j*256;
        g0[j]=a[d]; g1[j]=a[512+d];
        s += g0[j]+g1[j];
        q += g0[j]*g0[j]+g1[j]*g1[j];
    }
    float2 r = red2(s,q,shs,shq);
    float mu = r.x*(1.f/1024.f);
    float var = r.y*(1.f/1024.f) - mu*mu;
    float rs = rsqrtf(var + LEPS);

    float s2[2]; float ss=0.f, qq=0.f;
    #pragma unroll
    for (int j=0;j<2;j++){
        int d = threadIdx.x + j*256;
        float gate  = sigmf((g0[j]-mu)*rs*gamma[d]     + beta[d]);
        float cgate = sigmf((g1[j]-mu)*rs*gamma[512+d] + beta[512+d]);
        float parent = g_chl2[par][b*1536 + slot*512 + d];
        float cell = a[1024 + d];
        s2[j] = gate*parent + cgate*cell;
        ss += s2[j]; qq += s2[j]*s2[j];
    }
    float2 r2 = red2(ss,qq,shs,shq);
    float mu2 = r2.x*(1.f/512.f);
    float var2 = r2.y*(1.f/512.f) - mu2*mu2;
    float rs2 = rsqrtf(var2 + LEPS);

    #pragma unroll
    for (int j=0;j<2;j++){
        int d = threadIdx.x + j*256;
        float hnew = (s2[j]-mu2)*rs2;
        g_chl2[par][b*1536 + (slot+1)*512 + d] = hnew;
        if (slot == 0) g_Xp2[par][b*512 + d] = __float2half(hnew);
    }
}

__device__ __noinline__ void dev_head(const float* __restrict__ Wa,
                                      float* __restrict__ out_lg, int t, int par, int b,
                                      float* shs)
{
    if (b < 0 || b >= B_) return;
    if (threadIdx.x < 15) shs[threadIdx.x] = 0.f;
    __syncthreads();

    float p0 = g_P2[par][b*3], p1 = g_P2[par][b*3+1], p2 = g_P2[par][b*3+2];
    float acc[15];
    #pragma unroll
    for (int a=0;a<15;a++) acc[a]=0.f;
    for (int d = threadIdx.x; d < 512; d += NT){
        float x = p0*g_chl2[par][b*1536 + d] + p1*g_chl2[par][b*1536 + 512 + d]
                + p2*g_chl2[par][b*1536 + 1024 + d];
        #pragma unroll
        for (int a=0;a<15;a++) acc[a] += x * Wa[d*15 + a];
    }
    #pragma unroll
    for (int a=0;a<15;a++){
        float v = acc[a];
        #pragma unroll
        for (int off=16; off; off>>=1) v += __shfl_down_sync(0xffffffffu, v, off);
        if ((threadIdx.x & 31) == 0) atomicAdd(&shs[a], v);
    }
    __syncthreads();

    if (threadIdx.x == 0){
        const float* pc = g_PChead + (size_t)(t*64 + b)*16;
        float lg[15], mx = -1e30f;
        #pragma unroll
        for (int a=0;a<15;a++){ lg[a] = shs[a] + pc[a]; mx = fmaxf(mx, lg[a]); }
        float sum = 0.f;
        #pragma unroll
        for (int a=0;a<15;a++){ lg[a] = expf(lg[a]-mx); sum += lg[a]; }
        float pe = g_PE2[par][b];
        pe = fminf(fmaxf(pe, 1e-6f), 1.f - 1e-6f);
        float scale = (1.f - pe)/sum;
        float* op = out_lg + (size_t)(b*T_ + t)*16;
        #pragma unroll
        for (int a=0;a<15;a++){
            int j = (a < 5) ? a : a + 1;
            op[j] = logf(lg[a]*scale);
        }
        op[5] = logf(pe);
    }
    __syncthreads();
}

// ---------------- megakernel ----------------
__global__ void __launch_bounds__(NT, 1)
mega_kernel(const float* obs, const int* env_ids, const float* prev_m,
            const float* emb, const float* W_obs, const float* b_obs,
            const float* com_W1, const float* com_b1, const float* com_W2, const float* com_b2,
            const float* com_g, const float* com_beta,
            const float* dec_W1, const float* dec_b1, const float* dec_W2, const float* dec_b2,
            const float* dec_g, const float* dec_beta,
            const float* Wd1, const float* bd1, const float* Wd2, const float* bd2,
            const float* Wa, const float* ba,
            float* out_logits, float* out_ph)
{
    __shared__ __half As[160][72];
    __shared__ __half Ws[160][72];
    __shared__ float shs[16], shq[16];

    unsigned sA = (unsigned)__cvta_generic_to_shared(&As[0][0]);
    unsigned sW = (unsigned)__cvta_generic_to_shared(&Ws[0][0]);

    // stage 0: convert/transpose weights, prep state
    for (int i = 0; i < 3; i++){
        dev_tcvt(com_W1 + (size_t)i*2048*2048, g_comW1t + (size_t)i*2048*2048, 2048, 2048, As);
        dev_tcvt(com_W2 + (size_t)i*2048*2048, g_comW2t + (size_t)i*2048*2048, 2048, 2048, As);
    }
    for (int i = 0; i < 2; i++){
        dev_tcvt(dec_W1 + (size_t)i*1536*2048, g_decW1t + (size_t)i*2048*1536, 1536, 2048, As);
        dev_tcvt(dec_W2 + (size_t)i*2048*1536, g_decW2t + (size_t)i*1536*2048, 2048, 1536, As);
    }
    dev_tcvt(Wd1,   g_Wd1t,  2048, 512, As);
    dev_tcvt(W_obs, g_Wobst, 128,  512, As);
    dev_cvt4(obs, g_obsh, B_*T_*128/4);
    dev_prep(emb, env_ids, prev_m);
    gridbar();

    dev_gemm<0>(g_obsh, 128, g_Wobst, 128, b_obs, 0, g_obsinp, nullptr,
                B_*T_, 512, 128, 0, NB, sA, sW, As, Ws);
    gridbar();

    dev_xcomb();
    dev_pchead(Wa, ba);
    dev_pack_step0(g_obsinp);
    gridbar();

    for (int i = 0; i < 3; i++)
        dev_gemm<0>(g_Xcomb, 1024, g_comW1t + (size_t)i*2048*2048 + 1024, 2048,
                    com_b1 + i*2048, 0, g_PCcom + (size_t)i*4096*2048, nullptr,
                    4096, 2048, 1024, 0, NB, sA, sW, As, Ws);
    for (int i = 0; i < 2; i++)
        dev_gemm<0>(g_Xcomb, 1024, g_decW1t + (size_t)i*2048*1536 + 512, 1536,
                    dec_b1 + i*2048, 0, g_PCdec + (size_t)i*4096*2048, nullptr,
                    4096, 2048, 1024, 0, NB, sA, sW, As, Ws);
    dev_gemm<0>(g_Xcomb, 1024, g_Wd1t, 2048, bd1, 0, g_PCdist, nullptr,
                4096, 512, 1024, 0, NB, sA, sW, As, Ws);
    gridbar();

    // ---- t=0 com/dist/stick with FULL grid ----
    {
        const float* inp0 = g_obsinp;
        for (int i = 2; i >= 0; i--){
            dev_gemm<3>(g_Xvh, 1024, g_comW1t + (size_t)i*2048*2048, 2048,
                        g_PCcom + (size_t)i*4096*2048, 2048,
                        nullptr, g_A1c, 64, 2048, 1024, 0, NB, sA, sW, As, Ws);
            gridbar();
            dev_gemm<0>(g_A1c, 2048, g_comW2t + (size_t)i*2048*2048, 2048,
                        com_b2 + i*2048, 0, g_Afc, nullptr, 64, 2048, 2048, 0, NB, sA, sW, As, Ws);
            gridbar();
            dev_com_post(com_g + i*1536, com_beta + i*1536, inp0, i, blockIdx.x, shs, shq);
            gridbar();
        }
        dev_gemm<4>(g_Xpc, 1024, g_Wd1t + 1024, 2048, g_PCdist, 512,
                    g_H1, nullptr, 192, 512, 1024, 0, NB, sA, sW, As, Ws);
        gridbar();
        dev_stick(Wd2, bd2, out_ph, 0, 0, g_obsinp + 512, blockIdx.x, shs, shq);
        gridbar();
    }

    // ---- pipelined loop: A = dec(t)+head(t) on blocks 0-63 ; B = com(t+1)..stick(t+1) on 64-127 ----
    for (int t = 0; t < T_; t++){
        const int par = t & 1;
        if (blockIdx.x < NH){
            const int b = blockIdx.x;
            for (int i = 0; i < 2; i++){
                dev_gemm<3>(g_Xp2[par], 512, g_decW1t + (size_t)i*2048*1536, 1536,
                            g_PCdec + ((size_t)i*4096 + t*64)*2048, 2048,
                            nullptr, g_A1d, 64, 2048, 512, 0, NH, sA, sW, As, Ws);
                barid(1, NH);
                dev_gemm<0>(g_A1d, 2048, g_decW2t + (size_t)i*1536*2048, 2048,
                            dec_b2 + i*1536, 0, g_Afd, nullptr, 64, 1536, 2048, 0, NH, sA, sW, As, Ws);
                barid(1, NH);
                dev_dec_post(dec_g + i*1024, dec_beta + i*1024, i, par, b, shs, shq);
                barid(1, NH);
            }
            dev_head(Wa, out_logits, t, par, b, shs);
        } else if (t + 1 < T_) {
            const int tc = t + 1;
            const int b = blockIdx.x - NH;
            const float* inpc = g_obsinp + tc*512;
            for (int i = 2; i >= 0; i--){
                dev_gemm<3>(g_Xvh, 1024, g_comW1t + (size_t)i*2048*2048, 2048,
                            g_PCcom + ((size_t)i*4096 + tc*64)*2048, 2048,
                            nullptr, g_A1c, 64, 2048, 1024, NH, NH, sA, sW, As, Ws);
                barid(2, NH);
                dev_gemm<0>(g_A1c, 2048, g_comW2t + (size_t)i*2048*2048, 2048,
                            com_b2 + i*2048, 0, g_Afc, nullptr, 64, 2048, 2048, NH, NH, sA, sW, As, Ws);
                barid(2, NH);
                dev_com_post(com_g + i*1536, com_beta + i*1536, inpc, i, b, shs, shq);
                barid(2, NH);
            }
            dev_gemm<4>(g_Xpc, 1024, g_Wd1t + 1024, 2048,
                        g_PCdist + (size_t)tc*64*512, 512,
                        g_H1, nullptr, 192, 512, 1024, NH, NH, sA, sW, As, Ws);
            barid(2, NH);
            dev_stick(Wd2, bd2, out_ph, tc, par ^ 1,
                      (tc + 1 < T_) ? (g_obsinp + (tc+1)*512) : nullptr, b, shs, shq);
        }
        gridbar();
    }
}

// ---------------- launch ----------------
extern "C" void kernel_launch(void* const* d_in, const int* in_sizes, int n_in,
                              void* d_out, int out_size)
{
    const float* obs      = (const float*)d_in[0];
    const int*   env_ids  = (const int*)  d_in[1];
    const float* prev_m   = (const float*)d_in[2];
    const float* emb      = (const float*)d_in[4];
    const float* W_obs    = (const float*)d_in[5];
    const float* b_obs    = (const float*)d_in[6];
    const float* com_W1   = (const float*)d_in[7];
    const float* com_b1   = (const float*)d_in[8];
    const float* com_W2   = (const float*)d_in[9];
    const float* com_b2   = (const float*)d_in[10];
    const float* com_g    = (const float*)d_in[11];
    const float* com_beta = (const float*)d_in[12];
    const float* dec_W1   = (const float*)d_in[13];
    const float* dec_b1   = (const float*)d_in[14];
    const float* dec_W2   = (const float*)d_in[15];
    const float* dec_b2   = (const float*)d_in[16];
    const float* dec_g    = (const float*)d_in[17];
    const float* dec_beta = (const float*)d_in[18];
    const float* Wd1      = (const float*)d_in[19];
    const float* bd1      = (const float*)d_in[20];
    const float* Wd2      = (const float*)d_in[21];
    const float* bd2      = (const float*)d_in[22];
    const float* Wa       = (const float*)d_in[23];
    const float* ba       = (const float*)d_in[24];

    float* out_logits = (float*)d_out;
    float* out_ph     = (float*)d_out + B_*T_*16;

    mega_kernel<<<NB, NT>>>(obs, env_ids, prev_m, emb, W_obs, b_obs,
                            com_W1, com_b1, com_W2, com_b2, com_g, com_beta,
                            dec_W1, dec_b1, dec_W2, dec_b2, dec_g, dec_beta,
                            Wd1, bd1, Wd2, bd2, Wa, ba,
                            out_logits, out_ph);
}

// round 14
// speedup vs baseline: 1.4871x; 1.2246x over previous
#include <cuda_runtime.h>
#include <cuda_fp16.h>
#include <math.h>

#define NB 128
#define NH 64
#define NT 256
#define B_   64
#define T_   64
#define D_   512
#define LEPS 1e-3f
#define STAGEB 13824          // (32 A rows + 64 W rows) * 144 B
#define DEPTH  5
#define SMEMB  (DEPTH*STAGEB) // 69120 B

// ---------------- static device scratch ----------------
static __device__ __align__(16) __half g_comW1t[3ull*2048*2048];
static __device__ __align__(16) __half g_comW2t[3ull*2048*2048];
static __device__ __align__(16) __half g_decW1t[2ull*2048*1536];
static __device__ __align__(16) __half g_decW2t[2ull*1536*2048];
static __device__ __align__(16) __half g_Wd1t[512*2048];
static __device__ __align__(16) __half g_Wobst[512*128];
static __device__ __align__(16) __half g_obsh[B_*T_*128];
static __device__ __align__(16) __half g_Xcomb[4096*1024];
static __device__ __align__(16) __half g_Xvh[B_*1024];
static __device__ __align__(16) __half g_Xpc[B_*3*1024];
static __device__ __align__(16) __half g_Xp2[2][B_*512];
static __device__ __align__(16) __half g_A1c[B_*2048];
static __device__ __align__(16) __half g_A1d[B_*2048];
static __device__ __align__(16) float  g_obsinp[B_*T_*D_];
static __device__ __align__(16) float  g_PCcom[3ull*4096*2048];
static __device__ __align__(16) float  g_PCdec[2ull*4096*2048];
static __device__ __align__(16) float  g_PCdist[4096*512];
static __device__ __align__(16) float  g_PChead[4096*16];
static __device__ __align__(16) float  g_Afc[B_*2048];
static __device__ __align__(16) float  g_Afd[B_*2048];
static __device__ __align__(16) float  g_H1[B_*3*D_];
static __device__ __align__(16) float  g_H[B_*D_];
static __device__ __align__(16) float  g_M[B_*3*D_];
static __device__ __align__(16) float  g_cand[B_*3*D_];
static __device__ __align__(16) float  g_chl2[2][B_*3*D_];
static __device__ __align__(16) float  g_TE[B_*D_];
static __device__              float  g_P2[2][B_*3];
static __device__              float  g_PE2[2][B_];

// ---------------- barriers: 0 = full(128), 1 = A-half(64), 2 = B-half(64) ----------------
static __device__ __align__(128) unsigned g_bcnt[3*32];
static __device__ __align__(128) unsigned g_bgen[3*32];

__device__ __forceinline__ unsigned ld_acq(unsigned* p){
    unsigned v;
    asm volatile("ld.acquire.gpu.global.u32 %0, [%1];" : "=r"(v) : "l"(p));
    return v;
}

__device__ __forceinline__ void barid(int id, unsigned n){
    __syncthreads();
    if (threadIdx.x == 0){
        unsigned* c  = &g_bcnt[id*32];
        unsigned* ge = &g_bgen[id*32];
        unsigned g = *ge;
        unsigned old;
        asm volatile("atom.acq_rel.gpu.global.add.u32 %0, [%1], 1;"
                     : "=r"(old) : "l"(c));
        if (old == n - 1){
            *c = 0;
            asm volatile("st.release.gpu.global.u32 [%0], %1;" :: "l"(ge), "r"(g + 1));
        } else {
            while (ld_acq(ge) == g) __nanosleep(20);
        }
    }
    __syncthreads();
}
#define gridbar() barid(0, NB)

// ---------------- helpers ----------------
__device__ __forceinline__ float sigmf(float x){ return 1.f/(1.f+expf(-x)); }

__device__ __forceinline__ float2 red2(float s, float q, float* shs, float* shq){
    int lane = threadIdx.x & 31, w = threadIdx.x >> 5;
    #pragma unroll
    for (int off=16; off; off>>=1){
        s += __shfl_down_sync(0xffffffffu, s, off);
        q += __shfl_down_sync(0xffffffffu, q, off);
    }
    if (lane==0){ shs[w]=s; shq[w]=q; }
    __syncthreads();
    if (w==0){
        s = (lane<8)? shs[lane] : 0.f;
        q = (lane<8)? shq[lane] : 0.f;
        #pragma unroll
        for (int off=4; off; off>>=1){
            s += __shfl_down_sync(0xffffffffu, s, off);
            q += __shfl_down_sync(0xffffffffu, q, off);
        }
        if (lane==0){ shs[0]=s; shq[0]=q; }
    }
    __syncthreads();
    float2 r = make_float2(shs[0], shq[0]);
    __syncthreads();
    return r;
}

__device__ __forceinline__ float red1(float s, float* shs){
    int lane = threadIdx.x & 31, w = threadIdx.x >> 5;
    #pragma unroll
    for (int off=16; off; off>>=1) s += __shfl_down_sync(0xffffffffu, s, off);
    if (lane==0) shs[w]=s;
    __syncthreads();
    if (w==0){
        s = (lane<8)? shs[lane] : 0.f;
        #pragma unroll
        for (int off=4; off; off>>=1) s += __shfl_down_sync(0xffffffffu, s, off);
        if (lane==0) shs[0]=s;
    }
    __syncthreads();
    float r = shs[0];
    __syncthreads();
    return r;
}

// ---------------- cp.async ----------------
__device__ __forceinline__ void cpa16(unsigned saddr, const void* g){
    asm volatile("cp.async.ca.shared.global [%0], [%1], 16;" :: "r"(saddr), "l"(g));
}
#define CP_COMMIT() asm volatile("cp.async.commit_group;")
#define CP_WAIT3()  asm volatile("cp.async.wait_group 3;")

// ---------------- transpose-convert ----------------
__device__ void dev_tcvt(const float* __restrict__ W, __half* __restrict__ Wt,
                         int K, int N, __half (*S)[72])
{
    const int tid = threadIdx.x;
    const int r = tid >> 3, c4 = (tid & 7) * 4;
    const int Ntl = N >> 5;
    const int jobs = (K >> 5) * Ntl;
    for (int job = blockIdx.x; job < jobs; job += NB){
        const int k0 = (job / Ntl) << 5, n0 = (job % Ntl) << 5;
        __syncthreads();
        float4 v = *(const float4*)(W + (size_t)(k0 + r)*N + n0 + c4);
        S[r][c4]   = __float2half(v.x);
        S[r][c4+1] = __float2half(v.y);
        S[r][c4+2] = __float2half(v.z);
        S[r][c4+3] = __float2half(v.w);
        __syncthreads();
        __half2 h0 = __halves2half2(S[c4][r],   S[c4+1][r]);
        __half2 h1 = __halves2half2(S[c4+2][r], S[c4+3][r]);
        *(__half2*)(Wt + (size_t)(n0 + r)*K + k0 + c4)     = h0;
        *(__half2*)(Wt + (size_t)(n0 + r)*K + k0 + c4 + 2) = h1;
    }
    __syncthreads();
}

__device__ void dev_cvt4(const float* __restrict__ s, __half* __restrict__ d, int n4){
    const float4* s4 = (const float4*)s;
    __half2* d2 = (__half2*)d;
    for (int i = blockIdx.x*NT + threadIdx.x; i < n4; i += NB*NT){
        float4 v = s4[i];
        d2[2*i]   = __floats2half2_rn(v.x, v.y);
        d2[2*i+1] = __floats2half2_rn(v.z, v.w);
    }
}

__device__ void dev_prep(const float* __restrict__ emb, const int* __restrict__ ids,
                         const float* __restrict__ prevm){
    int i0 = blockIdx.x*NT + threadIdx.x, stride = NB*NT;
    for (int i = i0; i < B_*D_; i += stride){
        int b = i >> 9;
        g_TE[i] = emb[ids[b]*D_ + (i & 511)];
    }
    for (int i = i0; i < B_*3*D_; i += stride) g_M[i] = prevm[i];
}

__device__ void dev_xcomb(){
    for (int i = blockIdx.x*NT + threadIdx.x; i < 4096*1024; i += NB*NT){
        int row = i >> 10, d = i & 1023;
        int t = row >> 6, b = row & 63;
        float v = (d < 512) ? g_obsinp[(b*T_ + t)*512 + d]
                            : g_TE[b*512 + (d - 512)];
        g_Xcomb[i] = __float2half(v);
    }
}

__device__ void dev_pchead(const float* __restrict__ Wa, const float* __restrict__ ba){
    int gw = (blockIdx.x*NT + threadIdx.x) >> 5;
    int lane = threadIdx.x & 31;
    for (int row = gw; row < 4096; row += (NB*NT)>>5){
        int t = row >> 6, b = row & 63;
        float acc[15];
        #pragma unroll
        for (int a=0;a<15;a++) acc[a]=0.f;
        for (int d = lane; d < 512; d += 32){
            float te = g_TE[b*512 + d];
            float iv = g_obsinp[(b*T_ + t)*512 + d];
            #pragma unroll
            for (int a=0;a<15;a++)
                acc[a] += te*Wa[(512+d)*15 + a] + iv*Wa[(1024+d)*15 + a];
        }
        #pragma unroll
        for (int a=0;a<15;a++){
            float v = acc[a];
            #pragma unroll
            for (int off=16; off; off>>=1) v += __shfl_down_sync(0xffffffffu, v, off);
            if (lane == 0) g_PChead[row*16 + a] = v + ba[a];
        }
    }
}

// ---------------- GEMM: 32x64 tiles, BK=64, 5-deep ring ----------------
// C(MxN) = A(MxK)@Wt(NxK)^T + aux. 8 warps each own a 16x16 fragment.
// EPI 0: +bias[col] -> Cf ; EPI 3: +PC[row][col], relu -> Ch ; EPI 4: +PC[row/3][col], leaky -> Cf
template<int EPI>
__device__ __noinline__ void dev_gemm(const __half* __restrict__ A, int lda,
                                      const __half* __restrict__ Wt, int ldw,
                                      const float* __restrict__ aux, int ldaux,
                                      float* __restrict__ Cf, __half* __restrict__ Ch,
                                      int M, int N, int K, int base, int cnt,
                                      unsigned smu, char* smp)
{
    const int tid  = threadIdx.x;
    const int warp = tid >> 5, lane = tid & 31;
    const int wm = (warp & 1) * 16, wn = (warp >> 1) * 16;
    const int g  = lane >> 2,  tq = lane & 3;
    const int Ntiles = N >> 6;
    const int njobs = (M >> 5) * Ntiles;
    const int KT = K >> 6;
    // loader items: tid + j*256, j=0..2 ; row=item>>3 (0..95), seg=item&7
    const int r0 = tid >> 3,        s0 = tid & 7;
    const int r1 = (tid+256) >> 3,  s1 = tid & 7;
    const int r2 = (tid+512) >> 3,  s2 = tid & 7;

    for (int job = blockIdx.x - base; job < njobs; job += cnt){
        const int bM = (job / Ntiles) << 5, bN = (job % Ntiles) << 6;
        const __half* src0 = A  + (size_t)(bM + r0) * lda + s0*8;          // r0 in 0..31
        const __half* src1 = Wt + (size_t)(bN + r1 - 32) * ldw + s1*8;     // r1 in 32..63
        const __half* src2 = Wt + (size_t)(bN + r2 - 32) * ldw + s2*8;     // r2 in 64..95
        const unsigned d0 = smu + r0*144 + s0*16;
        const unsigned d1 = smu + r1*144 + s1*16;
        const unsigned d2 = smu + r2*144 + s2*16;

        __syncthreads();
        #pragma unroll
        for (int p = 0; p < 4; p++){
            if (p < KT){
                const int ko = p*64;
                const unsigned so = p*STAGEB;
                cpa16(d0 + so, src0 + ko);
                cpa16(d1 + so, src1 + ko);
                cpa16(d2 + so, src2 + ko);
            }
            CP_COMMIT();
        }

        float c[2][4];
        #pragma unroll
        for (int ni=0;ni<2;ni++){ c[ni][0]=0.f; c[ni][1]=0.f; c[ni][2]=0.f; c[ni][3]=0.f; }

        for (int kt = 0; kt < KT; kt++){
            CP_WAIT3();
            __syncthreads();
            if (kt + 4 < KT){
                const unsigned so = ((kt+4)%5)*STAGEB;
                const int ko = (kt+4)*64;
                cpa16(d0 + so, src0 + ko);
                cpa16(d1 + so, src1 + ko);
                cpa16(d2 + so, src2 + ko);
            }
            CP_COMMIT();
            const char* bse = smp + (kt % 5)*STAGEB;
            const __half* As = (const __half*)bse;
            const __half* Ws = (const __half*)(bse + 4608);
            #pragma unroll
            for (int ks = 0; ks < 4; ks++){
                const int ko = ks * 16;
                unsigned a0 = *(const unsigned*)(As + (wm+g)*72   + ko + tq*2);
                unsigned a1 = *(const unsigned*)(As + (wm+g+8)*72 + ko + tq*2);
                unsigned a2 = *(const unsigned*)(As + (wm+g)*72   + ko + 8 + tq*2);
                unsigned a3 = *(const unsigned*)(As + (wm+g+8)*72 + ko + 8 + tq*2);
                #pragma unroll
                for (int ni=0; ni<2; ni++){
                    unsigned b0 = *(const unsigned*)(Ws + (wn+ni*8+g)*72 + ko + tq*2);
                    unsigned b1 = *(const unsigned*)(Ws + (wn+ni*8+g)*72 + ko + 8 + tq*2);
                    asm volatile(
                        "mma.sync.aligned.m16n8k16.row.col.f32.f16.f16.f32 "
                        "{%0,%1,%2,%3},{%4,%5,%6,%7},{%8,%9},{%0,%1,%2,%3};\n"
                        : "+f"(c[ni][0]), "+f"(c[ni][1]), "+f"(c[ni][2]), "+f"(c[ni][3])
                        : "r"(a0), "r"(a1), "r"(a2), "r"(a3), "r"(b0), "r"(b1));
                }
            }
        }

        const int row = bM + wm + g;
        #pragma unroll
        for (int ni=0; ni<2; ni++){
            const int col = bN + wn + ni*8 + tq*2;
            float a00,a01,a10,a11;
            if (EPI == 0){
                a00 = aux[col]; a01 = aux[col+1]; a10 = a00; a11 = a01;
            } else if (EPI == 3){
                const float* p0 = aux + (size_t)row*ldaux;
                const float* p1 = aux + (size_t)(row+8)*ldaux;
                a00 = p0[col]; a01 = p0[col+1]; a10 = p1[col]; a11 = p1[col+1];
            } else {
                const float* p0 = aux + (size_t)(row/3)*ldaux;
                const float* p1 = aux + (size_t)((row+8)/3)*ldaux;
                a00 = p0[col]; a01 = p0[col+1]; a10 = p1[col]; a11 = p1[col+1];
            }
            float v00 = c[ni][0] + a00, v01 = c[ni][1] + a01;
            float v10 = c[ni][2] + a10, v11 = c[ni][3] + a11;
            if (EPI == 3){
                v00 = fmaxf(v00,0.f); v01 = fmaxf(v01,0.f);
                v10 = fmaxf(v10,0.f); v11 = fmaxf(v11,0.f);
                *(__half2*)(Ch + (size_t)row*N + col)     = __floats2half2_rn(v00, v01);
                *(__half2*)(Ch + (size_t)(row+8)*N + col) = __floats2half2_rn(v10, v11);
            } else {
                if (EPI == 4){
                    v00 = v00>0.f? v00 : 0.3f*v00;  v01 = v01>0.f? v01 : 0.3f*v01;
                    v10 = v10>0.f? v10 : 0.3f*v10;  v11 = v11>0.f? v11 : 0.3f*v11;
                }
                *(float2*)(Cf + (size_t)row*N + col)     = make_float2(v00, v01);
                *(float2*)(Cf + (size_t)(row+8)*N + col) = make_float2(v10, v11);
            }
        }
    }
}

// ---------------- elementwise stages ----------------
__device__ void dev_pack_step0(const float* __restrict__ inp){
    int b = blockIdx.x;
    if (b >= B_) return;
    for (int d = threadIdx.x; d < 512; d += NT){
        g_Xvh[b*1024 + d]       = __float2half(inp[b*(T_*D_) + d]);
        g_Xvh[b*1024 + 512 + d] = __float2half(g_M[b*1536 + 1024 + d]);
    }
}

__device__ __noinline__ void dev_com_post(const float* __restrict__ gamma, const float* __restrict__ beta,
                                          const float* __restrict__ inp, int slot, int b,
                                          float* shs, float* shq)
{
    if (b < 0 || b >= B_) return;
    const float* a = g_Afc + b*2048;
    float gv[2], gh[2], gc[2];
    float s=0.f, q=0.f;
    #pragma unroll
    for (int j=0;j<2;j++){
        int d = threadIdx.x + j*256;
        gv[j]=a[d]; gh[j]=a[512+d]; gc[j]=a[1024+d];
        s += gv[j]+gh[j]+gc[j];
        q += gv[j]*gv[j]+gh[j]*gh[j]+gc[j]*gc[j];
    }
    float2 r = red2(s,q,shs,shq);
    float mu = r.x*(1.f/1536.f);
    float var = r.y*(1.f/1536.f) - mu*mu;
    float rs = rsqrtf(var + LEPS);

    float s2[2]; float ss=0.f, qq=0.f;
    #pragma unroll
    for (int j=0;j<2;j++){
        int d = threadIdx.x + j*256;
        float vg = sigmf((gv[j]-mu)*rs*gamma[d]      + beta[d]);
        float hg = sigmf((gh[j]-mu)*rs*gamma[512+d]  + beta[512+d]);
        float cg = sigmf((gc[j]-mu)*rs*gamma[1024+d] + beta[1024+d]);
        float viv = (slot==2) ? inp[b*(T_*D_) + d] : g_H[b*512 + d];
        float hiv = g_M[b*1536 + slot*512 + d];
        float cell = a[1536 + d];
        s2[j] = vg*viv + hg*hiv + cg*cell;
        ss += s2[j]; qq += s2[j]*s2[j];
    }
    float2 r2 = red2(ss,qq,shs,shq);
    float mu2 = r2.x*(1.f/512.f);
    float var2 = r2.y*(1.f/512.f) - mu2*mu2;
    float rs2 = rsqrtf(var2 + LEPS);

    #pragma unroll
    for (int j=0;j<2;j++){
        int d = threadIdx.x + j*256;
        float hnew = (s2[j]-mu2)*rs2;
        g_H[b*512 + d] = hnew;
        g_cand[b*1536 + slot*512 + d] = hnew;
        if (slot > 0){
            g_Xvh[b*1024 + d]       = __float2half(hnew);
            g_Xvh[b*1024 + 512 + d] = __float2half(g_M[b*1536 + (slot-1)*512 + d]);
        } else {
            #pragma unroll
            for (int n=0;n<3;n++){
                int rr = b*3 + n;
                g_Xpc[rr*1024 + d]       = __float2half(g_M[b*1536 + n*512 + d]);
                float cv = (n==0) ? hnew : g_cand[b*1536 + n*512 + d];
                g_Xpc[rr*1024 + 512 + d] = __float2half(cv);
            }
        }
    }
}

__device__ __noinline__ void dev_stick(const float* __restrict__ Wd2, const float* __restrict__ bd2,
                                       float* __restrict__ out_ph, int tc, int par,
                                       const float* __restrict__ inpn, int b,
                                       float* shs, float* shq)
{
    if (b < 0 || b >= B_) return;
    float a0=0.f, a1=0.f, a2=0.f;
    #pragma unroll
    for (int j=0;j<2;j++){
        int d = threadIdx.x + j*256;
        float w = Wd2[d];
        a0 += g_H1[(b*3+0)*512 + d]*w;
        a1 += g_H1[(b*3+1)*512 + d]*w;
        a2 += g_H1[(b*3+2)*512 + d]*w;
    }
    float dot0 = red1(a0, shs);
    float dot1 = red1(a1, shs);
    float dot2 = red1(a2, shs);
    if (threadIdx.x == 0){
        float bb = bd2[0];
        float b0 = sigmf(dot0+bb), b1 = sigmf(dot1+bb), b2 = sigmf(dot2+bb);
        float y0 = 1.f-b2, y1 = y0*(1.f-b1), y2 = y1*(1.f-b0);
        float ph0 = y2, ph1 = b0*y1, ph2 = b1*y0, ph3 = b2;
        float* op = out_ph + (size_t)(b*T_ + tc)*4;
        op[0]=ph0; op[1]=ph1; op[2]=ph2; op[3]=ph3;
        float inv = 1.f/(ph1+ph2+ph3);
        float p0 = ph1*inv, p1 = ph2*inv, p2 = ph3*inv;
        g_P2[par][b*3]=p0; g_P2[par][b*3+1]=p1; g_P2[par][b*3+2]=p2;
        g_PE2[par][b] = ph0;
        shq[0] = p0+p1+p2;
        shq[1] = p1+p2;
        shq[2] = p2;
    }
    __syncthreads();
    float rc0 = shq[0], rc1 = shq[1], rc2 = shq[2];
    #pragma unroll
    for (int j=0;j<2;j++){
        int d = threadIdx.x + j*256;
        float m0, m2;
        {
            float mm = g_M[b*1536 + d]*(1.f-rc0) + g_cand[b*1536 + d]*rc0;
            g_M[b*1536 + d] = mm; m0 = mm;
        }
        {
            float mm = g_M[b*1536 + 512 + d]*(1.f-rc1) + g_cand[b*1536 + 512 + d]*rc1;
            g_M[b*1536 + 512 + d] = mm;
        }
        {
            float mm = g_M[b*1536 + 1024 + d]*(1.f-rc2) + g_cand[b*1536 + 1024 + d]*rc2;
            g_M[b*1536 + 1024 + d] = mm; m2 = mm;
        }
        g_chl2[par][b*1536 + d] = m0;
        g_Xp2[par][b*512 + d] = __float2half(m0);
        if (inpn){
            g_Xvh[b*1024 + d]       = __float2half(inpn[b*(T_*D_) + d]);
            g_Xvh[b*1024 + 512 + d] = __float2half(m2);
        }
    }
    __syncthreads();
}

__device__ __noinline__ void dev_dec_post(const float* __restrict__ gamma, const float* __restrict__ beta,
                                          int slot, int par, int b, float* shs, float* shq)
{
    if (b < 0 || b >= B_) return;
    const float* a = g_Afd + b*1536;
    float g0[2], g1[2];
    float s=0.f, q=0.f;
    #pragma unroll
    for (int j=0;j<2;j++){
        int d = threadIdx.x + j*256;
        g0[j]=a[d]; g1[j]=a[512+d];
        s += g0[j]+g1[j];
        q += g0[j]*g0[j]+g1[j]*g1[j];
    }
    float2 r = red2(s,q,shs,shq);
    float mu = r.x*(1.f/1024.f);
    float var = r.y*(1.f/1024.f) - mu*mu;
    float rs = rsqrtf(var + LEPS);

    float s2[2]; float ss=0.f, qq=0.f;
    #pragma unroll
    for (int j=0;j<2;j++){
        int d = threadIdx.x + j*256;
        float gate  = sigmf((g0[j]-mu)*rs*gamma[d]     + beta[d]);
        float cgate = sigmf((g1[j]-mu)*rs*gamma[512+d] + beta[512+d]);
        float parent = g_chl2[par][b*1536 + slot*512 + d];
        float cell = a[1024 + d];
        s2[j] = gate*parent + cgate*cell;
        ss += s2[j]; qq += s2[j]*s2[j];
    }
    float2 r2 = red2(ss,qq,shs,shq);
    float mu2 = r2.x*(1.f/512.f);
    float var2 = r2.y*(1.f/512.f) - mu2*mu2;
    float rs2 = rsqrtf(var2 + LEPS);

    #pragma unroll
    for (int j=0;j<2;j++){
        int d = threadIdx.x + j*256;
        float hnew = (s2[j]-mu2)*rs2;
        g_chl2[par][b*1536 + (slot+1)*512 + d] = hnew;
        if (slot == 0) g_Xp2[par][b*512 + d] = __float2half(hnew);
    }
}

__device__ __noinline__ void dev_head(const float* __restrict__ Wa,
                                      float* __restrict__ out_lg, int t, int par, int b,
                                      float* shs)
{
    if (b < 0 || b >= B_) return;
    if (threadIdx.x < 15) shs[threadIdx.x] = 0.f;
    __syncthreads();

    float p0 = g_P2[par][b*3], p1 = g_P2[par][b*3+1], p2 = g_P2[par][b*3+2];
    float acc[15];
    #pragma unroll
    for (int a=0;a<15;a++) acc[a]=0.f;
    for (int d = threadIdx.x; d < 512; d += NT){
        float x = p0*g_chl2[par][b*1536 + d] + p1*g_chl2[par][b*1536 + 512 + d]
                + p2*g_chl2[par][b*1536 + 1024 + d];
        #pragma unroll
        for (int a=0;a<15;a++) acc[a] += x * Wa[d*15 + a];
    }
    #pragma unroll
    for (int a=0;a<15;a++){
        float v = acc[a];
        #pragma unroll
        for (int off=16; off; off>>=1) v += __shfl_down_sync(0xffffffffu, v, off);
        if ((threadIdx.x & 31) == 0) atomicAdd(&shs[a], v);
    }
    __syncthreads();

    if (threadIdx.x == 0){
        const float* pc = g_PChead + (size_t)(t*64 + b)*16;
        float lg[15], mx = -1e30f;
        #pragma unroll
        for (int a=0;a<15;a++){ lg[a] = shs[a] + pc[a]; mx = fmaxf(mx, lg[a]); }
        float sum = 0.f;
        #pragma unroll
        for (int a=0;a<15;a++){ lg[a] = expf(lg[a]-mx); sum += lg[a]; }
        float pe = g_PE2[par][b];
        pe = fminf(fmaxf(pe, 1e-6f), 1.f - 1e-6f);
        float scale = (1.f - pe)/sum;
        float* op = out_lg + (size_t)(b*T_ + t)*16;
        #pragma unroll
        for (int a=0;a<15;a++){
            int j = (a < 5) ? a : a + 1;
            op[j] = logf(lg[a]*scale);
        }
        op[5] = logf(pe);
    }
    __syncthreads();
}

// ---------------- megakernel ----------------
__global__ void __launch_bounds__(NT, 1)
mega_kernel(const float* obs, const int* env_ids, const float* prev_m,
            const float* emb, const float* W_obs, const float* b_obs,
            const float* com_W1, const float* com_b1, const float* com_W2, const float* com_b2,
            const float* com_g, const float* com_beta,
            const float* dec_W1, const float* dec_b1, const float* dec_W2, const float* dec_b2,
            const float* dec_g, const float* dec_beta,
            const float* Wd1, const float* bd1, const float* Wd2, const float* bd2,
            const float* Wa, const float* ba,
            float* out_logits, float* out_ph)
{
    extern __shared__ char dynsm[];
    __shared__ float shs[16], shq[16];
    unsigned smu = (unsigned)__cvta_generic_to_shared(dynsm);
    __half (*S)[72] = (__half(*)[72])dynsm;

    for (int i = 0; i < 3; i++){
        dev_tcvt(com_W1 + (size_t)i*2048*2048, g_comW1t + (size_t)i*2048*2048, 2048, 2048, S);
        dev_tcvt(com_W2 + (size_t)i*2048*2048, g_comW2t + (size_t)i*2048*2048, 2048, 2048, S);
    }
    for (int i = 0; i < 2; i++){
        dev_tcvt(dec_W1 + (size_t)i*1536*2048, g_decW1t + (size_t)i*2048*1536, 1536, 2048, S);
        dev_tcvt(dec_W2 + (size_t)i*2048*1536, g_decW2t + (size_t)i*1536*2048, 2048, 1536, S);
    }
    dev_tcvt(Wd1,   g_Wd1t,  2048, 512, S);
    dev_tcvt(W_obs, g_Wobst, 128,  512, S);
    dev_cvt4(obs, g_obsh, B_*T_*128/4);
    dev_prep(emb, env_ids, prev_m);
    gridbar();

    dev_gemm<0>(g_obsh, 128, g_Wobst, 128, b_obs, 0, g_obsinp, nullptr,
                B_*T_, 512, 128, 0, NB, smu, dynsm);
    gridbar();

    dev_xcomb();
    dev_pchead(Wa, ba);
    dev_pack_step0(g_obsinp);
    gridbar();

    for (int i = 0; i < 3; i++)
        dev_gemm<0>(g_Xcomb, 1024, g_comW1t + (size_t)i*2048*2048 + 1024, 2048,
                    com_b1 + i*2048, 0, g_PCcom + (size_t)i*4096*2048, nullptr,
                    4096, 2048, 1024, 0, NB, smu, dynsm);
    for (int i = 0; i < 2; i++)
        dev_gemm<0>(g_Xcomb, 1024, g_decW1t + (size_t)i*2048*1536 + 512, 1536,
                    dec_b1 + i*2048, 0, g_PCdec + (size_t)i*4096*2048, nullptr,
                    4096, 2048, 1024, 0, NB, smu, dynsm);
    dev_gemm<0>(g_Xcomb, 1024, g_Wd1t, 2048, bd1, 0, g_PCdist, nullptr,
                4096, 512, 1024, 0, NB, smu, dynsm);
    gridbar();

    // ---- t=0 com/dist/stick with FULL grid ----
    {
        const float* inp0 = g_obsinp;
        for (int i = 2; i >= 0; i--){
            dev_gemm<3>(g_Xvh, 1024, g_comW1t + (size_t)i*2048*2048, 2048,
                        g_PCcom + (size_t)i*4096*2048, 2048,
                        nullptr, g_A1c, 64, 2048, 1024, 0, NB, smu, dynsm);
            gridbar();
            dev_gemm<0>(g_A1c, 2048, g_comW2t + (size_t)i*2048*2048, 2048,
                        com_b2 + i*2048, 0, g_Afc, nullptr, 64, 2048, 2048, 0, NB, smu, dynsm);
            gridbar();
            dev_com_post(com_g + i*1536, com_beta + i*1536, inp0, i, blockIdx.x, shs, shq);
            gridbar();
        }
        dev_gemm<4>(g_Xpc, 1024, g_Wd1t + 1024, 2048, g_PCdist, 512,
                    g_H1, nullptr, 192, 512, 1024, 0, NB, smu, dynsm);
        gridbar();
        dev_stick(Wd2, bd2, out_ph, 0, 0, g_obsinp + 512, blockIdx.x, shs, shq);
        gridbar();
    }

    // ---- pipelined loop: A = dec(t)+head(t) on 0-63 ; B = com(t+1)..stick(t+1) on 64-127 ----
    for (int t = 0; t < T_; t++){
        const int par = t & 1;
        if (blockIdx.x < NH){
            const int b = blockIdx.x;
            for (int i = 0; i < 2; i++){
                dev_gemm<3>(g_Xp2[par], 512, g_decW1t + (size_t)i*2048*1536, 1536,
                            g_PCdec + ((size_t)i*4096 + t*64)*2048, 2048,
                            nullptr, g_A1d, 64, 2048, 512, 0, NH, smu, dynsm);
                barid(1, NH);
                dev_gemm<0>(g_A1d, 2048, g_decW2t + (size_t)i*1536*2048, 2048,
                            dec_b2 + i*1536, 0, g_Afd, nullptr, 64, 1536, 2048, 0, NH, smu, dynsm);
                barid(1, NH);
                dev_dec_post(dec_g + i*1024, dec_beta + i*1024, i, par, b, shs, shq);
                barid(1, NH);
            }
            dev_head(Wa, out_logits, t, par, b, shs);
        } else if (t + 1 < T_) {
            const int tc = t + 1;
            const int b = blockIdx.x - NH;
            const float* inpc = g_obsinp + tc*512;
            for (int i = 2; i >= 0; i--){
                dev_gemm<3>(g_Xvh, 1024, g_comW1t + (size_t)i*2048*2048, 2048,
                            g_PCcom + ((size_t)i*4096 + tc*64)*2048, 2048,
                            nullptr, g_A1c, 64, 2048, 1024, NH, NH, smu, dynsm);
                barid(2, NH);
                dev_gemm<0>(g_A1c, 2048, g_comW2t + (size_t)i*2048*2048, 2048,
                            com_b2 + i*2048, 0, g_Afc, nullptr, 64, 2048, 2048, NH, NH, smu, dynsm);
                barid(2, NH);
                dev_com_post(com_g + i*1536, com_beta + i*1536, inpc, i, b, shs, shq);
                barid(2, NH);
            }
            dev_gemm<4>(g_Xpc, 1024, g_Wd1t + 1024, 2048,
                        g_PCdist + (size_t)tc*64*512, 512,
                        g_H1, nullptr, 192, 512, 1024, NH, NH, smu, dynsm);
            barid(2, NH);
            dev_stick(Wd2, bd2, out_ph, tc, par ^ 1,
                      (tc + 1 < T_) ? (g_obsinp + (tc+1)*512) : nullptr, b, shs, shq);
        }
        gridbar();
    }
}

// ---------------- launch ----------------
extern "C" void kernel_launch(void* const* d_in, const int* in_sizes, int n_in,
                              void* d_out, int out_size)
{
    const float* obs      = (const float*)d_in[0];
    const int*   env_ids  = (const int*)  d_in[1];
    const float* prev_m   = (const float*)d_in[2];
    const float* emb      = (const float*)d_in[4];
    const float* W_obs    = (const float*)d_in[5];
    const float* b_obs    = (const float*)d_in[6];
    const float* com_W1   = (const float*)d_in[7];
    const float* com_b1   = (const float*)d_in[8];
    const float* com_W2   = (const float*)d_in[9];
    const float* com_b2   = (const float*)d_in[10];
    const float* com_g    = (const float*)d_in[11];
    const float* com_beta = (const float*)d_in[12];
    const float* dec_W1   = (const float*)d_in[13];
    const float* dec_b1   = (const float*)d_in[14];
    const float* dec_W2   = (const float*)d_in[15];
    const float* dec_b2   = (const float*)d_in[16];
    const float* dec_g    = (const float*)d_in[17];
    const float* dec_beta = (const float*)d_in[18];
    const float* Wd1      = (const float*)d_in[19];
    const float* bd1      = (const float*)d_in[20];
    const float* Wd2      = (const float*)d_in[21];
    const float* bd2      = (const float*)d_in[22];
    const float* Wa       = (const float*)d_in[23];
    const float* ba       = (const float*)d_in[24];

    float* out_logits = (float*)d_out;
    float* out_ph     = (float*)d_out + B_*T_*16;

    static bool attr_set = false;
    if (!attr_set){
        cudaFuncSetAttribute(mega_kernel, cudaFuncAttributeMaxDynamicSharedMemorySize, SMEMB);
        attr_set = true;
    }

    mega_kernel<<<NB, NT, SMEMB>>>(obs, env_ids, prev_m, emb, W_obs, b_obs,
                            com_W1, com_b1, com_W2, com_b2, com_g, com_beta,
                            dec_W1, dec_b1, dec_W2, dec_b2, dec_g, dec_beta,
                            Wd1, bd1, Wd2, bd2, Wa, ba,
                            out_logits, out_ph);
}

// round 15
// speedup vs baseline: 1.5559x; 1.0463x over previous
#include <cuda_runtime.h>
#include <cuda_fp16.h>
#include <math.h>

#define NB 128
#define NH 64
#define NT 256
#define B_   64
#define T_   64
#define D_   512
#define LEPS 1e-3f
#define STAGEB 13824          // (32 A rows + 64 W rows) * 144 B
#define DEPTH  6
#define SMEMB  (DEPTH*STAGEB) // 82944 B

// ---------------- static device scratch ----------------
static __device__ __align__(16) __half g_comW1t[3ull*2048*2048];
static __device__ __align__(16) __half g_comW2t[3ull*2048*2048];
static __device__ __align__(16) __half g_decW1t[2ull*2048*1536];
static __device__ __align__(16) __half g_decW2t[2ull*1536*2048];
static __device__ __align__(16) __half g_Wd1t[512*2048];
static __device__ __align__(16) __half g_Wobst[512*128];
static __device__ __align__(16) __half g_obsh[B_*T_*128];
static __device__ __align__(16) __half g_Xcomb[4096*1024];
static __device__ __align__(16) __half g_Xvh[B_*1024];
static __device__ __align__(16) __half g_Xpc[B_*3*1024];
static __device__ __align__(16) __half g_Xp2[2][B_*512];
static __device__ __align__(16) __half g_A1c[B_*2048];
static __device__ __align__(16) __half g_A1d[B_*2048];
static __device__ __align__(16) float  g_obsinp[B_*T_*D_];
static __device__ __align__(16) float  g_PCcom[3ull*4096*2048];
static __device__ __align__(16) float  g_PCdec[2ull*4096*2048];
static __device__ __align__(16) float  g_PCdist[4096*512];
static __device__ __align__(16) float  g_PChead[4096*16];
static __device__ __align__(16) float  g_Afc[B_*2048];
static __device__ __align__(16) float  g_Afd[B_*2048];
static __device__ __align__(16) float  g_H1[B_*3*D_];
static __device__ __align__(16) float  g_H[B_*D_];
static __device__ __align__(16) float  g_M[B_*3*D_];
static __device__ __align__(16) float  g_cand[B_*3*D_];
static __device__ __align__(16) float  g_chl2[2][B_*3*D_];
static __device__ __align__(16) float  g_TE[B_*D_];
static __device__              float  g_P2[2][B_*3];
static __device__              float  g_PE2[2][B_];

// ---------------- barriers: 0 = full(128), 1 = A-half(64), 2 = B-half(64) ----------------
static __device__ __align__(128) unsigned g_bcnt[3*32];
static __device__ __align__(128) unsigned g_bgen[3*32];

__device__ __forceinline__ unsigned ld_acq(unsigned* p){
    unsigned v;
    asm volatile("ld.acquire.gpu.global.u32 %0, [%1];" : "=r"(v) : "l"(p));
    return v;
}

__device__ __forceinline__ void barid(int id, unsigned n){
    __syncthreads();
    if (threadIdx.x == 0){
        unsigned* c  = &g_bcnt[id*32];
        unsigned* ge = &g_bgen[id*32];
        unsigned g = *ge;
        unsigned old;
        asm volatile("atom.acq_rel.gpu.global.add.u32 %0, [%1], 1;"
                     : "=r"(old) : "l"(c));
        if (old == n - 1){
            *c = 0;
            asm volatile("st.release.gpu.global.u32 [%0], %1;" :: "l"(ge), "r"(g + 1));
        } else {
            while (ld_acq(ge) == g) __nanosleep(20);
        }
    }
    __syncthreads();
}
#define gridbar() barid(0, NB)

// ---------------- helpers ----------------
__device__ __forceinline__ float sigmf(float x){ return 1.f/(1.f+expf(-x)); }

__device__ __forceinline__ float2 red2(float s, float q, float* shs, float* shq){
    int lane = threadIdx.x & 31, w = threadIdx.x >> 5;
    #pragma unroll
    for (int off=16; off; off>>=1){
        s += __shfl_down_sync(0xffffffffu, s, off);
        q += __shfl_down_sync(0xffffffffu, q, off);
    }
    if (lane==0){ shs[w]=s; shq[w]=q; }
    __syncthreads();
    if (w==0){
        s = (lane<8)? shs[lane] : 0.f;
        q = (lane<8)? shq[lane] : 0.f;
        #pragma unroll
        for (int off=4; off; off>>=1){
            s += __shfl_down_sync(0xffffffffu, s, off);
            q += __shfl_down_sync(0xffffffffu, q, off);
        }
        if (lane==0){ shs[0]=s; shq[0]=q; }
    }
    __syncthreads();
    float2 r = make_float2(shs[0], shq[0]);
    __syncthreads();
    return r;
}

__device__ __forceinline__ float red1(float s, float* shs){
    int lane = threadIdx.x & 31, w = threadIdx.x >> 5;
    #pragma unroll
    for (int off=16; off; off>>=1) s += __shfl_down_sync(0xffffffffu, s, off);
    if (lane==0) shs[w]=s;
    __syncthreads();
    if (w==0){
        s = (lane<8)? shs[lane] : 0.f;
        #pragma unroll
        for (int off=4; off; off>>=1) s += __shfl_down_sync(0xffffffffu, s, off);
        if (lane==0) shs[0]=s;
    }
    __syncthreads();
    float r = shs[0];
    __syncthreads();
    return r;
}

// ---------------- cp.async ----------------
__device__ __forceinline__ void cpa16(unsigned saddr, const void* g){
    asm volatile("cp.async.ca.shared.global [%0], [%1], 16;" :: "r"(saddr), "l"(g));
}
#define CP_COMMIT() asm volatile("cp.async.commit_group;")
#define CP_WAIT2()  asm volatile("cp.async.wait_group 2;")

// ---------------- transpose-convert ----------------
__device__ void dev_tcvt(const float* __restrict__ W, __half* __restrict__ Wt,
                         int K, int N, __half (*S)[72])
{
    const int tid = threadIdx.x;
    const int r = tid >> 3, c4 = (tid & 7) * 4;
    const int Ntl = N >> 5;
    const int jobs = (K >> 5) * Ntl;
    for (int job = blockIdx.x; job < jobs; job += NB){
        const int k0 = (job / Ntl) << 5, n0 = (job % Ntl) << 5;
        __syncthreads();
        float4 v = *(const float4*)(W + (size_t)(k0 + r)*N + n0 + c4);
        S[r][c4]   = __float2half(v.x);
        S[r][c4+1] = __float2half(v.y);
        S[r][c4+2] = __float2half(v.z);
        S[r][c4+3] = __float2half(v.w);
        __syncthreads();
        __half2 h0 = __halves2half2(S[c4][r],   S[c4+1][r]);
        __half2 h1 = __halves2half2(S[c4+2][r], S[c4+3][r]);
        *(__half2*)(Wt + (size_t)(n0 + r)*K + k0 + c4)     = h0;
        *(__half2*)(Wt + (size_t)(n0 + r)*K + k0 + c4 + 2) = h1;
    }
    __syncthreads();
}

__device__ void dev_cvt4(const float* __restrict__ s, __half* __restrict__ d, int n4){
    const float4* s4 = (const float4*)s;
    __half2* d2 = (__half2*)d;
    for (int i = blockIdx.x*NT + threadIdx.x; i < n4; i += NB*NT){
        float4 v = s4[i];
        d2[2*i]   = __floats2half2_rn(v.x, v.y);
        d2[2*i+1] = __floats2half2_rn(v.z, v.w);
    }
}

__device__ void dev_prep(const float* __restrict__ emb, const int* __restrict__ ids,
                         const float* __restrict__ prevm){
    int i0 = blockIdx.x*NT + threadIdx.x, stride = NB*NT;
    for (int i = i0; i < B_*D_; i += stride){
        int b = i >> 9;
        g_TE[i] = emb[ids[b]*D_ + (i & 511)];
    }
    for (int i = i0; i < B_*3*D_; i += stride) g_M[i] = prevm[i];
}

__device__ void dev_xcomb(){
    for (int i = blockIdx.x*NT + threadIdx.x; i < 4096*1024; i += NB*NT){
        int row = i >> 10, d = i & 1023;
        int t = row >> 6, b = row & 63;
        float v = (d < 512) ? g_obsinp[(b*T_ + t)*512 + d]
                            : g_TE[b*512 + (d - 512)];
        g_Xcomb[i] = __float2half(v);
    }
}

__device__ void dev_pchead(const float* __restrict__ Wa, const float* __restrict__ ba){
    int gw = (blockIdx.x*NT + threadIdx.x) >> 5;
    int lane = threadIdx.x & 31;
    for (int row = gw; row < 4096; row += (NB*NT)>>5){
        int t = row >> 6, b = row & 63;
        float acc[15];
        #pragma unroll
        for (int a=0;a<15;a++) acc[a]=0.f;
        for (int d = lane; d < 512; d += 32){
            float te = g_TE[b*512 + d];
            float iv = g_obsinp[(b*T_ + t)*512 + d];
            #pragma unroll
            for (int a=0;a<15;a++)
                acc[a] += te*Wa[(512+d)*15 + a] + iv*Wa[(1024+d)*15 + a];
        }
        #pragma unroll
        for (int a=0;a<15;a++){
            float v = acc[a];
            #pragma unroll
            for (int off=16; off; off>>=1) v += __shfl_down_sync(0xffffffffu, v, off);
            if (lane == 0) g_PChead[row*16 + a] = v + ba[a];
        }
    }
}

// ---------------- GEMM: 32x64 tiles, BK=64 chunks, 6-deep ring, 2 chunks per sync ----------------
// EPI 0: +bias[col] -> Cf ; EPI 3: +PC[row][col], relu -> Ch ; EPI 4: +PC[row/3][col], leaky -> Cf
template<int EPI>
__device__ __noinline__ void dev_gemm(const __half* __restrict__ A, int lda,
                                      const __half* __restrict__ Wt, int ldw,
                                      const float* __restrict__ aux, int ldaux,
                                      float* __restrict__ Cf, __half* __restrict__ Ch,
                                      int M, int N, int K, int base, int cnt,
                                      unsigned smu, char* smp)
{
    const int tid  = threadIdx.x;
    const int warp = tid >> 5, lane = tid & 31;
    const int wm = (warp & 1) * 16, wn = (warp >> 1) * 16;
    const int g  = lane >> 2,  tq = lane & 3;
    const int Ntiles = N >> 6;
    const int njobs = (M >> 5) * Ntiles;
    const int KT = K >> 6;   // always even (K multiple of 128)
    const int r0 = tid >> 3,        s0 = tid & 7;
    const int r1 = (tid+256) >> 3,  s1 = tid & 7;
    const int r2 = (tid+512) >> 3,  s2 = tid & 7;

    for (int job = blockIdx.x - base; job < njobs; job += cnt){
        const int bM = (job / Ntiles) << 5, bN = (job % Ntiles) << 6;
        const __half* src0 = A  + (size_t)(bM + r0) * lda + s0*8;
        const __half* src1 = Wt + (size_t)(bN + r1 - 32) * ldw + s1*8;
        const __half* src2 = Wt + (size_t)(bN + r2 - 32) * ldw + s2*8;
        const unsigned d0 = smu + r0*144 + s0*16;
        const unsigned d1 = smu + r1*144 + s1*16;
        const unsigned d2 = smu + r2*144 + s2*16;

        __syncthreads();
        #pragma unroll
        for (int p = 0; p < 4; p++){
            if (p < KT){
                const int ko = p*64;
                const unsigned so = p*STAGEB;
                cpa16(d0 + so, src0 + ko);
                cpa16(d1 + so, src1 + ko);
                cpa16(d2 + so, src2 + ko);
            }
            CP_COMMIT();
        }

        float c[2][4];
        #pragma unroll
        for (int ni=0;ni<2;ni++){ c[ni][0]=0.f; c[ni][1]=0.f; c[ni][2]=0.f; c[ni][3]=0.f; }

        for (int kp = 0; kp < KT; kp += 2){
            CP_WAIT2();          // chunks kp, kp+1 ready
            __syncthreads();
            #pragma unroll
            for (int h = 0; h < 2; h++){
                const int kc = kp + 4 + h;
                if (kc < KT){
                    const unsigned so = (kc % DEPTH)*STAGEB;
                    const int ko = kc*64;
                    cpa16(d0 + so, src0 + ko);
                    cpa16(d1 + so, src1 + ko);
                    cpa16(d2 + so, src2 + ko);
                }
                CP_COMMIT();
            }
            #pragma unroll
            for (int h = 0; h < 2; h++){
                const char* bse = smp + ((kp + h) % DEPTH)*STAGEB;
                const __half* As = (const __half*)bse;
                const __half* Ws = (const __half*)(bse + 4608);
                #pragma unroll
                for (int ks = 0; ks < 4; ks++){
                    const int ko = ks * 16;
                    unsigned a0 = *(const unsigned*)(As + (wm+g)*72   + ko + tq*2);
                    unsigned a1 = *(const unsigned*)(As + (wm+g+8)*72 + ko + tq*2);
                    unsigned a2 = *(const unsigned*)(As + (wm+g)*72   + ko + 8 + tq*2);
                    unsigned a3 = *(const unsigned*)(As + (wm+g+8)*72 + ko + 8 + tq*2);
                    #pragma unroll
                    for (int ni=0; ni<2; ni++){
                        unsigned b0 = *(const unsigned*)(Ws + (wn+ni*8+g)*72 + ko + tq*2);
                        unsigned b1 = *(const unsigned*)(Ws + (wn+ni*8+g)*72 + ko + 8 + tq*2);
                        asm volatile(
                            "mma.sync.aligned.m16n8k16.row.col.f32.f16.f16.f32 "
                            "{%0,%1,%2,%3},{%4,%5,%6,%7},{%8,%9},{%0,%1,%2,%3};\n"
                            : "+f"(c[ni][0]), "+f"(c[ni][1]), "+f"(c[ni][2]), "+f"(c[ni][3])
                            : "r"(a0), "r"(a1), "r"(a2), "r"(a3), "r"(b0), "r"(b1));
                    }
                }
            }
        }

        const int row = bM + wm + g;
        #pragma unroll
        for (int ni=0; ni<2; ni++){
            const int col = bN + wn + ni*8 + tq*2;
            float a00,a01,a10,a11;
            if (EPI == 0){
                a00 = aux[col]; a01 = aux[col+1]; a10 = a00; a11 = a01;
            } else if (EPI == 3){
                const float* p0 = aux + (size_t)row*ldaux;
                const float* p1 = aux + (size_t)(row+8)*ldaux;
                a00 = p0[col]; a01 = p0[col+1]; a10 = p1[col]; a11 = p1[col+1];
            } else {
                const float* p0 = aux + (size_t)(row/3)*ldaux;
                const float* p1 = aux + (size_t)((row+8)/3)*ldaux;
                a00 = p0[col]; a01 = p0[col+1]; a10 = p1[col]; a11 = p1[col+1];
            }
            float v00 = c[ni][0] + a00, v01 = c[ni][1] + a01;
            float v10 = c[ni][2] + a10, v11 = c[ni][3] + a11;
            if (EPI == 3){
                v00 = fmaxf(v00,0.f); v01 = fmaxf(v01,0.f);
                v10 = fmaxf(v10,0.f); v11 = fmaxf(v11,0.f);
                *(__half2*)(Ch + (size_t)row*N + col)     = __floats2half2_rn(v00, v01);
                *(__half2*)(Ch + (size_t)(row+8)*N + col) = __floats2half2_rn(v10, v11);
            } else {
                if (EPI == 4){
                    v00 = v00>0.f? v00 : 0.3f*v00;  v01 = v01>0.f? v01 : 0.3f*v01;
                    v10 = v10>0.f? v10 : 0.3f*v10;  v11 = v11>0.f? v11 : 0.3f*v11;
                }
                *(float2*)(Cf + (size_t)row*N + col)     = make_float2(v00, v01);
                *(float2*)(Cf + (size_t)(row+8)*N + col) = make_float2(v10, v11);
            }
        }
    }
}

// ---------------- elementwise stages ----------------
__device__ void dev_pack_step0(const float* __restrict__ inp){
    int b = blockIdx.x;
    if (b >= B_) return;
    for (int d = threadIdx.x; d < 512; d += NT){
        g_Xvh[b*1024 + d]       = __float2half(inp[b*(T_*D_) + d]);
        g_Xvh[b*1024 + 512 + d] = __float2half(g_M[b*1536 + 1024 + d]);
    }
}

__device__ __noinline__ void dev_com_post(const float* __restrict__ gamma, const float* __restrict__ beta,
                                          const float* __restrict__ inp, int slot, int b,
                                          float* shs, float* shq)
{
    if (b < 0 || b >= B_) return;
    const float* a = g_Afc + b*2048;
    float gv[2], gh[2], gc[2];
    float s=0.f, q=0.f;
    #pragma unroll
    for (int j=0;j<2;j++){
        int d = threadIdx.x + j*256;
        gv[j]=a[d]; gh[j]=a[512+d]; gc[j]=a[1024+d];
        s += gv[j]+gh[j]+gc[j];
        q += gv[j]*gv[j]+gh[j]*gh[j]+gc[j]*gc[j];
    }
    float2 r = red2(s,q,shs,shq);
    float mu = r.x*(1.f/1536.f);
    float var = r.y*(1.f/1536.f) - mu*mu;
    float rs = rsqrtf(var + LEPS);

    float s2[2]; float ss=0.f, qq=0.f;
    #pragma unroll
    for (int j=0;j<2;j++){
        int d = threadIdx.x + j*256;
        float vg = sigmf((gv[j]-mu)*rs*gamma[d]      + beta[d]);
        float hg = sigmf((gh[j]-mu)*rs*gamma[512+d]  + beta[512+d]);
        float cg = sigmf((gc[j]-mu)*rs*gamma[1024+d] + beta[1024+d]);
        float viv = (slot==2) ? inp[b*(T_*D_) + d] : g_H[b*512 + d];
        float hiv = g_M[b*1536 + slot*512 + d];
        float cell = a[1536 + d];
        s2[j] = vg*viv + hg*hiv + cg*cell;
        ss += s2[j]; qq += s2[j]*s2[j];
    }
    float2 r2 = red2(ss,qq,shs,shq);
    float mu2 = r2.x*(1.f/512.f);
    float var2 = r2.y*(1.f/512.f) - mu2*mu2;
    float rs2 = rsqrtf(var2 + LEPS);

    #pragma unroll
    for (int j=0;j<2;j++){
        int d = threadIdx.x + j*256;
        float hnew = (s2[j]-mu2)*rs2;
        g_H[b*512 + d] = hnew;
        g_cand[b*1536 + slot*512 + d] = hnew;
        if (slot > 0){
            g_Xvh[b*1024 + d]       = __float2half(hnew);
            g_Xvh[b*1024 + 512 + d] = __float2half(g_M[b*1536 + (slot-1)*512 + d]);
        } else {
            #pragma unroll
            for (int n=0;n<3;n++){
                int rr = b*3 + n;
                g_Xpc[rr*1024 + d]       = __float2half(g_M[b*1536 + n*512 + d]);
                float cv = (n==0) ? hnew : g_cand[b*1536 + n*512 + d];
                g_Xpc[rr*1024 + 512 + d] = __float2half(cv);
            }
        }
    }
}

__device__ __noinline__ void dev_stick(const float* __restrict__ Wd2, const float* __restrict__ bd2,
                                       float* __restrict__ out_ph, int tc, int par,
                                       const float* __restrict__ inpn, int b,
                                       float* shs, float* shq)
{
    if (b < 0 || b >= B_) return;
    float a0=0.f, a1=0.f, a2=0.f;
    #pragma unroll
    for (int j=0;j<2;j++){
        int d = threadIdx.x + j*256;
        float w = Wd2[d];
        a0 += g_H1[(b*3+0)*512 + d]*w;
        a1 += g_H1[(b*3+1)*512 + d]*w;
        a2 += g_H1[(b*3+2)*512 + d]*w;
    }
    float dot0 = red1(a0, shs);
    float dot1 = red1(a1, shs);
    float dot2 = red1(a2, shs);
    if (threadIdx.x == 0){
        float bb = bd2[0];
        float b0 = sigmf(dot0+bb), b1 = sigmf(dot1+bb), b2 = sigmf(dot2+bb);
        float y0 = 1.f-b2, y1 = y0*(1.f-b1), y2 = y1*(1.f-b0);
        float ph0 = y2, ph1 = b0*y1, ph2 = b1*y0, ph3 = b2;
        float* op = out_ph + (size_t)(b*T_ + tc)*4;
        op[0]=ph0; op[1]=ph1; op[2]=ph2; op[3]=ph3;
        float inv = 1.f/(ph1+ph2+ph3);
        float p0 = ph1*inv, p1 = ph2*inv, p2 = ph3*inv;
        g_P2[par][b*3]=p0; g_P2[par][b*3+1]=p1; g_P2[par][b*3+2]=p2;
        g_PE2[par][b] = ph0;
        shq[0] = p0+p1+p2;
        shq[1] = p1+p2;
        shq[2] = p2;
    }
    __syncthreads();
    float rc0 = shq[0], rc1 = shq[1], rc2 = shq[2];
    #pragma unroll
    for (int j=0;j<2;j++){
        int d = threadIdx.x + j*256;
        float m0, m2;
        {
            float mm = g_M[b*1536 + d]*(1.f-rc0) + g_cand[b*1536 + d]*rc0;
            g_M[b*1536 + d] = mm; m0 = mm;
        }
        {
            float mm = g_M[b*1536 + 512 + d]*(1.f-rc1) + g_cand[b*1536 + 512 + d]*rc1;
            g_M[b*1536 + 512 + d] = mm;
        }
        {
            float mm = g_M[b*1536 + 1024 + d]*(1.f-rc2) + g_cand[b*1536 + 1024 + d]*rc2;
            g_M[b*1536 + 1024 + d] = mm; m2 = mm;
        }
        g_chl2[par][b*1536 + d] = m0;
        g_Xp2[par][b*512 + d] = __float2half(m0);
        if (inpn){
            g_Xvh[b*1024 + d]       = __float2half(inpn[b*(T_*D_) + d]);
            g_Xvh[b*1024 + 512 + d] = __float2half(m2);
        }
    }
    __syncthreads();
}

__device__ __noinline__ void dev_dec_post(const float* __restrict__ gamma, const float* __restrict__ beta,
                                          int slot, int par, int b, float* shs, float* shq)
{
    if (b < 0 || b >= B_) return;
    const float* a = g_Afd + b*1536;
    float g0[2], g1[2];
    float s=0.f, q=0.f;
    #pragma unroll
    for (int j=0;j<2;j++){
        int d = threadIdx.x + j*256;
        g0[j]=a[d]; g1[j]=a[512+d];
        s += g0[j]+g1[j];
        q += g0[j]*g0[j]+g1[j]*g1[j];
    }
    float2 r = red2(s,q,shs,shq);
    float mu = r.x*(1.f/1024.f);
    float var = r.y*(1.f/1024.f) - mu*mu;
    float rs = rsqrtf(var + LEPS);

    float s2[2]; float ss=0.f, qq=0.f;
    #pragma unroll
    for (int j=0;j<2;j++){
        int d = threadIdx.x + j*256;
        float gate  = sigmf((g0[j]-mu)*rs*gamma[d]     + beta[d]);
        float cgate = sigmf((g1[j]-mu)*rs*gamma[512+d] + beta[512+d]);
        float parent = g_chl2[par][b*1536 + slot*512 + d];
        float cell = a[1024 + d];
        s2[j] = gate*parent + cgate*cell;
        ss += s2[j]; qq += s2[j]*s2[j];
    }
    float2 r2 = red2(ss,qq,shs,shq);
    float mu2 = r2.x*(1.f/512.f);
    float var2 = r2.y*(1.f/512.f) - mu2*mu2;
    float rs2 = rsqrtf(var2 + LEPS);

    #pragma unroll
    for (int j=0;j<2;j++){
        int d = threadIdx.x + j*256;
        float hnew = (s2[j]-mu2)*rs2;
        g_chl2[par][b*1536 + (slot+1)*512 + d] = hnew;
        if (slot == 0) g_Xp2[par][b*512 + d] = __float2half(hnew);
    }
}

__device__ __noinline__ void dev_head(const float* __restrict__ Wa,
                                      float* __restrict__ out_lg, int t, int par, int b,
                                      float* shs)
{
    if (b < 0 || b >= B_) return;
    if (threadIdx.x < 15) shs[threadIdx.x] = 0.f;
    __syncthreads();

    float p0 = g_P2[par][b*3], p1 = g_P2[par][b*3+1], p2 = g_P2[par][b*3+2];
    float acc[15];
    #pragma unroll
    for (int a=0;a<15;a++) acc[a]=0.f;
    for (int d = threadIdx.x; d < 512; d += NT){
        float x = p0*g_chl2[par][b*1536 + d] + p1*g_chl2[par][b*1536 + 512 + d]
                + p2*g_chl2[par][b*1536 + 1024 + d];
        #pragma unroll
        for (int a=0;a<15;a++) acc[a] += x * Wa[d*15 + a];
    }
    #pragma unroll
    for (int a=0;a<15;a++){
        float v = acc[a];
        #pragma unroll
        for (int off=16; off; off>>=1) v += __shfl_down_sync(0xffffffffu, v, off);
        if ((threadIdx.x & 31) == 0) atomicAdd(&shs[a], v);
    }
    __syncthreads();

    if (threadIdx.x == 0){
        const float* pc = g_PChead + (size_t)(t*64 + b)*16;
        float lg[15], mx = -1e30f;
        #pragma unroll
        for (int a=0;a<15;a++){ lg[a] = shs[a] + pc[a]; mx = fmaxf(mx, lg[a]); }
        float sum = 0.f;
        #pragma unroll
        for (int a=0;a<15;a++){ lg[a] = expf(lg[a]-mx); sum += lg[a]; }
        float pe = g_PE2[par][b];
        pe = fminf(fmaxf(pe, 1e-6f), 1.f - 1e-6f);
        float scale = (1.f - pe)/sum;
        float* op = out_lg + (size_t)(b*T_ + t)*16;
        #pragma unroll
        for (int a=0;a<15;a++){
            int j = (a < 5) ? a : a + 1;
            op[j] = logf(lg[a]*scale);
        }
        op[5] = logf(pe);
    }
    __syncthreads();
}

// ---------------- megakernel ----------------
__global__ void __launch_bounds__(NT, 1)
mega_kernel(const float* obs, const int* env_ids, const float* prev_m,
            const float* emb, const float* W_obs, const float* b_obs,
            const float* com_W1, const float* com_b1, const float* com_W2, const float* com_b2,
            const float* com_g, const float* com_beta,
            const float* dec_W1, const float* dec_b1, const float* dec_W2, const float* dec_b2,
            const float* dec_g, const float* dec_beta,
            const float* Wd1, const float* bd1, const float* Wd2, const float* bd2,
            const float* Wa, const float* ba,
            float* out_logits, float* out_ph)
{
    extern __shared__ char dynsm[];
    __shared__ float shs[16], shq[16];
    unsigned smu = (unsigned)__cvta_generic_to_shared(dynsm);
    __half (*S)[72] = (__half(*)[72])dynsm;

    for (int i = 0; i < 3; i++){
        dev_tcvt(com_W1 + (size_t)i*2048*2048, g_comW1t + (size_t)i*2048*2048, 2048, 2048, S);
        dev_tcvt(com_W2 + (size_t)i*2048*2048, g_comW2t + (size_t)i*2048*2048, 2048, 2048, S);
    }
    for (int i = 0; i < 2; i++){
        dev_tcvt(dec_W1 + (size_t)i*1536*2048, g_decW1t + (size_t)i*2048*1536, 1536, 2048, S);
        dev_tcvt(dec_W2 + (size_t)i*2048*1536, g_decW2t + (size_t)i*1536*2048, 2048, 1536, S);
    }
    dev_tcvt(Wd1,   g_Wd1t,  2048, 512, S);
    dev_tcvt(W_obs, g_Wobst, 128,  512, S);
    dev_cvt4(obs, g_obsh, B_*T_*128/4);
    dev_prep(emb, env_ids, prev_m);
    gridbar();

    dev_gemm<0>(g_obsh, 128, g_Wobst, 128, b_obs, 0, g_obsinp, nullptr,
                B_*T_, 512, 128, 0, NB, smu, dynsm);
    gridbar();

    dev_xcomb();
    dev_pchead(Wa, ba);
    dev_pack_step0(g_obsinp);
    gridbar();

    for (int i = 0; i < 3; i++)
        dev_gemm<0>(g_Xcomb, 1024, g_comW1t + (size_t)i*2048*2048 + 1024, 2048,
                    com_b1 + i*2048, 0, g_PCcom + (size_t)i*4096*2048, nullptr,
                    4096, 2048, 1024, 0, NB, smu, dynsm);
    for (int i = 0; i < 2; i++)
        dev_gemm<0>(g_Xcomb, 1024, g_decW1t + (size_t)i*2048*1536 + 512, 1536,
                    dec_b1 + i*2048, 0, g_PCdec + (size_t)i*4096*2048, nullptr,
                    4096, 2048, 1024, 0, NB, smu, dynsm);
    dev_gemm<0>(g_Xcomb, 1024, g_Wd1t, 2048, bd1, 0, g_PCdist, nullptr,
                4096, 512, 1024, 0, NB, smu, dynsm);
    gridbar();

    // ---- t=0 com/dist/stick with FULL grid ----
    {
        const float* inp0 = g_obsinp;
        for (int i = 2; i >= 0; i--){
            dev_gemm<3>(g_Xvh, 1024, g_comW1t + (size_t)i*2048*2048, 2048,
                        g_PCcom + (size_t)i*4096*2048, 2048,
                        nullptr, g_A1c, 64, 2048, 1024, 0, NB, smu, dynsm);
            gridbar();
            dev_gemm<0>(g_A1c, 2048, g_comW2t + (size_t)i*2048*2048, 2048,
                        com_b2 + i*2048, 0, g_Afc, nullptr, 64, 2048, 2048, 0, NB, smu, dynsm);
            gridbar();
            dev_com_post(com_g + i*1536, com_beta + i*1536, inp0, i, blockIdx.x, shs, shq);
            gridbar();
        }
        dev_gemm<4>(g_Xpc, 1024, g_Wd1t + 1024, 2048, g_PCdist, 512,
                    g_H1, nullptr, 192, 512, 1024, 0, NB, smu, dynsm);
        gridbar();
        dev_stick(Wd2, bd2, out_ph, 0, 0, g_obsinp + 512, blockIdx.x, shs, shq);
        gridbar();
    }

    // ---- pipelined loop ----
    for (int t = 0; t < T_; t++){
        const int par = t & 1;
        if (blockIdx.x < NH){
            const int b = blockIdx.x;
            for (int i = 0; i < 2; i++){
                dev_gemm<3>(g_Xp2[par], 512, g_decW1t + (size_t)i*2048*1536, 1536,
                            g_PCdec + ((size_t)i*4096 + t*64)*2048, 2048,
                            nullptr, g_A1d, 64, 2048, 512, 0, NH, smu, dynsm);
                barid(1, NH);
                dev_gemm<0>(g_A1d, 2048, g_decW2t + (size_t)i*1536*2048, 2048,
                            dec_b2 + i*1536, 0, g_Afd, nullptr, 64, 1536, 2048, 0, NH, smu, dynsm);
                barid(1, NH);
                dev_dec_post(dec_g + i*1024, dec_beta + i*1024, i, par, b, shs, shq);
                barid(1, NH);
            }
            dev_head(Wa, out_logits, t, par, b, shs);
        } else if (t + 1 < T_) {
            const int tc = t + 1;
            const int b = blockIdx.x - NH;
            const float* inpc = g_obsinp + tc*512;
            for (int i = 2; i >= 0; i--){
                dev_gemm<3>(g_Xvh, 1024, g_comW1t + (size_t)i*2048*2048, 2048,
                            g_PCcom + ((size_t)i*4096 + tc*64)*2048, 2048,
                            nullptr, g_A1c, 64, 2048, 1024, NH, NH, smu, dynsm);
                barid(2, NH);
                dev_gemm<0>(g_A1c, 2048, g_comW2t + (size_t)i*2048*2048, 2048,
                            com_b2 + i*2048, 0, g_Afc, nullptr, 64, 2048, 2048, NH, NH, smu, dynsm);
                barid(2, NH);
                dev_com_post(com_g + i*1536, com_beta + i*1536, inpc, i, b, shs, shq);
                barid(2, NH);
            }
            dev_gemm<4>(g_Xpc, 1024, g_Wd1t + 1024, 2048,
                        g_PCdist + (size_t)tc*64*512, 512,
                        g_H1, nullptr, 192, 512, 1024, NH, NH, smu, dynsm);
            barid(2, NH);
            dev_stick(Wd2, bd2, out_ph, tc, par ^ 1,
                      (tc + 1 < T_) ? (g_obsinp + (tc+1)*512) : nullptr, b, shs, shq);
        }
        gridbar();
    }
}

// ---------------- launch ----------------
extern "C" void kernel_launch(void* const* d_in, const int* in_sizes, int n_in,
                              void* d_out, int out_size)
{
    const float* obs      = (const float*)d_in[0];
    const int*   env_ids  = (const int*)  d_in[1];
    const float* prev_m   = (const float*)d_in[2];
    const float* emb      = (const float*)d_in[4];
    const float* W_obs    = (const float*)d_in[5];
    const float* b_obs    = (const float*)d_in[6];
    const float* com_W1   = (const float*)d_in[7];
    const float* com_b1   = (const float*)d_in[8];
    const float* com_W2   = (const float*)d_in[9];
    const float* com_b2   = (const float*)d_in[10];
    const float* com_g    = (const float*)d_in[11];
    const float* com_beta = (const float*)d_in[12];
    const float* dec_W1   = (const float*)d_in[13];
    const float* dec_b1   = (const float*)d_in[14];
    const float* dec_W2   = (const float*)d_in[15];
    const float* dec_b2   = (const float*)d_in[16];
    const float* dec_g    = (const float*)d_in[17];
    const float* dec_beta = (const float*)d_in[18];
    const float* Wd1      = (const float*)d_in[19];
    const float* bd1      = (const float*)d_in[20];
    const float* Wd2      = (const float*)d_in[21];
    const float* bd2      = (const float*)d_in[22];
    const float* Wa       = (const float*)d_in[23];
    const float* ba       = (const float*)d_in[24];

    float* out_logits = (float*)d_out;
    float* out_ph     = (float*)d_out + B_*T_*16;

    static bool attr_set = false;
    if (!attr_set){
        cudaFuncSetAttribute(mega_kernel, cudaFuncAttributeMaxDynamicSharedMemorySize, SMEMB);
        attr_set = true;
    }

    mega_kernel<<<NB, NT, SMEMB>>>(obs, env_ids, prev_m, emb, W_obs, b_obs,
                            com_W1, com_b1, com_W2, com_b2, com_g, com_beta,
                            dec_W1, dec_b1, dec_W2, dec_b2, dec_g, dec_beta,
                            Wd1, bd1, Wd2, bd2, Wa, ba,
                            out_logits, out_ph);
}

// round 16
// speedup vs baseline: 1.5961x; 1.0258x over previous
#include <cuda_runtime.h>
#include <cuda_fp16.h>
#include <math.h>

#define NB 128
#define NH 64
#define NT 256
#define B_   64
#define T_   64
#define D_   512
#define LEPS 1e-3f
#define STAGEB 13824          // (32 A rows + 64 W rows) * 144 B
#define DEPTH  6
#define SMEMB  (DEPTH*STAGEB) // 82944 B

// ---------------- static device scratch ----------------
static __device__ __align__(16) __half g_comW1t[3ull*2048*2048];
static __device__ __align__(16) __half g_comW2t[3ull*2048*2048];
static __device__ __align__(16) __half g_decW1t[2ull*2048*1536];
static __device__ __align__(16) __half g_decW2t[2ull*1536*2048];
static __device__ __align__(16) __half g_Wd1t[512*2048];
static __device__ __align__(16) __half g_Wobst[512*128];
static __device__ __align__(16) __half g_obsh[B_*T_*128];
static __device__ __align__(16) __half g_Xcomb[4096*1024];
static __device__ __align__(16) __half g_Xvh[B_*1024];
static __device__ __align__(16) __half g_Xpc[B_*3*1024];
static __device__ __align__(16) __half g_Xp2[2][B_*512];
static __device__ __align__(16) __half g_A1c[B_*2048];
static __device__ __align__(16) __half g_A1d[B_*2048];
static __device__ __align__(16) float  g_obsinp[B_*T_*D_];
static __device__ __align__(16) float  g_PCcom[3ull*4096*2048];
static __device__ __align__(16) float  g_PCdec[2ull*4096*2048];
static __device__ __align__(16) float  g_PCdist[4096*512];
static __device__ __align__(16) float  g_PChead[4096*16];
static __device__ __align__(16) float  g_Afc[B_*2048];
static __device__ __align__(16) float  g_Afd[B_*2048];
static __device__ __align__(16) float  g_H1[B_*3*D_];
static __device__ __align__(16) float  g_H[B_*D_];
static __device__ __align__(16) float  g_M[B_*3*D_];
static __device__ __align__(16) float  g_cand[B_*3*D_];
static __device__ __align__(16) float  g_chl2[2][B_*3*D_];
static __device__ __align__(16) float  g_TE[B_*D_];
static __device__              float  g_P2[2][B_*3];
static __device__              float  g_PE2[2][B_];

// ---------------- barriers: 0 = full(128), 1 = A-half(64), 2 = B-half(64) ----------------
static __device__ __align__(128) unsigned g_bcnt[3*32];
static __device__ __align__(128) unsigned g_bgen[3*32];

__device__ __forceinline__ unsigned ld_acq(unsigned* p){
    unsigned v;
    asm volatile("ld.acquire.gpu.global.u32 %0, [%1];" : "=r"(v) : "l"(p));
    return v;
}

__device__ __forceinline__ void barid(int id, unsigned n){
    __syncthreads();
    if (threadIdx.x == 0){
        unsigned* c  = &g_bcnt[id*32];
        unsigned* ge = &g_bgen[id*32];
        unsigned g = *ge;
        unsigned old;
        asm volatile("atom.acq_rel.gpu.global.add.u32 %0, [%1], 1;"
                     : "=r"(old) : "l"(c));
        if (old == n - 1){
            *c = 0;
            asm volatile("st.release.gpu.global.u32 [%0], %1;" :: "l"(ge), "r"(g + 1));
        } else {
            while (ld_acq(ge) == g) __nanosleep(20);
        }
    }
    __syncthreads();
}
#define gridbar() barid(0, NB)

// ---------------- helpers ----------------
__device__ __forceinline__ float sigmf(float x){ return 1.f/(1.f+expf(-x)); }

__device__ __forceinline__ float2 red2(float s, float q, float* shs, float* shq){
    int lane = threadIdx.x & 31, w = threadIdx.x >> 5;
    #pragma unroll
    for (int off=16; off; off>>=1){
        s += __shfl_down_sync(0xffffffffu, s, off);
        q += __shfl_down_sync(0xffffffffu, q, off);
    }
    if (lane==0){ shs[w]=s; shq[w]=q; }
    __syncthreads();
    if (w==0){
        s = (lane<8)? shs[lane] : 0.f;
        q = (lane<8)? shq[lane] : 0.f;
        #pragma unroll
        for (int off=4; off; off>>=1){
            s += __shfl_down_sync(0xffffffffu, s, off);
            q += __shfl_down_sync(0xffffffffu, q, off);
        }
        if (lane==0){ shs[0]=s; shq[0]=q; }
    }
    __syncthreads();
    float2 r = make_float2(shs[0], shq[0]);
    __syncthreads();
    return r;
}

__device__ __forceinline__ float red1(float s, float* shs){
    int lane = threadIdx.x & 31, w = threadIdx.x >> 5;
    #pragma unroll
    for (int off=16; off; off>>=1) s += __shfl_down_sync(0xffffffffu, s, off);
    if (lane==0) shs[w]=s;
    __syncthreads();
    if (w==0){
        s = (lane<8)? shs[lane] : 0.f;
        #pragma unroll
        for (int off=4; off; off>>=1) s += __shfl_down_sync(0xffffffffu, s, off);
        if (lane==0) shs[0]=s;
    }
    __syncthreads();
    float r = shs[0];
    __syncthreads();
    return r;
}

// ---------------- cp.async / ldmatrix ----------------
__device__ __forceinline__ void cpa16(unsigned saddr, const void* g){
    asm volatile("cp.async.ca.shared.global [%0], [%1], 16;" :: "r"(saddr), "l"(g));
}
#define CP_COMMIT() asm volatile("cp.async.commit_group;")
#define CP_WAIT2()  asm volatile("cp.async.wait_group 2;")

__device__ __forceinline__ void ldsm4(unsigned& r0, unsigned& r1, unsigned& r2, unsigned& r3,
                                      unsigned a){
    asm volatile("ldmatrix.sync.aligned.m8n8.x4.shared.b16 {%0,%1,%2,%3}, [%4];"
                 : "=r"(r0), "=r"(r1), "=r"(r2), "=r"(r3) : "r"(a));
}

// ---------------- transpose-convert ----------------
__device__ void dev_tcvt(const float* __restrict__ W, __half* __restrict__ Wt,
                         int K, int N, __half (*S)[72])
{
    const int tid = threadIdx.x;
    const int r = tid >> 3, c4 = (tid & 7) * 4;
    const int Ntl = N >> 5;
    const int jobs = (K >> 5) * Ntl;
    for (int job = blockIdx.x; job < jobs; job += NB){
        const int k0 = (job / Ntl) << 5, n0 = (job % Ntl) << 5;
        __syncthreads();
        float4 v = *(const float4*)(W + (size_t)(k0 + r)*N + n0 + c4);
        S[r][c4]   = __float2half(v.x);
        S[r][c4+1] = __float2half(v.y);
        S[r][c4+2] = __float2half(v.z);
        S[r][c4+3] = __float2half(v.w);
        __syncthreads();
        __half2 h0 = __halves2half2(S[c4][r],   S[c4+1][r]);
        __half2 h1 = __halves2half2(S[c4+2][r], S[c4+3][r]);
        *(__half2*)(Wt + (size_t)(n0 + r)*K + k0 + c4)     = h0;
        *(__half2*)(Wt + (size_t)(n0 + r)*K + k0 + c4 + 2) = h1;
    }
    __syncthreads();
}

__device__ void dev_cvt4(const float* __restrict__ s, __half* __restrict__ d, int n4){
    const float4* s4 = (const float4*)s;
    __half2* d2 = (__half2*)d;
    for (int i = blockIdx.x*NT + threadIdx.x; i < n4; i += NB*NT){
        float4 v = s4[i];
        d2[2*i]   = __floats2half2_rn(v.x, v.y);
        d2[2*i+1] = __floats2half2_rn(v.z, v.w);
    }
}

__device__ void dev_prep(const float* __restrict__ emb, const int* __restrict__ ids,
                         const float* __restrict__ prevm){
    int i0 = blockIdx.x*NT + threadIdx.x, stride = NB*NT;
    for (int i = i0; i < B_*D_; i += stride){
        int b = i >> 9;
        g_TE[i] = emb[ids[b]*D_ + (i & 511)];
    }
    for (int i = i0; i < B_*3*D_; i += stride) g_M[i] = prevm[i];
}

__device__ void dev_xcomb(){
    for (int i = blockIdx.x*NT + threadIdx.x; i < 4096*1024; i += NB*NT){
        int row = i >> 10, d = i & 1023;
        int t = row >> 6, b = row & 63;
        float v = (d < 512) ? g_obsinp[(b*T_ + t)*512 + d]
                            : g_TE[b*512 + (d - 512)];
        g_Xcomb[i] = __float2half(v);
    }
}

__device__ void dev_pchead(const float* __restrict__ Wa, const float* __restrict__ ba){
    int gw = (blockIdx.x*NT + threadIdx.x) >> 5;
    int lane = threadIdx.x & 31;
    for (int row = gw; row < 4096; row += (NB*NT)>>5){
        int t = row >> 6, b = row & 63;
        float acc[15];
        #pragma unroll
        for (int a=0;a<15;a++) acc[a]=0.f;
        for (int d = lane; d < 512; d += 32){
            float te = g_TE[b*512 + d];
            float iv = g_obsinp[(b*T_ + t)*512 + d];
            #pragma unroll
            for (int a=0;a<15;a++)
                acc[a] += te*Wa[(512+d)*15 + a] + iv*Wa[(1024+d)*15 + a];
        }
        #pragma unroll
        for (int a=0;a<15;a++){
            float v = acc[a];
            #pragma unroll
            for (int off=16; off; off>>=1) v += __shfl_down_sync(0xffffffffu, v, off);
            if (lane == 0) g_PChead[row*16 + a] = v + ba[a];
        }
    }
}

// ---------------- GEMM: 32x64 tiles, BK=64 chunks, 6-deep ring, 2 chunks/sync, ldmatrix ----------------
// EPI 0: +bias[col] -> Cf ; EPI 3: +PC[row][col], relu -> Ch ; EPI 4: +PC[row/3][col], leaky -> Cf
template<int EPI>
__device__ __noinline__ void dev_gemm(const __half* __restrict__ A, int lda,
                                      const __half* __restrict__ Wt, int ldw,
                                      const float* __restrict__ aux, int ldaux,
                                      float* __restrict__ Cf, __half* __restrict__ Ch,
                                      int M, int N, int K, int base, int cnt,
                                      unsigned smu, char* smp)
{
    const int tid  = threadIdx.x;
    const int warp = tid >> 5, lane = tid & 31;
    const int wm = (warp & 1) * 16, wn = (warp >> 1) * 16;
    const int g  = lane >> 2,  tq = lane & 3;
    const int Ntiles = N >> 6;
    const int njobs = (M >> 5) * Ntiles;
    const int KT = K >> 6;
    const int r0 = tid >> 3,        s0 = tid & 7;
    const int r1 = (tid+256) >> 3,  s1 = tid & 7;
    const int r2 = (tid+512) >> 3,  s2 = tid & 7;

    // ldmatrix per-lane address offsets (within a stage)
    const int l8 = lane & 7;
    const unsigned aoff = (unsigned)((wm + l8 + ((lane>>3)&1)*8)*144 + (lane>>4)*16);
    const unsigned boff = (unsigned)(4608 + (wn + l8 + (lane>>4)*8)*144 + ((lane>>3)&1)*16);

    for (int job = blockIdx.x - base; job < njobs; job += cnt){
        const int bM = (job / Ntiles) << 5, bN = (job % Ntiles) << 6;
        const __half* src0 = A  + (size_t)(bM + r0) * lda + s0*8;
        const __half* src1 = Wt + (size_t)(bN + r1 - 32) * ldw + s1*8;
        const __half* src2 = Wt + (size_t)(bN + r2 - 32) * ldw + s2*8;
        const unsigned d0 = smu + r0*144 + s0*16;
        const unsigned d1 = smu + r1*144 + s1*16;
        const unsigned d2 = smu + r2*144 + s2*16;

        __syncthreads();
        #pragma unroll
        for (int p = 0; p < 4; p++){
            if (p < KT){
                const int ko = p*64;
                const unsigned so = p*STAGEB;
                cpa16(d0 + so, src0 + ko);
                cpa16(d1 + so, src1 + ko);
                cpa16(d2 + so, src2 + ko);
            }
            CP_COMMIT();
        }

        float c[2][4];
        #pragma unroll
        for (int ni=0;ni<2;ni++){ c[ni][0]=0.f; c[ni][1]=0.f; c[ni][2]=0.f; c[ni][3]=0.f; }

        for (int kp = 0; kp < KT; kp += 2){
            CP_WAIT2();
            __syncthreads();
            #pragma unroll
            for (int h = 0; h < 2; h++){
                const int kc = kp + 4 + h;
                if (kc < KT){
                    const unsigned so = (kc % DEPTH)*STAGEB;
                    const int ko = kc*64;
                    cpa16(d0 + so, src0 + ko);
                    cpa16(d1 + so, src1 + ko);
                    cpa16(d2 + so, src2 + ko);
                }
                CP_COMMIT();
            }
            #pragma unroll
            for (int h = 0; h < 2; h++){
                const unsigned sb = smu + ((kp + h) % DEPTH)*STAGEB;
                #pragma unroll
                for (int ks = 0; ks < 4; ks++){
                    unsigned a0,a1,a2,a3, b0,b1,b2,b3;
                    ldsm4(a0,a1,a2,a3, sb + aoff + ks*32);
                    ldsm4(b0,b1,b2,b3, sb + boff + ks*32);
                    asm volatile(
                        "mma.sync.aligned.m16n8k16.row.col.f32.f16.f16.f32 "
                        "{%0,%1,%2,%3},{%4,%5,%6,%7},{%8,%9},{%0,%1,%2,%3};\n"
                        : "+f"(c[0][0]), "+f"(c[0][1]), "+f"(c[0][2]), "+f"(c[0][3])
                        : "r"(a0), "r"(a1), "r"(a2), "r"(a3), "r"(b0), "r"(b1));
                    asm volatile(
                        "mma.sync.aligned.m16n8k16.row.col.f32.f16.f16.f32 "
                        "{%0,%1,%2,%3},{%4,%5,%6,%7},{%8,%9},{%0,%1,%2,%3};\n"
                        : "+f"(c[1][0]), "+f"(c[1][1]), "+f"(c[1][2]), "+f"(c[1][3])
                        : "r"(a0), "r"(a1), "r"(a2), "r"(a3), "r"(b2), "r"(b3));
                }
            }
        }

        const int row = bM + wm + g;
        #pragma unroll
        for (int ni=0; ni<2; ni++){
            const int col = bN + wn + ni*8 + tq*2;
            float a00,a01,a10,a11;
            if (EPI == 0){
                a00 = aux[col]; a01 = aux[col+1]; a10 = a00; a11 = a01;
            } else if (EPI == 3){
                const float* p0 = aux + (size_t)row*ldaux;
                const float* p1 = aux + (size_t)(row+8)*ldaux;
                a00 = p0[col]; a01 = p0[col+1]; a10 = p1[col]; a11 = p1[col+1];
            } else {
                const float* p0 = aux + (size_t)(row/3)*ldaux;
                const float* p1 = aux + (size_t)((row+8)/3)*ldaux;
                a00 = p0[col]; a01 = p0[col+1]; a10 = p1[col]; a11 = p1[col+1];
            }
            float v00 = c[ni][0] + a00, v01 = c[ni][1] + a01;
            float v10 = c[ni][2] + a10, v11 = c[ni][3] + a11;
            if (EPI == 3){
                v00 = fmaxf(v00,0.f); v01 = fmaxf(v01,0.f);
                v10 = fmaxf(v10,0.f); v11 = fmaxf(v11,0.f);
                *(__half2*)(Ch + (size_t)row*N + col)     = __floats2half2_rn(v00, v01);
                *(__half2*)(Ch + (size_t)(row+8)*N + col) = __floats2half2_rn(v10, v11);
            } else {
                if (EPI == 4){
                    v00 = v00>0.f? v00 : 0.3f*v00;  v01 = v01>0.f? v01 : 0.3f*v01;
                    v10 = v10>0.f? v10 : 0.3f*v10;  v11 = v11>0.f? v11 : 0.3f*v11;
                }
                *(float2*)(Cf + (size_t)row*N + col)     = make_float2(v00, v01);
                *(float2*)(Cf + (size_t)(row+8)*N + col) = make_float2(v10, v11);
            }
        }
    }
}

// ---------------- elementwise stages ----------------
__device__ void dev_pack_step0(const float* __restrict__ inp){
    int b = blockIdx.x;
    if (b >= B_) return;
    for (int d = threadIdx.x; d < 512; d += NT){
        g_Xvh[b*1024 + d]       = __float2half(inp[b*(T_*D_) + d]);
        g_Xvh[b*1024 + 512 + d] = __float2half(g_M[b*1536 + 1024 + d]);
    }
}

__device__ __noinline__ void dev_com_post(const float* __restrict__ gamma, const float* __restrict__ beta,
                                          const float* __restrict__ inp, int slot, int b,
                                          float* shs, float* shq)
{
    if (b < 0 || b >= B_) return;
    const float* a = g_Afc + b*2048;
    float gv[2], gh[2], gc[2];
    float s=0.f, q=0.f;
    #pragma unroll
    for (int j=0;j<2;j++){
        int d = threadIdx.x + j*256;
        gv[j]=a[d]; gh[j]=a[512+d]; gc[j]=a[1024+d];
        s += gv[j]+gh[j]+gc[j];
        q += gv[j]*gv[j]+gh[j]*gh[j]+gc[j]*gc[j];
    }
    float2 r = red2(s,q,shs,shq);
    float mu = r.x*(1.f/1536.f);
    float var = r.y*(1.f/1536.f) - mu*mu;
    float rs = rsqrtf(var + LEPS);

    float s2[2]; float ss=0.f, qq=0.f;
    #pragma unroll
    for (int j=0;j<2;j++){
        int d = threadIdx.x + j*256;
        float vg = sigmf((gv[j]-mu)*rs*gamma[d]      + beta[d]);
        float hg = sigmf((gh[j]-mu)*rs*gamma[512+d]  + beta[512+d]);
        float cg = sigmf((gc[j]-mu)*rs*gamma[1024+d] + beta[1024+d]);
        float viv = (slot==2) ? inp[b*(T_*D_) + d] : g_H[b*512 + d];
        float hiv = g_M[b*1536 + slot*512 + d];
        float cell = a[1536 + d];
        s2[j] = vg*viv + hg*hiv + cg*cell;
        ss += s2[j]; qq += s2[j]*s2[j];
    }
    float2 r2 = red2(ss,qq,shs,shq);
    float mu2 = r2.x*(1.f/512.f);
    float var2 = r2.y*(1.f/512.f) - mu2*mu2;
    float rs2 = rsqrtf(var2 + LEPS);

    #pragma unroll
    for (int j=0;j<2;j++){
        int d = threadIdx.x + j*256;
        float hnew = (s2[j]-mu2)*rs2;
        g_H[b*512 + d] = hnew;
        g_cand[b*1536 + slot*512 + d] = hnew;
        if (slot > 0){
            g_Xvh[b*1024 + d]       = __float2half(hnew);
            g_Xvh[b*1024 + 512 + d] = __float2half(g_M[b*1536 + (slot-1)*512 + d]);
        } else {
            #pragma unroll
            for (int n=0;n<3;n++){
                int rr = b*3 + n;
                g_Xpc[rr*1024 + d]       = __float2half(g_M[b*1536 + n*512 + d]);
                float cv = (n==0) ? hnew : g_cand[b*1536 + n*512 + d];
                g_Xpc[rr*1024 + 512 + d] = __float2half(cv);
            }
        }
    }
}

__device__ __noinline__ void dev_stick(const float* __restrict__ Wd2, const float* __restrict__ bd2,
                                       float* __restrict__ out_ph, int tc, int par,
                                       const float* __restrict__ inpn, int b,
                                       float* shs, float* shq)
{
    if (b < 0 || b >= B_) return;
    float a0=0.f, a1=0.f, a2=0.f;
    #pragma unroll
    for (int j=0;j<2;j++){
        int d = threadIdx.x + j*256;
        float w = Wd2[d];
        a0 += g_H1[(b*3+0)*512 + d]*w;
        a1 += g_H1[(b*3+1)*512 + d]*w;
        a2 += g_H1[(b*3+2)*512 + d]*w;
    }
    float dot0 = red1(a0, shs);
    float dot1 = red1(a1, shs);
    float dot2 = red1(a2, shs);
    if (threadIdx.x == 0){
        float bb = bd2[0];
        float b0 = sigmf(dot0+bb), b1 = sigmf(dot1+bb), b2 = sigmf(dot2+bb);
        float y0 = 1.f-b2, y1 = y0*(1.f-b1), y2 = y1*(1.f-b0);
        float ph0 = y2, ph1 = b0*y1, ph2 = b1*y0, ph3 = b2;
        float* op = out_ph + (size_t)(b*T_ + tc)*4;
        op[0]=ph0; op[1]=ph1; op[2]=ph2; op[3]=ph3;
        float inv = 1.f/(ph1+ph2+ph3);
        float p0 = ph1*inv, p1 = ph2*inv, p2 = ph3*inv;
        g_P2[par][b*3]=p0; g_P2[par][b*3+1]=p1; g_P2[par][b*3+2]=p2;
        g_PE2[par][b] = ph0;
        shq[0] = p0+p1+p2;
        shq[1] = p1+p2;
        shq[2] = p2;
    }
    __syncthreads();
    float rc0 = shq[0], rc1 = shq[1], rc2 = shq[2];
    #pragma unroll
    for (int j=0;j<2;j++){
        int d = threadIdx.x + j*256;
        float m0, m2;
        {
            float mm = g_M[b*1536 + d]*(1.f-rc0) + g_cand[b*1536 + d]*rc0;
            g_M[b*1536 + d] = mm; m0 = mm;
        }
        {
            float mm = g_M[b*1536 + 512 + d]*(1.f-rc1) + g_cand[b*1536 + 512 + d]*rc1;
            g_M[b*1536 + 512 + d] = mm;
        }
        {
            float mm = g_M[b*1536 + 1024 + d]*(1.f-rc2) + g_cand[b*1536 + 1024 + d]*rc2;
            g_M[b*1536 + 1024 + d] = mm; m2 = mm;
        }
        g_chl2[par][b*1536 + d] = m0;
        g_Xp2[par][b*512 + d] = __float2half(m0);
        if (inpn){
            g_Xvh[b*1024 + d]       = __float2half(inpn[b*(T_*D_) + d]);
            g_Xvh[b*1024 + 512 + d] = __float2half(m2);
        }
    }
    __syncthreads();
}

__device__ __noinline__ void dev_dec_post(const float* __restrict__ gamma, const float* __restrict__ beta,
                                          int slot, int par, int b, float* shs, float* shq)
{
    if (b < 0 || b >= B_) return;
    const float* a = g_Afd + b*1536;
    float g0[2], g1[2];
    float s=0.f, q=0.f;
    #pragma unroll
    for (int j=0;j<2;j++){
        int d = threadIdx.x + j*256;
        g0[j]=a[d]; g1[j]=a[512+d];
        s += g0[j]+g1[j];
        q += g0[j]*g0[j]+g1[j]*g1[j];
    }
    float2 r = red2(s,q,shs,shq);
    float mu = r.x*(1.f/1024.f);
    float var = r.y*(1.f/1024.f) - mu*mu;
    float rs = rsqrtf(var + LEPS);

    float s2[2]; float ss=0.f, qq=0.f;
    #pragma unroll
    for (int j=0;j<2;j++){
        int d = threadIdx.x + j*256;
        float gate  = sigmf((g0[j]-mu)*rs*gamma[d]     + beta[d]);
        float cgate = sigmf((g1[j]-mu)*rs*gamma[512+d] + beta[512+d]);
        float parent = g_chl2[par][b*1536 + slot*512 + d];
        float cell = a[1024 + d];
        s2[j] = gate*parent + cgate*cell;
        ss += s2[j]; qq += s2[j]*s2[j];
    }
    float2 r2 = red2(ss,qq,shs,shq);
    float mu2 = r2.x*(1.f/512.f);
    float var2 = r2.y*(1.f/512.f) - mu2*mu2;
    float rs2 = rsqrtf(var2 + LEPS);

    #pragma unroll
    for (int j=0;j<2;j++){
        int d = threadIdx.x + j*256;
        float hnew = (s2[j]-mu2)*rs2;
        g_chl2[par][b*1536 + (slot+1)*512 + d] = hnew;
        if (slot == 0) g_Xp2[par][b*512 + d] = __float2half(hnew);
    }
}

__device__ __noinline__ void dev_head(const float* __restrict__ Wa,
                                      float* __restrict__ out_lg, int t, int par, int b,
                                      float* shs)
{
    if (b < 0 || b >= B_) return;
    if (threadIdx.x < 15) shs[threadIdx.x] = 0.f;
    __syncthreads();

    float p0 = g_P2[par][b*3], p1 = g_P2[par][b*3+1], p2 = g_P2[par][b*3+2];
    float acc[15];
    #pragma unroll
    for (int a=0;a<15;a++) acc[a]=0.f;
    for (int d = threadIdx.x; d < 512; d += NT){
        float x = p0*g_chl2[par][b*1536 + d] + p1*g_chl2[par][b*1536 + 512 + d]
                + p2*g_chl2[par][b*1536 + 1024 + d];
        #pragma unroll
        for (int a=0;a<15;a++) acc[a] += x * Wa[d*15 + a];
    }
    #pragma unroll
    for (int a=0;a<15;a++){
        float v = acc[a];
        #pragma unroll
        for (int off=16; off; off>>=1) v += __shfl_down_sync(0xffffffffu, v, off);
        if ((threadIdx.x & 31) == 0) atomicAdd(&shs[a], v);
    }
    __syncthreads();

    if (threadIdx.x == 0){
        const float* pc = g_PChead + (size_t)(t*64 + b)*16;
        float lg[15], mx = -1e30f;
        #pragma unroll
        for (int a=0;a<15;a++){ lg[a] = shs[a] + pc[a]; mx = fmaxf(mx, lg[a]); }
        float sum = 0.f;
        #pragma unroll
        for (int a=0;a<15;a++){ lg[a] = expf(lg[a]-mx); sum += lg[a]; }
        float pe = g_PE2[par][b];
        pe = fminf(fmaxf(pe, 1e-6f), 1.f - 1e-6f);
        float scale = (1.f - pe)/sum;
        float* op = out_lg + (size_t)(b*T_ + t)*16;
        #pragma unroll
        for (int a=0;a<15;a++){
            int j = (a < 5) ? a : a + 1;
            op[j] = logf(lg[a]*scale);
        }
        op[5] = logf(pe);
    }
    __syncthreads();
}

// ---------------- megakernel ----------------
__global__ void __launch_bounds__(NT, 1)
mega_kernel(const float* obs, const int* env_ids, const float* prev_m,
            const float* emb, const float* W_obs, const float* b_obs,
            const float* com_W1, const float* com_b1, const float* com_W2, const float* com_b2,
            const float* com_g, const float* com_beta,
            const float* dec_W1, const float* dec_b1, const float* dec_W2, const float* dec_b2,
            const float* dec_g, const float* dec_beta,
            const float* Wd1, const float* bd1, const float* Wd2, const float* bd2,
            const float* Wa, const float* ba,
            float* out_logits, float* out_ph)
{
    extern __shared__ char dynsm[];
    __shared__ float shs[16], shq[16];
    unsigned smu = (unsigned)__cvta_generic_to_shared(dynsm);
    __half (*S)[72] = (__half(*)[72])dynsm;

    for (int i = 0; i < 3; i++){
        dev_tcvt(com_W1 + (size_t)i*2048*2048, g_comW1t + (size_t)i*2048*2048, 2048, 2048, S);
        dev_tcvt(com_W2 + (size_t)i*2048*2048, g_comW2t + (size_t)i*2048*2048, 2048, 2048, S);
    }
    for (int i = 0; i < 2; i++){
        dev_tcvt(dec_W1 + (size_t)i*1536*2048, g_decW1t + (size_t)i*2048*1536, 1536, 2048, S);
        dev_tcvt(dec_W2 + (size_t)i*2048*1536, g_decW2t + (size_t)i*1536*2048, 2048, 1536, S);
    }
    dev_tcvt(Wd1,   g_Wd1t,  2048, 512, S);
    dev_tcvt(W_obs, g_Wobst, 128,  512, S);
    dev_cvt4(obs, g_obsh, B_*T_*128/4);
    dev_prep(emb, env_ids, prev_m);
    gridbar();

    dev_gemm<0>(g_obsh, 128, g_Wobst, 128, b_obs, 0, g_obsinp, nullptr,
                B_*T_, 512, 128, 0, NB, smu, dynsm);
    gridbar();

    dev_xcomb();
    dev_pchead(Wa, ba);
    dev_pack_step0(g_obsinp);
    gridbar();

    for (int i = 0; i < 3; i++)
        dev_gemm<0>(g_Xcomb, 1024, g_comW1t + (size_t)i*2048*2048 + 1024, 2048,
                    com_b1 + i*2048, 0, g_PCcom + (size_t)i*4096*2048, nullptr,
                    4096, 2048, 1024, 0, NB, smu, dynsm);
    for (int i = 0; i < 2; i++)
        dev_gemm<0>(g_Xcomb, 1024, g_decW1t + (size_t)i*2048*1536 + 512, 1536,
                    dec_b1 + i*2048, 0, g_PCdec + (size_t)i*4096*2048, nullptr,
                    4096, 2048, 1024, 0, NB, smu, dynsm);
    dev_gemm<0>(g_Xcomb, 1024, g_Wd1t, 2048, bd1, 0, g_PCdist, nullptr,
                4096, 512, 1024, 0, NB, smu, dynsm);
    gridbar();

    // ---- t=0 com/dist/stick with FULL grid ----
    {
        const float* inp0 = g_obsinp;
        for (int i = 2; i >= 0; i--){
            dev_gemm<3>(g_Xvh, 1024, g_comW1t + (size_t)i*2048*2048, 2048,
                        g_PCcom + (size_t)i*4096*2048, 2048,
                        nullptr, g_A1c, 64, 2048, 1024, 0, NB, smu, dynsm);
            gridbar();
            dev_gemm<0>(g_A1c, 2048, g_comW2t + (size_t)i*2048*2048, 2048,
                        com_b2 + i*2048, 0, g_Afc, nullptr, 64, 2048, 2048, 0, NB, smu, dynsm);
            gridbar();
            dev_com_post(com_g + i*1536, com_beta + i*1536, inp0, i, blockIdx.x, shs, shq);
            gridbar();
        }
        dev_gemm<4>(g_Xpc, 1024, g_Wd1t + 1024, 2048, g_PCdist, 512,
                    g_H1, nullptr, 192, 512, 1024, 0, NB, smu, dynsm);
        gridbar();
        dev_stick(Wd2, bd2, out_ph, 0, 0, g_obsinp + 512, blockIdx.x, shs, shq);
        gridbar();
    }

    // ---- pipelined loop ----
    for (int t = 0; t < T_; t++){
        const int par = t & 1;
        if (blockIdx.x < NH){
            const int b = blockIdx.x;
            for (int i = 0; i < 2; i++){
                dev_gemm<3>(g_Xp2[par], 512, g_decW1t + (size_t)i*2048*1536, 1536,
                            g_PCdec + ((size_t)i*4096 + t*64)*2048, 2048,
                            nullptr, g_A1d, 64, 2048, 512, 0, NH, smu, dynsm);
                barid(1, NH);
                dev_gemm<0>(g_A1d, 2048, g_decW2t + (size_t)i*1536*2048, 2048,
                            dec_b2 + i*1536, 0, g_Afd, nullptr, 64, 1536, 2048, 0, NH, smu, dynsm);
                barid(1, NH);
                dev_dec_post(dec_g + i*1024, dec_beta + i*1024, i, par, b, shs, shq);
                barid(1, NH);
            }
            dev_head(Wa, out_logits, t, par, b, shs);
        } else if (t + 1 < T_) {
            const int tc = t + 1;
            const int b = blockIdx.x - NH;
            const float* inpc = g_obsinp + tc*512;
            for (int i = 2; i >= 0; i--){
                dev_gemm<3>(g_Xvh, 1024, g_comW1t + (size_t)i*2048*2048, 2048,
                            g_PCcom + ((size_t)i*4096 + tc*64)*2048, 2048,
                            nullptr, g_A1c, 64, 2048, 1024, NH, NH, smu, dynsm);
                barid(2, NH);
                dev_gemm<0>(g_A1c, 2048, g_comW2t + (size_t)i*2048*2048, 2048,
                            com_b2 + i*2048, 0, g_Afc, nullptr, 64, 2048, 2048, NH, NH, smu, dynsm);
                barid(2, NH);
                dev_com_post(com_g + i*1536, com_beta + i*1536, inpc, i, b, shs, shq);
                barid(2, NH);
            }
            dev_gemm<4>(g_Xpc, 1024, g_Wd1t + 1024, 2048,
                        g_PCdist + (size_t)tc*64*512, 512,
                        g_H1, nullptr, 192, 512, 1024, NH, NH, smu, dynsm);
            barid(2, NH);
            dev_stick(Wd2, bd2, out_ph, tc, par ^ 1,
                      (tc + 1 < T_) ? (g_obsinp + (tc+1)*512) : nullptr, b, shs, shq);
        }
        gridbar();
    }
}

// ---------------- launch ----------------
extern "C" void kernel_launch(void* const* d_in, const int* in_sizes, int n_in,
                              void* d_out, int out_size)
{
    const float* obs      = (const float*)d_in[0];
    const int*   env_ids  = (const int*)  d_in[1];
    const float* prev_m   = (const float*)d_in[2];
    const float* emb      = (const float*)d_in[4];
    const float* W_obs    = (const float*)d_in[5];
    const float* b_obs    = (const float*)d_in[6];
    const float* com_W1   = (const float*)d_in[7];
    const float* com_b1   = (const float*)d_in[8];
    const float* com_W2   = (const float*)d_in[9];
    const float* com_b2   = (const float*)d_in[10];
    const float* com_g    = (const float*)d_in[11];
    const float* com_beta = (const float*)d_in[12];
    const float* dec_W1   = (const float*)d_in[13];
    const float* dec_b1   = (const float*)d_in[14];
    const float* dec_W2   = (const float*)d_in[15];
    const float* dec_b2   = (const float*)d_in[16];
    const float* dec_g    = (const float*)d_in[17];
    const float* dec_beta = (const float*)d_in[18];
    const float* Wd1      = (const float*)d_in[19];
    const float* bd1      = (const float*)d_in[20];
    const float* Wd2      = (const float*)d_in[21];
    const float* bd2      = (const float*)d_in[22];
    const float* Wa       = (const float*)d_in[23];
    const float* ba       = (const float*)d_in[24];

    float* out_logits = (float*)d_out;
    float* out_ph     = (float*)d_out + B_*T_*16;

    static bool attr_set = false;
    if (!attr_set){
        cudaFuncSetAttribute(mega_kernel, cudaFuncAttributeMaxDynamicSharedMemorySize, SMEMB);
        attr_set = true;
    }

    mega_kernel<<<NB, NT, SMEMB>>>(obs, env_ids, prev_m, emb, W_obs, b_obs,
                            com_W1, com_b1, com_W2, com_b2, com_g, com_beta,
                            dec_W1, dec_b1, dec_W2, dec_b2, dec_g, dec_beta,
                            Wd1, bd1, Wd2, bd2, Wa, ba,
                            out_logits, out_ph);
}